// round 6
// baseline (speedup 1.0000x reference)
#include <cuda_runtime.h>
#include <cuda_fp16.h>
#include <cstdint>

#define BT 32768
#define NF 32
#define NU 64
#define EPS 1e-3f
#define W_OFF (BT * NU)

// per-feature image (bytes): W2' fp16[64][72] | Wg' fp16[128][72] | vec f32[8][64]
#define IMG_BYTES  29696
#define OFF_WG_B   9216
#define OFF_VEC_B  27648
// k_vsn smem byte offsets
#define H2_OFF     59392u          // 2 img buffers before this; 4 warps x 4608 B
#define XS_OFF     77824u          // 128*33 floats = 16896 B
#define MBAR_OFF   94720u
#define SMEM_TOTAL 94736u

__device__ __align__(16) unsigned char g_img[NF][IMG_BYTES];

// ---------------- helpers ----------------
__device__ __forceinline__ uint32_t smem_u32(const void* p) {
    uint32_t a;
    asm("{ .reg .u64 t; cvta.to.shared.u64 t, %1; cvt.u32.u64 %0, t; }" : "=r"(a) : "l"(p));
    return a;
}
__device__ __forceinline__ float eluf(float z)  { return z > 0.f ? z : (__expf(z) - 1.f); }
// sigmoid via tanh.approx (1 MUFU)
__device__ __forceinline__ float sigmf(float z) {
    float t, h = 0.5f * z;
    asm("tanh.approx.f32 %0, %1;" : "=f"(t) : "f"(h));
    return fmaf(0.5f, t, 0.5f);
}
__device__ __forceinline__ uint32_t packh2(float lo, float hi) {
    __half2 h = __floats2half2_rn(lo, hi);
    return *reinterpret_cast<uint32_t*>(&h);
}
__device__ __forceinline__ void mma16(float* c, const uint32_t* a, uint32_t b0, uint32_t b1) {
    asm volatile(
        "mma.sync.aligned.m16n8k16.row.col.f32.f16.f16.f32 "
        "{%0,%1,%2,%3}, {%4,%5,%6,%7}, {%8,%9}, {%0,%1,%2,%3};"
        : "+f"(c[0]), "+f"(c[1]), "+f"(c[2]), "+f"(c[3])
        : "r"(a[0]), "r"(a[1]), "r"(a[2]), "r"(a[3]), "r"(b0), "r"(b1));
}

#define MBARRIER_INIT(addr, cnt) \
    asm volatile("mbarrier.init.shared.b64 [%0], %1;" :: "r"(addr), "r"(cnt) : "memory")
#define MBARRIER_EXPECT_TX(addr, tx) \
    asm volatile("mbarrier.arrive.expect_tx.shared.b64 _, [%0], %1;" :: "r"(addr), "r"(tx) : "memory")
#define MBARRIER_WAIT_PARITY(addr, par) do { \
    uint32_t _m = (addr); uint32_t _p = (par); uint32_t _d; \
    asm volatile("{ .reg .pred p; mbarrier.try_wait.parity.acquire.cta.shared::cta.b64 p, [%1], %2; selp.b32 %0, 1, 0, p; }" \
        : "=r"(_d) : "r"(_m), "r"(_p) : "memory"); \
    if (!_d) { \
        asm volatile("{ .reg .pred P1; WL_%=: mbarrier.try_wait.parity.acquire.cta.shared::cta.b64 P1, [%0], %1, 0x989680; @P1 bra.uni WD_%=; bra.uni WL_%=; WD_%=: }" \
            :: "r"(_m), "r"(_p) : "memory"); \
    } } while (0)

__device__ __forceinline__ void bulk_g2s(uint32_t dst, const void* src, uint32_t bytes, uint32_t mbar) {
    asm volatile("cp.async.bulk.shared::cluster.global.mbarrier::complete_tx::bytes [%0], [%1], %2, [%3];"
                 :: "r"(dst), "l"(src), "r"(bytes), "r"(mbar) : "memory");
}

// ============================================================================
// Kernel 0: weights GRN + LN + softmax -> w [BT,32]
// Block 512 = 128 tokens, 4 threads/token (each owns 8 of 32 outputs).
// ============================================================================
#define KW_S1 0
#define KW_S2 1024
#define KW_G1 2048
#define KW_G2 3072
#define KW_VB 4096        // 6*32
#define KW_X  4288        // 128*36
#define KW_H  8896
#define KW_H2 13504
#define KW_FLOATS 18112   // 72448 bytes

__global__ __launch_bounds__(512) void k_weights(
    const float* __restrict__ x,
    const float* __restrict__ w1w, const float* __restrict__ b1w,
    const float* __restrict__ w2w, const float* __restrict__ b2w,
    const float* __restrict__ wg1w, const float* __restrict__ bg1w,
    const float* __restrict__ wg2w, const float* __restrict__ bg2w,
    const float* __restrict__ gammaw, const float* __restrict__ betaw,
    float* __restrict__ wout)
{
    extern __shared__ float sw[];
    const int tid = threadIdx.x;
    for (int i = tid; i < 1024; i += 512) {
        sw[KW_S1 + i] = w1w[i]; sw[KW_S2 + i] = w2w[i];
        sw[KW_G1 + i] = wg1w[i]; sw[KW_G2 + i] = wg2w[i];
    }
    if (tid < 32) {
        sw[KW_VB + tid]       = b1w[tid];
        sw[KW_VB + 32 + tid]  = b2w[tid];
        sw[KW_VB + 64 + tid]  = bg1w[tid];
        sw[KW_VB + 96 + tid]  = bg2w[tid];
        sw[KW_VB + 128 + tid] = gammaw[tid];
        sw[KW_VB + 160 + tid] = betaw[tid];
    }
    const int tok = tid >> 2;
    const int gb  = (tid & 3) * 8;
    const size_t tokG = (size_t)blockIdx.x * 128 + tok;
    {
        const float4* xp = (const float4*)(x + tokG * 32 + gb);
        float4* xr = (float4*)&sw[KW_X + tok * 36 + gb];
        xr[0] = xp[0]; xr[1] = xp[1];
    }
    __syncthreads();

    float h[8];
    #pragma unroll
    for (int g = 0; g < 8; g++) h[g] = sw[KW_VB + gb + g];
    #pragma unroll 4
    for (int f = 0; f < 32; f++) {
        float xv = sw[KW_X + tok * 36 + f];
        const float4* wr = (const float4*)&sw[KW_S1 + f * 32 + gb];
        float4 w0 = wr[0], w1 = wr[1];
        h[0] += xv * w0.x; h[1] += xv * w0.y; h[2] += xv * w0.z; h[3] += xv * w0.w;
        h[4] += xv * w1.x; h[5] += xv * w1.y; h[6] += xv * w1.z; h[7] += xv * w1.w;
    }
    #pragma unroll
    for (int g = 0; g < 8; g++) {
        float v = h[g];
        sw[KW_H + tok * 36 + gb + g] = (v > 0.f) ? v : (__expf(v) - 1.f);
    }
    __syncthreads();

    float h2[8];
    #pragma unroll
    for (int g = 0; g < 8; g++) h2[g] = sw[KW_VB + 32 + gb + g];
    #pragma unroll 4
    for (int f = 0; f < 32; f++) {
        float hv = sw[KW_H + tok * 36 + f];
        const float4* wr = (const float4*)&sw[KW_S2 + f * 32 + gb];
        float4 w0 = wr[0], w1 = wr[1];
        h2[0] += hv * w0.x; h2[1] += hv * w0.y; h2[2] += hv * w0.z; h2[3] += hv * w0.w;
        h2[4] += hv * w1.x; h2[5] += hv * w1.y; h2[6] += hv * w1.z; h2[7] += hv * w1.w;
    }
    #pragma unroll
    for (int g = 0; g < 8; g++) sw[KW_H2 + tok * 36 + gb + g] = h2[g];
    __syncthreads();

    float o1[8], o2[8];
    #pragma unroll
    for (int g = 0; g < 8; g++) { o1[g] = sw[KW_VB + 64 + gb + g]; o2[g] = sw[KW_VB + 96 + gb + g]; }
    #pragma unroll 4
    for (int f = 0; f < 32; f++) {
        float hv = sw[KW_H2 + tok * 36 + f];
        const float4* w1r = (const float4*)&sw[KW_G1 + f * 32 + gb];
        const float4* w2r = (const float4*)&sw[KW_G2 + f * 32 + gb];
        float4 wa0 = w1r[0], wa1 = w1r[1], wb0 = w2r[0], wb1 = w2r[1];
        o1[0] += hv * wa0.x; o1[1] += hv * wa0.y; o1[2] += hv * wa0.z; o1[3] += hv * wa0.w;
        o1[4] += hv * wa1.x; o1[5] += hv * wa1.y; o1[6] += hv * wa1.z; o1[7] += hv * wa1.w;
        o2[0] += hv * wb0.x; o2[1] += hv * wb0.y; o2[2] += hv * wb0.z; o2[3] += hv * wb0.w;
        o2[4] += hv * wb1.x; o2[5] += hv * wb1.y; o2[6] += hv * wb1.z; o2[7] += hv * wb1.w;
    }

    float s[8], ssum = 0.f, ssq = 0.f;
    #pragma unroll
    for (int g = 0; g < 8; g++) {
        float sg = 1.f / (1.f + __expf(-o2[g]));
        float v = o1[g] * sg + sw[KW_X + tok * 36 + gb + g];
        s[g] = v; ssum += v; ssq += v * v;
    }
    #pragma unroll
    for (int off = 1; off < 4; off <<= 1) {
        ssum += __shfl_xor_sync(0xffffffffu, ssum, off);
        ssq  += __shfl_xor_sync(0xffffffffu, ssq,  off);
    }
    float mean = ssum * (1.f / 32.f);
    float var  = ssq * (1.f / 32.f) - mean * mean;
    float inv  = rsqrtf(var + EPS);

    float y[8], mx = -1e30f;
    #pragma unroll
    for (int g = 0; g < 8; g++) {
        float v = (s[g] - mean) * inv * sw[KW_VB + 128 + gb + g] + sw[KW_VB + 160 + gb + g];
        y[g] = v; mx = fmaxf(mx, v);
    }
    #pragma unroll
    for (int off = 1; off < 4; off <<= 1)
        mx = fmaxf(mx, __shfl_xor_sync(0xffffffffu, mx, off));
    float se = 0.f;
    #pragma unroll
    for (int g = 0; g < 8; g++) { float e = __expf(y[g] - mx); y[g] = e; se += e; }
    #pragma unroll
    for (int off = 1; off < 4; off <<= 1)
        se += __shfl_xor_sync(0xffffffffu, se, off);
    float r = 1.f / se;
    {
        float4* op = (float4*)(wout + tokG * 32 + gb);
        op[0] = make_float4(y[0] * r, y[1] * r, y[2] * r, y[3] * r);
        op[1] = make_float4(y[4] * r, y[5] * r, y[6] * r, y[7] * r);
    }
}

// ============================================================================
// Kernel 1: prep — per-feature fp16 images + folded gate biases.
// ============================================================================
__global__ __launch_bounds__(256) void k_prep(
    const float* __restrict__ W2, const float* __restrict__ Wg1, const float* __restrict__ Wg2,
    const float* __restrict__ b2, const float* __restrict__ bg1, const float* __restrict__ bg2,
    const float* __restrict__ W1, const float* __restrict__ b1,
    const float* __restrict__ Wp, const float* __restrict__ bp,
    const float* __restrict__ gamma, const float* __restrict__ beta)
{
    const int f = blockIdx.x;
    const int tid = threadIdx.x;
    const float* W2f  = W2  + (size_t)f * 4096;
    const float* Wg1f = Wg1 + (size_t)f * 4096;
    const float* Wg2f = Wg2 + (size_t)f * 4096;
    unsigned char* img = g_img[f];
    __half* W2h = (__half*)img;
    __half* Wgh = (__half*)(img + OFF_WG_B);
    float*  vec = (float*)(img + OFF_VEC_B);

    for (int i = tid; i < 4096; i += 256) {
        int n = i >> 6, k = i & 63;
        W2h[n * 72 + k] = __float2half_rn(W2f[k * 64 + n]);
    }
    for (int i = tid; i < 8192; i += 256) {
        int n = i >> 6, k = i & 63;
        float v = (n < 64) ? Wg1f[k * 64 + n] : Wg2f[k * 64 + (n - 64)];
        Wgh[n * 72 + k] = __float2half_rn(v);
    }
    if (tid < 64) {
        int o = f * 64 + tid;
        vec[0   + tid] = W1[o];
        vec[64  + tid] = b1[o];
        vec[128 + tid] = Wp[o];
        vec[192 + tid] = bp[o];
        vec[256 + tid] = gamma[o];
        vec[320 + tid] = beta[o];
        float s1 = bg1[o], s2 = bg2[o];
        for (int u = 0; u < 64; u++) {
            float bv = b2[f * 64 + u];
            s1 += bv * Wg1f[u * 64 + tid];
            s2 += bv * Wg2f[u * 64 + tid];
        }
        vec[384 + tid] = s1;
        vec[448 + tid] = s2;
    }
}

// ============================================================================
// Kernel 2: main — per-feature GRNs via mma.sync fp16, LN fully in registers.
// CTA = 128 tokens, 4 warps x 32 tokens. Double-buffered weight images.
// ============================================================================
__global__ __launch_bounds__(128, 2) void k_vsn(
    const float* __restrict__ x,
    const float* __restrict__ w,
    float* __restrict__ out)
{
    extern __shared__ char smem[];
    const uint32_t sbase = smem_u32(smem);
    float* xs = (float*)(smem + XS_OFF);

    const int tid  = threadIdx.x;
    const int lane = tid & 31;
    const int warp = tid >> 5;
    const int q    = lane & 3;
    const int g    = lane >> 2;
    const int wtok = warp * 32;
    const size_t blk = (size_t)blockIdx.x * 128;

    uint32_t* h2u = (uint32_t*)(smem + H2_OFF) + warp * 1152;   // fp16 [32][72] as words

    const uint32_t mbar0 = sbase + MBAR_OFF;
    const uint32_t mbar1 = sbase + MBAR_OFF + 8;
    if (tid == 0) { MBARRIER_INIT(mbar0, 1); MBARRIER_INIT(mbar1, 1); }

    {   // stage x tile [128][33]
        const float4* xp = (const float4*)(x + (blk + tid) * NF);
        #pragma unroll
        for (int i = 0; i < 8; i++) {
            float4 v = xp[i];
            xs[tid * 33 + i * 4 + 0] = v.x; xs[tid * 33 + i * 4 + 1] = v.y;
            xs[tid * 33 + i * 4 + 2] = v.z; xs[tid * 33 + i * 4 + 3] = v.w;
        }
    }
    __syncthreads();
    if (tid == 0) {
        MBARRIER_EXPECT_TX(mbar0, IMG_BYTES);
        bulk_g2s(sbase, &g_img[0][0], IMG_BYTES, mbar0);
        MBARRIER_EXPECT_TX(mbar1, IMG_BYTES);
        bulk_g2s(sbase + IMG_BYTES, &g_img[1][0], IMG_BYTES, mbar1);
    }

    float acc[4][16];
    #pragma unroll
    for (int t = 0; t < 4; t++)
        #pragma unroll
        for (int c = 0; c < 16; c++) acc[t][c] = 0.f;

    #pragma unroll 1
    for (int f = 0; f < NF; f++) {
        const int buf = f & 1;
        MBARRIER_WAIT_PARITY(buf ? mbar1 : mbar0, (f >> 1) & 1);

        const uint32_t* bw   = (const uint32_t*)(smem + buf * IMG_BYTES);
        const uint32_t* wgw  = (const uint32_t*)(smem + buf * IMG_BYTES + OFF_WG_B);
        const float*    vecf = (const float*)(smem + buf * IMG_BYTES + OFF_VEC_B);

        float xf[4], wf[4];
        #pragma unroll
        for (int t = 0; t < 4; t++) {
            int row = g + 8 * t;
            xf[t] = xs[(wtok + row) * 33 + f];
            wf[t] = w[(blk + wtok + row) * NF + f];
        }

        // ---- A1 = fp16(elu(xf*W1+b1)) fragments ----
        uint32_t a1[2][4][4];
        #pragma unroll
        for (int s = 0; s < 4; s++) {
            #pragma unroll
            for (int p = 0; p < 2; p++) {
                int u0 = 16 * s + 2 * q + 8 * p;
                float wa = vecf[u0],     ba = vecf[64 + u0];
                float wb = vecf[u0 + 1], bb = vecf[64 + u0 + 1];
                #pragma unroll
                for (int m = 0; m < 2; m++) {
                    a1[m][s][2*p]   = packh2(eluf(fmaf(xf[2*m],   wa, ba)),
                                             eluf(fmaf(xf[2*m],   wb, bb)));
                    a1[m][s][2*p+1] = packh2(eluf(fmaf(xf[2*m+1], wa, ba)),
                                             eluf(fmaf(xf[2*m+1], wb, bb)));
                }
            }
        }

        // ---- GEMM1: h2' = h1 @ W2 -> fp16 per-warp tile ----
        #pragma unroll 2
        for (int j = 0; j < 8; j++) {
            const uint32_t* Br = bw + (8 * j + g) * 36 + q;
            float c0[4] = {0.f,0.f,0.f,0.f};
            float c1[4] = {0.f,0.f,0.f,0.f};
            #pragma unroll
            for (int s = 0; s < 4; s++) {
                uint32_t b0 = Br[8 * s], b1v = Br[8 * s + 4];
                mma16(c0, a1[0][s], b0, b1v);
                mma16(c1, a1[1][s], b0, b1v);
            }
            int cw = 4 * j + q;
            h2u[(g     ) * 36 + cw] = packh2(c0[0], c0[1]);
            h2u[(g +  8) * 36 + cw] = packh2(c0[2], c0[3]);
            h2u[(g + 16) * 36 + cw] = packh2(c1[0], c1[1]);
            h2u[(g + 24) * 36 + cw] = packh2(c1[2], c1[3]);
        }
        __syncwarp();

        // ---- A2 fragments from fp16 h2 tile ----
        uint32_t a2[2][4][4];
        #pragma unroll
        for (int m = 0; m < 2; m++)
            #pragma unroll
            for (int s = 0; s < 4; s++) {
                int r0 = (16 * m + g) * 36 + 8 * s + q;
                a2[m][s][0] = h2u[r0];
                a2[m][s][1] = h2u[r0 + 288];
                a2[m][s][2] = h2u[r0 + 4];
                a2[m][s][3] = h2u[r0 + 292];
            }

        // ---- GEMM2 (o1 | o2) + gate + residual; sv kept in registers ----
        float sv[4][16];
        float ssum[4] = {0.f,0.f,0.f,0.f};
        float ssq[4]  = {0.f,0.f,0.f,0.f};
        #pragma unroll 1
        for (int j = 0; j < 8; j++) {
            const uint32_t* B1r = wgw + (8 * j + g) * 36 + q;
            const uint32_t* B2r = B1r + 2304;
            float c1[8] = {0.f,0.f,0.f,0.f,0.f,0.f,0.f,0.f};
            float c2[8] = {0.f,0.f,0.f,0.f,0.f,0.f,0.f,0.f};
            #pragma unroll
            for (int s = 0; s < 4; s++) {
                uint32_t b10 = B1r[8 * s], b11 = B1r[8 * s + 4];
                uint32_t b20 = B2r[8 * s], b21 = B2r[8 * s + 4];
                mma16(c1,     a2[0][s], b10, b11);
                mma16(c1 + 4, a2[1][s], b10, b11);
                mma16(c2,     a2[0][s], b20, b21);
                mma16(c2 + 4, a2[1][s], b20, b21);
            }
            int col0 = 8 * j + 2 * q;
            float2 be1v = *(const float2*)&vecf[384 + col0];
            float2 be2v = *(const float2*)&vecf[448 + col0];
            float2 wpv  = *(const float2*)&vecf[128 + col0];
            float2 bpv  = *(const float2*)&vecf[192 + col0];
            #pragma unroll
            for (int t = 0; t < 4; t++) {
                int m = t >> 1, r = t & 1;
                float o1a = c1[m * 4 + 2 * r]     + be1v.x;
                float o1b = c1[m * 4 + 2 * r + 1] + be1v.y;
                float o2a = c2[m * 4 + 2 * r]     + be2v.x;
                float o2b = c2[m * 4 + 2 * r + 1] + be2v.y;
                float sv0 = fmaf(o1a, sigmf(o2a), fmaf(xf[t], wpv.x, bpv.x));
                float sv1 = fmaf(o1b, sigmf(o2b), fmaf(xf[t], wpv.y, bpv.y));
                sv[t][2 * j]     = sv0;
                sv[t][2 * j + 1] = sv1;
                ssum[t] += sv0 + sv1;
                ssq[t]  = fmaf(sv0, sv0, fmaf(sv1, sv1, ssq[t]));
            }
        }

        // ---- per-row LN stats (quad reduce) ----
        #pragma unroll
        for (int off = 1; off < 4; off <<= 1) {
            #pragma unroll
            for (int t = 0; t < 4; t++) {
                ssum[t] += __shfl_xor_sync(0xffffffffu, ssum[t], off);
                ssq[t]  += __shfl_xor_sync(0xffffffffu, ssq[t],  off);
            }
        }

        // ---- normalize + weighted accumulate (all-register) ----
        #pragma unroll
        for (int t = 0; t < 4; t++) {
            float mean = ssum[t] * (1.f / 64.f);
            float var  = ssq[t] * (1.f / 64.f) - mean * mean;
            float inv  = rsqrtf(var + EPS);
            float wi   = wf[t] * inv;            // fold wf into scale
            float wm   = wf[t];
            #pragma unroll
            for (int j = 0; j < 8; j++) {
                int col0 = 8 * j + 2 * q;
                float2 gv = *(const float2*)&vecf[256 + col0];
                float2 bv = *(const float2*)&vecf[320 + col0];
                acc[t][2*j]   = fmaf(wi * (sv[t][2*j]   - mean), gv.x, fmaf(wm, bv.x, acc[t][2*j]));
                acc[t][2*j+1] = fmaf(wi * (sv[t][2*j+1] - mean), gv.y, fmaf(wm, bv.y, acc[t][2*j+1]));
            }
        }

        __syncthreads();   // all warps done with buf before it is refilled
        if (tid == 0 && f + 2 < NF) {
            uint32_t mb = buf ? mbar1 : mbar0;
            MBARRIER_EXPECT_TX(mb, IMG_BYTES);
            bulk_g2s(sbase + buf * IMG_BYTES, &g_img[f + 2][0], IMG_BYTES, mb);
        }
    }

    // ---- store out [BT, 64] ----
    #pragma unroll
    for (int t = 0; t < 4; t++) {
        float* orow = out + (blk + wtok + g + 8 * t) * (size_t)NU;
        #pragma unroll
        for (int j = 0; j < 8; j++)
            *(float2*)&orow[8 * j + 2 * q] = make_float2(acc[t][2 * j], acc[t][2 * j + 1]);
    }
}

// ============================================================================
extern "C" void kernel_launch(void* const* d_in, const int* in_sizes, int n_in,
                              void* d_out, int out_size) {
    const float* x    = (const float*)d_in[0];
    const float* W1   = (const float*)d_in[1];
    const float* b1   = (const float*)d_in[2];
    const float* W2   = (const float*)d_in[3];
    const float* b2   = (const float*)d_in[4];
    const float* Wg1  = (const float*)d_in[5];
    const float* bg1  = (const float*)d_in[6];
    const float* Wg2  = (const float*)d_in[7];
    const float* bg2  = (const float*)d_in[8];
    const float* Wp   = (const float*)d_in[9];
    const float* bp   = (const float*)d_in[10];
    const float* gamma= (const float*)d_in[11];
    const float* beta = (const float*)d_in[12];
    const float* w1w  = (const float*)d_in[13];
    const float* b1w  = (const float*)d_in[14];
    const float* w2w  = (const float*)d_in[15];
    const float* b2w  = (const float*)d_in[16];
    const float* wg1w = (const float*)d_in[17];
    const float* bg1w = (const float*)d_in[18];
    const float* wg2w = (const float*)d_in[19];
    const float* bg2w = (const float*)d_in[20];
    const float* gammaw = (const float*)d_in[21];
    const float* betaw  = (const float*)d_in[22];

    float* outp = (float*)d_out;
    float* wp   = outp + W_OFF;

    cudaFuncSetAttribute(k_weights, cudaFuncAttributeMaxDynamicSharedMemorySize,
                         KW_FLOATS * sizeof(float));
    k_weights<<<BT / 128, 512, KW_FLOATS * sizeof(float)>>>(
        x, w1w, b1w, w2w, b2w, wg1w, bg1w, wg2w, bg2w, gammaw, betaw, wp);

    k_prep<<<NF, 256>>>(W2, Wg1, Wg2, b2, bg1, bg2, W1, b1, Wp, bp, gamma, beta);

    cudaFuncSetAttribute(k_vsn, cudaFuncAttributeMaxDynamicSharedMemorySize, SMEM_TOTAL);
    k_vsn<<<BT / 128, 128, SMEM_TOTAL>>>(x, wp, outp);
}

// round 8
// speedup vs baseline: 1.0169x; 1.0169x over previous
#include <cuda_runtime.h>
#include <cuda_fp16.h>
#include <cstdint>

#define BT 32768
#define NF 32
#define NU 64
#define EPS 1e-3f
#define W_OFF (BT * NU)

// per-feature image (bytes): W2' fp16[64][72] | Wg' fp16[128][72] | vec f32[8][64]
#define IMG_BYTES  29696
#define OFF_WG_B   9216
#define OFF_VEC_B  27648
// k_vsn smem byte offsets
#define H2SV_OFF   59392u          // 8 warps x 4352 B (h2 fp16 [16][72] / sv f32 [16][68])
#define XS_OFF     94208u          // 128*33 floats = 16896 B
#define MBAR_OFF   111104u
#define SMEM_TOTAL 111120u

__device__ __align__(16) unsigned char g_img[NF][IMG_BYTES];

// ---------------- helpers ----------------
__device__ __forceinline__ uint32_t smem_u32(const void* p) {
    uint32_t a;
    asm("{ .reg .u64 t; cvta.to.shared.u64 t, %1; cvt.u32.u64 %0, t; }" : "=r"(a) : "l"(p));
    return a;
}
__device__ __forceinline__ float eluf(float z)  { return z > 0.f ? z : (__expf(z) - 1.f); }
__device__ __forceinline__ float sigmf(float z) {
    float t, h = 0.5f * z;
    asm("tanh.approx.f32 %0, %1;" : "=f"(t) : "f"(h));
    return fmaf(0.5f, t, 0.5f);
}
__device__ __forceinline__ uint32_t packh2(float lo, float hi) {
    __half2 h = __floats2half2_rn(lo, hi);
    return *reinterpret_cast<uint32_t*>(&h);
}
__device__ __forceinline__ void mma16(float* c, const uint32_t* a, uint32_t b0, uint32_t b1) {
    asm volatile(
        "mma.sync.aligned.m16n8k16.row.col.f32.f16.f16.f32 "
        "{%0,%1,%2,%3}, {%4,%5,%6,%7}, {%8,%9}, {%0,%1,%2,%3};"
        : "+f"(c[0]), "+f"(c[1]), "+f"(c[2]), "+f"(c[3])
        : "r"(a[0]), "r"(a[1]), "r"(a[2]), "r"(a[3]), "r"(b0), "r"(b1));
}

#define MBARRIER_INIT(addr, cnt) \
    asm volatile("mbarrier.init.shared.b64 [%0], %1;" :: "r"(addr), "r"(cnt) : "memory")
#define MBARRIER_EXPECT_TX(addr, tx) \
    asm volatile("mbarrier.arrive.expect_tx.shared.b64 _, [%0], %1;" :: "r"(addr), "r"(tx) : "memory")
#define MBARRIER_WAIT_PARITY(addr, par) do { \
    uint32_t _m = (addr); uint32_t _p = (par); uint32_t _d; \
    asm volatile("{ .reg .pred p; mbarrier.try_wait.parity.acquire.cta.shared::cta.b64 p, [%1], %2; selp.b32 %0, 1, 0, p; }" \
        : "=r"(_d) : "r"(_m), "r"(_p) : "memory"); \
    if (!_d) { \
        asm volatile("{ .reg .pred P1; WL_%=: mbarrier.try_wait.parity.acquire.cta.shared::cta.b64 P1, [%0], %1, 0x989680; @P1 bra.uni WD_%=; bra.uni WL_%=; WD_%=: }" \
            :: "r"(_m), "r"(_p) : "memory"); \
    } } while (0)

__device__ __forceinline__ void bulk_g2s(uint32_t dst, const void* src, uint32_t bytes, uint32_t mbar) {
    asm volatile("cp.async.bulk.shared::cluster.global.mbarrier::complete_tx::bytes [%0], [%1], %2, [%3];"
                 :: "r"(dst), "l"(src), "r"(bytes), "r"(mbar) : "memory");
}

// ============================================================================
// Kernel 0: weights GRN + LN + softmax -> w [BT,32]  (R5 version: best measured)
// Block 256 = 128 tokens, 2 threads/token (each owns 16 of 32 outputs).
// ============================================================================
#define KW_S1 0
#define KW_S2 1024
#define KW_G1 2048
#define KW_G2 3072
#define KW_VB 4096        // 6*32
#define KW_X  4288        // 128*36
#define KW_H  8896
#define KW_H2 13504
#define KW_FLOATS 18112

__global__ __launch_bounds__(256) void k_weights(
    const float* __restrict__ x,
    const float* __restrict__ w1w, const float* __restrict__ b1w,
    const float* __restrict__ w2w, const float* __restrict__ b2w,
    const float* __restrict__ wg1w, const float* __restrict__ bg1w,
    const float* __restrict__ wg2w, const float* __restrict__ bg2w,
    const float* __restrict__ gammaw, const float* __restrict__ betaw,
    float* __restrict__ wout)
{
    extern __shared__ float sw[];
    const int tid = threadIdx.x;
    for (int i = tid; i < 1024; i += 256) {
        sw[KW_S1 + i] = w1w[i]; sw[KW_S2 + i] = w2w[i];
        sw[KW_G1 + i] = wg1w[i]; sw[KW_G2 + i] = wg2w[i];
    }
    if (tid < 32) {
        sw[KW_VB + tid]       = b1w[tid];
        sw[KW_VB + 32 + tid]  = b2w[tid];
        sw[KW_VB + 64 + tid]  = bg1w[tid];
        sw[KW_VB + 96 + tid]  = bg2w[tid];
        sw[KW_VB + 128 + tid] = gammaw[tid];
        sw[KW_VB + 160 + tid] = betaw[tid];
    }
    const int tok  = tid >> 1;
    const int gb   = (tid & 1) * 16;
    const size_t tokG = (size_t)blockIdx.x * 128 + tok;
    {
        const float4* xp = (const float4*)(x + tokG * 32 + gb);
        float4* xr = (float4*)&sw[KW_X + tok * 36 + gb];
        #pragma unroll
        for (int c = 0; c < 4; c++) xr[c] = xp[c];
    }
    __syncthreads();

    float h[16];
    #pragma unroll
    for (int g = 0; g < 16; g++) h[g] = sw[KW_VB + gb + g];
    for (int f = 0; f < 32; f++) {
        float xv = sw[KW_X + tok * 36 + f];
        const float4* wr = (const float4*)&sw[KW_S1 + f * 32 + gb];
        #pragma unroll
        for (int c = 0; c < 4; c++) {
            float4 wv = wr[c];
            h[4*c+0] += xv * wv.x; h[4*c+1] += xv * wv.y;
            h[4*c+2] += xv * wv.z; h[4*c+3] += xv * wv.w;
        }
    }
    #pragma unroll
    for (int g = 0; g < 16; g++) {
        float v = h[g];
        sw[KW_H + tok * 36 + gb + g] = (v > 0.f) ? v : (__expf(v) - 1.f);
    }
    __syncthreads();

    float h2[16];
    #pragma unroll
    for (int g = 0; g < 16; g++) h2[g] = sw[KW_VB + 32 + gb + g];
    for (int f = 0; f < 32; f++) {
        float hv = sw[KW_H + tok * 36 + f];
        const float4* wr = (const float4*)&sw[KW_S2 + f * 32 + gb];
        #pragma unroll
        for (int c = 0; c < 4; c++) {
            float4 wv = wr[c];
            h2[4*c+0] += hv * wv.x; h2[4*c+1] += hv * wv.y;
            h2[4*c+2] += hv * wv.z; h2[4*c+3] += hv * wv.w;
        }
    }
    #pragma unroll
    for (int g = 0; g < 16; g++) sw[KW_H2 + tok * 36 + gb + g] = h2[g];
    __syncthreads();

    float o1[16], o2[16];
    #pragma unroll
    for (int g = 0; g < 16; g++) { o1[g] = sw[KW_VB + 64 + gb + g]; o2[g] = sw[KW_VB + 96 + gb + g]; }
    for (int f = 0; f < 32; f++) {
        float hv = sw[KW_H2 + tok * 36 + f];
        const float4* w1r = (const float4*)&sw[KW_G1 + f * 32 + gb];
        const float4* w2r = (const float4*)&sw[KW_G2 + f * 32 + gb];
        #pragma unroll
        for (int c = 0; c < 4; c++) {
            float4 wa = w1r[c], wb = w2r[c];
            o1[4*c+0] += hv * wa.x; o1[4*c+1] += hv * wa.y;
            o1[4*c+2] += hv * wa.z; o1[4*c+3] += hv * wa.w;
            o2[4*c+0] += hv * wb.x; o2[4*c+1] += hv * wb.y;
            o2[4*c+2] += hv * wb.z; o2[4*c+3] += hv * wb.w;
        }
    }

    float s[16], ssum = 0.f, ssq = 0.f;
    #pragma unroll
    for (int g = 0; g < 16; g++) {
        float sg = 1.f / (1.f + __expf(-o2[g]));
        float v = o1[g] * sg + sw[KW_X + tok * 36 + gb + g];
        s[g] = v; ssum += v; ssq += v * v;
    }
    ssum += __shfl_xor_sync(0xffffffffu, ssum, 1);
    ssq  += __shfl_xor_sync(0xffffffffu, ssq, 1);
    float mean = ssum * (1.f / 32.f);
    float var  = ssq * (1.f / 32.f) - mean * mean;
    float inv  = rsqrtf(var + EPS);

    float y[16], mx = -1e30f;
    #pragma unroll
    for (int g = 0; g < 16; g++) {
        float v = (s[g] - mean) * inv * sw[KW_VB + 128 + gb + g] + sw[KW_VB + 160 + gb + g];
        y[g] = v; mx = fmaxf(mx, v);
    }
    mx = fmaxf(mx, __shfl_xor_sync(0xffffffffu, mx, 1));
    float se = 0.f;
    #pragma unroll
    for (int g = 0; g < 16; g++) { float e = __expf(y[g] - mx); y[g] = e; se += e; }
    se += __shfl_xor_sync(0xffffffffu, se, 1);
    float r = 1.f / se;
    {
        float4* op = (float4*)(wout + tokG * 32 + gb);
        #pragma unroll
        for (int c = 0; c < 4; c++)
            op[c] = make_float4(y[4*c] * r, y[4*c+1] * r, y[4*c+2] * r, y[4*c+3] * r);
    }
}

// ============================================================================
// Kernel 1: prep — per-feature fp16 images + folded gate biases.
// ============================================================================
__global__ __launch_bounds__(256) void k_prep(
    const float* __restrict__ W2, const float* __restrict__ Wg1, const float* __restrict__ Wg2,
    const float* __restrict__ b2, const float* __restrict__ bg1, const float* __restrict__ bg2,
    const float* __restrict__ W1, const float* __restrict__ b1,
    const float* __restrict__ Wp, const float* __restrict__ bp,
    const float* __restrict__ gamma, const float* __restrict__ beta)
{
    const int f = blockIdx.x;
    const int tid = threadIdx.x;
    const float* W2f  = W2  + (size_t)f * 4096;
    const float* Wg1f = Wg1 + (size_t)f * 4096;
    const float* Wg2f = Wg2 + (size_t)f * 4096;
    unsigned char* img = g_img[f];
    __half* W2h = (__half*)img;
    __half* Wgh = (__half*)(img + OFF_WG_B);
    float*  vec = (float*)(img + OFF_VEC_B);

    for (int i = tid; i < 4096; i += 256) {
        int n = i >> 6, k = i & 63;
        W2h[n * 72 + k] = __float2half_rn(W2f[k * 64 + n]);
    }
    for (int i = tid; i < 8192; i += 256) {
        int n = i >> 6, k = i & 63;
        float v = (n < 64) ? Wg1f[k * 64 + n] : Wg2f[k * 64 + (n - 64)];
        Wgh[n * 72 + k] = __float2half_rn(v);
    }
    if (tid < 64) {
        int o = f * 64 + tid;
        vec[0   + tid] = W1[o];
        vec[64  + tid] = b1[o];
        vec[128 + tid] = Wp[o];
        vec[192 + tid] = bp[o];
        vec[256 + tid] = gamma[o];
        vec[320 + tid] = beta[o];
        float s1 = bg1[o], s2 = bg2[o];
        for (int u = 0; u < 64; u++) {
            float bv = b2[f * 64 + u];
            s1 += bv * Wg1f[u * 64 + tid];
            s2 += bv * Wg2f[u * 64 + tid];
        }
        vec[384 + tid] = s1;
        vec[448 + tid] = s2;
    }
}

// ============================================================================
// Kernel 2: main — per-feature GRNs via mma.sync fp16.
// CTA = 128 tokens, 256 threads, 8 warps x 16 tokens (ONE m-tile per warp).
// 2 CTAs/SM -> 16 warps/SM for latency hiding.
// ============================================================================
__global__ __launch_bounds__(256, 2) void k_vsn(
    const float* __restrict__ x,
    const float* __restrict__ w,
    float* __restrict__ out)
{
    extern __shared__ char smem[];
    const uint32_t sbase = smem_u32(smem);
    float* xs = (float*)(smem + XS_OFF);

    const int tid  = threadIdx.x;
    const int lane = tid & 31;
    const int warp = tid >> 5;
    const int q    = lane & 3;
    const int g    = lane >> 2;
    const int wtok = warp * 16;
    const size_t blk = (size_t)blockIdx.x * 128;

    uint32_t* h2u = (uint32_t*)(smem + H2SV_OFF) + warp * 1088;   // fp16 [16][72] as words
    float*    svw = (float*)(smem + H2SV_OFF) + warp * 1088;      // f32 [16][68] (same region)

    const uint32_t mbar0 = sbase + MBAR_OFF;
    const uint32_t mbar1 = sbase + MBAR_OFF + 8;
    if (tid == 0) { MBARRIER_INIT(mbar0, 1); MBARRIER_INIT(mbar1, 1); }

    {   // stage x tile [128][33]: 2 threads per row, SCALAR stores (stride 33 is odd)
        const int row  = tid >> 1;
        const int half = (tid & 1) * 16;
        const float4* xp = (const float4*)(x + (blk + row) * NF + half);
        #pragma unroll
        for (int i = 0; i < 4; i++) {
            float4 v = xp[i];
            xs[row * 33 + half + i * 4 + 0] = v.x;
            xs[row * 33 + half + i * 4 + 1] = v.y;
            xs[row * 33 + half + i * 4 + 2] = v.z;
            xs[row * 33 + half + i * 4 + 3] = v.w;
        }
    }
    __syncthreads();
    if (tid == 0) {
        MBARRIER_EXPECT_TX(mbar0, IMG_BYTES);
        bulk_g2s(sbase, &g_img[0][0], IMG_BYTES, mbar0);
        MBARRIER_EXPECT_TX(mbar1, IMG_BYTES);
        bulk_g2s(sbase + IMG_BYTES, &g_img[1][0], IMG_BYTES, mbar1);
    }

    float acc[2][16];
    #pragma unroll
    for (int t = 0; t < 2; t++)
        #pragma unroll
        for (int c = 0; c < 16; c++) acc[t][c] = 0.f;

    #pragma unroll 1
    for (int f = 0; f < NF; f++) {
        const int buf = f & 1;
        MBARRIER_WAIT_PARITY(buf ? mbar1 : mbar0, (f >> 1) & 1);

        const uint32_t* bw   = (const uint32_t*)(smem + buf * IMG_BYTES);
        const uint32_t* wgw  = (const uint32_t*)(smem + buf * IMG_BYTES + OFF_WG_B);
        const float*    vecf = (const float*)(smem + buf * IMG_BYTES + OFF_VEC_B);

        float xf[2], wf[2];
        #pragma unroll
        for (int t = 0; t < 2; t++) {
            int row = g + 8 * t;
            xf[t] = xs[(wtok + row) * 33 + f];
            wf[t] = w[(blk + wtok + row) * NF + f];
        }

        // ---- A1 = fp16(elu(xf*W1+b1)) fragments (one m16 tile) ----
        uint32_t a1[4][4];
        #pragma unroll
        for (int s = 0; s < 4; s++) {
            #pragma unroll
            for (int p = 0; p < 2; p++) {
                int u0 = 16 * s + 2 * q + 8 * p;
                float wa = vecf[u0],     ba = vecf[64 + u0];
                float wb = vecf[u0 + 1], bb = vecf[64 + u0 + 1];
                a1[s][2*p]   = packh2(eluf(fmaf(xf[0], wa, ba)), eluf(fmaf(xf[0], wb, bb)));
                a1[s][2*p+1] = packh2(eluf(fmaf(xf[1], wa, ba)), eluf(fmaf(xf[1], wb, bb)));
            }
        }

        // ---- GEMM1: h2' = h1 @ W2 -> fp16 per-warp tile [16][72] ----
        #pragma unroll
        for (int j = 0; j < 8; j++) {
            const uint32_t* Br = bw + (8 * j + g) * 36 + q;
            float c0[4] = {0.f,0.f,0.f,0.f};
            #pragma unroll
            for (int s = 0; s < 4; s++)
                mma16(c0, a1[s], Br[8 * s], Br[8 * s + 4]);
            int cw = 4 * j + q;
            h2u[(g    ) * 36 + cw] = packh2(c0[0], c0[1]);
            h2u[(g + 8) * 36 + cw] = packh2(c0[2], c0[3]);
        }
        __syncwarp();

        // ---- A2 fragments from fp16 h2 tile ----
        uint32_t a2[4][4];
        #pragma unroll
        for (int s = 0; s < 4; s++) {
            int r0 = g * 36 + 8 * s + q;
            a2[s][0] = h2u[r0];
            a2[s][1] = h2u[r0 + 288];     // +8 rows
            a2[s][2] = h2u[r0 + 4];
            a2[s][3] = h2u[r0 + 292];
        }
        __syncwarp();   // region now reused as f32 sv spill

        // ---- GEMM2 (o1 | o2) + gate + residual ----
        float ssum[2] = {0.f, 0.f};
        float ssq[2]  = {0.f, 0.f};
        #pragma unroll 2
        for (int j = 0; j < 8; j++) {
            const uint32_t* B1r = wgw + (8 * j + g) * 36 + q;
            const uint32_t* B2r = B1r + 2304;   // +64 rows
            float c1[4] = {0.f,0.f,0.f,0.f};
            float c2[4] = {0.f,0.f,0.f,0.f};
            #pragma unroll
            for (int s = 0; s < 4; s++) {
                mma16(c1, a2[s], B1r[8 * s], B1r[8 * s + 4]);
                mma16(c2, a2[s], B2r[8 * s], B2r[8 * s + 4]);
            }
            int col0 = 8 * j + 2 * q;
            float2 be1v = *(const float2*)&vecf[384 + col0];
            float2 be2v = *(const float2*)&vecf[448 + col0];
            float2 wpv  = *(const float2*)&vecf[128 + col0];
            float2 bpv  = *(const float2*)&vecf[192 + col0];
            #pragma unroll
            for (int t = 0; t < 2; t++) {
                float o1a = c1[2*t]     + be1v.x;
                float o1b = c1[2*t + 1] + be1v.y;
                float o2a = c2[2*t]     + be2v.x;
                float o2b = c2[2*t + 1] + be2v.y;
                float sv0 = fmaf(o1a, sigmf(o2a), fmaf(xf[t], wpv.x, bpv.x));
                float sv1 = fmaf(o1b, sigmf(o2b), fmaf(xf[t], wpv.y, bpv.y));
                *(float2*)&svw[(g + 8 * t) * 68 + col0] = make_float2(sv0, sv1);
                ssum[t] += sv0 + sv1;
                ssq[t]  = fmaf(sv0, sv0, fmaf(sv1, sv1, ssq[t]));
            }
        }

        // ---- per-row LN stats (quad reduce over q) ----
        #pragma unroll
        for (int off = 1; off < 4; off <<= 1) {
            #pragma unroll
            for (int t = 0; t < 2; t++) {
                ssum[t] += __shfl_xor_sync(0xffffffffu, ssum[t], off);
                ssq[t]  += __shfl_xor_sync(0xffffffffu, ssq[t],  off);
            }
        }

        // ---- pass 2: normalize + weighted accumulate ----
        #pragma unroll
        for (int t = 0; t < 2; t++) {
            float mean = ssum[t] * (1.f / 64.f);
            float var  = ssq[t] * (1.f / 64.f) - mean * mean;
            float inv  = rsqrtf(var + EPS);
            float wi   = wf[t] * inv;
            float wm   = wf[t];
            #pragma unroll
            for (int j = 0; j < 8; j++) {
                int col0 = 8 * j + 2 * q;
                float2 gv = *(const float2*)&vecf[256 + col0];
                float2 bv = *(const float2*)&vecf[320 + col0];
                float2 sv = *(const float2*)&svw[(g + 8 * t) * 68 + col0];
                acc[t][2*j]   = fmaf(wi * (sv.x - mean), gv.x, fmaf(wm, bv.x, acc[t][2*j]));
                acc[t][2*j+1] = fmaf(wi * (sv.y - mean), gv.y, fmaf(wm, bv.y, acc[t][2*j+1]));
            }
        }

        __syncthreads();   // all warps done with buf before refill
        if (tid == 0 && f + 2 < NF) {
            uint32_t mb = buf ? mbar1 : mbar0;
            MBARRIER_EXPECT_TX(mb, IMG_BYTES);
            bulk_g2s(sbase + buf * IMG_BYTES, &g_img[f + 2][0], IMG_BYTES, mb);
        }
    }

    // ---- store out [BT, 64] ----
    #pragma unroll
    for (int t = 0; t < 2; t++) {
        float* orow = out + (blk + wtok + g + 8 * t) * (size_t)NU;
        #pragma unroll
        for (int j = 0; j < 8; j++)
            *(float2*)&orow[8 * j + 2 * q] = make_float2(acc[t][2 * j], acc[t][2 * j + 1]);
    }
}

// ============================================================================
extern "C" void kernel_launch(void* const* d_in, const int* in_sizes, int n_in,
                              void* d_out, int out_size) {
    const float* x    = (const float*)d_in[0];
    const float* W1   = (const float*)d_in[1];
    const float* b1   = (const float*)d_in[2];
    const float* W2   = (const float*)d_in[3];
    const float* b2   = (const float*)d_in[4];
    const float* Wg1  = (const float*)d_in[5];
    const float* bg1  = (const float*)d_in[6];
    const float* Wg2  = (const float*)d_in[7];
    const float* bg2  = (const float*)d_in[8];
    const float* Wp   = (const float*)d_in[9];
    const float* bp   = (const float*)d_in[10];
    const float* gamma= (const float*)d_in[11];
    const float* beta = (const float*)d_in[12];
    const float* w1w  = (const float*)d_in[13];
    const float* b1w  = (const float*)d_in[14];
    const float* w2w  = (const float*)d_in[15];
    const float* b2w  = (const float*)d_in[16];
    const float* wg1w = (const float*)d_in[17];
    const float* bg1w = (const float*)d_in[18];
    const float* wg2w = (const float*)d_in[19];
    const float* bg2w = (const float*)d_in[20];
    const float* gammaw = (const float*)d_in[21];
    const float* betaw  = (const float*)d_in[22];

    float* outp = (float*)d_out;
    float* wp   = outp + W_OFF;

    cudaFuncSetAttribute(k_weights, cudaFuncAttributeMaxDynamicSharedMemorySize,
                         KW_FLOATS * sizeof(float));
    k_weights<<<BT / 128, 256, KW_FLOATS * sizeof(float)>>>(
        x, w1w, b1w, w2w, b2w, wg1w, bg1w, wg2w, bg2w, gammaw, betaw, wp);

    k_prep<<<NF, 256>>>(W2, Wg1, Wg2, b2, bg1, bg2, W1, b1, Wp, bp, gamma, beta);

    cudaFuncSetAttribute(k_vsn, cudaFuncAttributeMaxDynamicSharedMemorySize, SMEM_TOTAL);
    k_vsn<<<BT / 128, 256, SMEM_TOTAL>>>(x, wp, outp);
}

// round 9
// speedup vs baseline: 1.0417x; 1.0244x over previous
#include <cuda_runtime.h>
#include <cuda_fp16.h>
#include <cstdint>

#define BT 32768
#define NF 32
#define NU 64
#define EPS 1e-3f
#define W_OFF (BT * NU)

// per-feature image (bytes): W2' fp16[64][72] | Wg' fp16[128][72] | vec f32[8][64]
#define IMG_BYTES  29696
#define OFF_WG_B   9216
#define OFF_VEC_B  27648
// k_vsn smem byte offsets
#define H2SV_OFF   59392u          // 8 warps x 4352 B (h2 fp16 [16][72] / sv f32 [16][68])
#define XS_OFF     94208u          // 128*33 floats = 16896 B
#define MBAR_OFF   111104u
#define SMEM_TOTAL 111120u

__device__ __align__(16) unsigned char g_img[NF][IMG_BYTES];

// ---------------- helpers ----------------
__device__ __forceinline__ uint32_t smem_u32(const void* p) {
    uint32_t a;
    asm("{ .reg .u64 t; cvta.to.shared.u64 t, %1; cvt.u32.u64 %0, t; }" : "=r"(a) : "l"(p));
    return a;
}
__device__ __forceinline__ float eluf(float z)  { return z > 0.f ? z : (__expf(z) - 1.f); }
__device__ __forceinline__ float sigmf(float z) {
    float t, h = 0.5f * z;
    asm("tanh.approx.f32 %0, %1;" : "=f"(t) : "f"(h));
    return fmaf(0.5f, t, 0.5f);
}
__device__ __forceinline__ uint32_t packh2(float lo, float hi) {
    __half2 h = __floats2half2_rn(lo, hi);
    return *reinterpret_cast<uint32_t*>(&h);
}
__device__ __forceinline__ void mma16(float* c, const uint32_t* a, uint32_t b0, uint32_t b1) {
    asm volatile(
        "mma.sync.aligned.m16n8k16.row.col.f32.f16.f16.f32 "
        "{%0,%1,%2,%3}, {%4,%5,%6,%7}, {%8,%9}, {%0,%1,%2,%3};"
        : "+f"(c[0]), "+f"(c[1]), "+f"(c[2]), "+f"(c[3])
        : "r"(a[0]), "r"(a[1]), "r"(a[2]), "r"(a[3]), "r"(b0), "r"(b1));
}
__device__ __forceinline__ void ldsm4(uint32_t* r, uint32_t addr) {
    asm volatile("ldmatrix.sync.aligned.m8n8.x4.shared.b16 {%0,%1,%2,%3}, [%4];"
        : "=r"(r[0]), "=r"(r[1]), "=r"(r[2]), "=r"(r[3]) : "r"(addr));
}

#define MBARRIER_INIT(addr, cnt) \
    asm volatile("mbarrier.init.shared.b64 [%0], %1;" :: "r"(addr), "r"(cnt) : "memory")
#define MBARRIER_EXPECT_TX(addr, tx) \
    asm volatile("mbarrier.arrive.expect_tx.shared.b64 _, [%0], %1;" :: "r"(addr), "r"(tx) : "memory")
#define MBARRIER_WAIT_PARITY(addr, par) do { \
    uint32_t _m = (addr); uint32_t _p = (par); uint32_t _d; \
    asm volatile("{ .reg .pred p; mbarrier.try_wait.parity.acquire.cta.shared::cta.b64 p, [%1], %2; selp.b32 %0, 1, 0, p; }" \
        : "=r"(_d) : "r"(_m), "r"(_p) : "memory"); \
    if (!_d) { \
        asm volatile("{ .reg .pred P1; WL_%=: mbarrier.try_wait.parity.acquire.cta.shared::cta.b64 P1, [%0], %1, 0x989680; @P1 bra.uni WD_%=; bra.uni WL_%=; WD_%=: }" \
            :: "r"(_m), "r"(_p) : "memory"); \
    } } while (0)

__device__ __forceinline__ void bulk_g2s(uint32_t dst, const void* src, uint32_t bytes, uint32_t mbar) {
    asm volatile("cp.async.bulk.shared::cluster.global.mbarrier::complete_tx::bytes [%0], [%1], %2, [%3];"
                 :: "r"(dst), "l"(src), "r"(bytes), "r"(mbar) : "memory");
}

// ============================================================================
// Kernel 0: weights GRN + LN + softmax -> w [BT,32]  (best measured version)
// ============================================================================
#define KW_S1 0
#define KW_S2 1024
#define KW_G1 2048
#define KW_G2 3072
#define KW_VB 4096
#define KW_X  4288
#define KW_H  8896
#define KW_H2 13504
#define KW_FLOATS 18112

__global__ __launch_bounds__(256) void k_weights(
    const float* __restrict__ x,
    const float* __restrict__ w1w, const float* __restrict__ b1w,
    const float* __restrict__ w2w, const float* __restrict__ b2w,
    const float* __restrict__ wg1w, const float* __restrict__ bg1w,
    const float* __restrict__ wg2w, const float* __restrict__ bg2w,
    const float* __restrict__ gammaw, const float* __restrict__ betaw,
    float* __restrict__ wout)
{
    extern __shared__ float sw[];
    const int tid = threadIdx.x;
    for (int i = tid; i < 1024; i += 256) {
        sw[KW_S1 + i] = w1w[i]; sw[KW_S2 + i] = w2w[i];
        sw[KW_G1 + i] = wg1w[i]; sw[KW_G2 + i] = wg2w[i];
    }
    if (tid < 32) {
        sw[KW_VB + tid]       = b1w[tid];
        sw[KW_VB + 32 + tid]  = b2w[tid];
        sw[KW_VB + 64 + tid]  = bg1w[tid];
        sw[KW_VB + 96 + tid]  = bg2w[tid];
        sw[KW_VB + 128 + tid] = gammaw[tid];
        sw[KW_VB + 160 + tid] = betaw[tid];
    }
    const int tok  = tid >> 1;
    const int gb   = (tid & 1) * 16;
    const size_t tokG = (size_t)blockIdx.x * 128 + tok;
    {
        const float4* xp = (const float4*)(x + tokG * 32 + gb);
        float4* xr = (float4*)&sw[KW_X + tok * 36 + gb];
        #pragma unroll
        for (int c = 0; c < 4; c++) xr[c] = xp[c];
    }
    __syncthreads();

    float h[16];
    #pragma unroll
    for (int g = 0; g < 16; g++) h[g] = sw[KW_VB + gb + g];
    for (int f = 0; f < 32; f++) {
        float xv = sw[KW_X + tok * 36 + f];
        const float4* wr = (const float4*)&sw[KW_S1 + f * 32 + gb];
        #pragma unroll
        for (int c = 0; c < 4; c++) {
            float4 wv = wr[c];
            h[4*c+0] += xv * wv.x; h[4*c+1] += xv * wv.y;
            h[4*c+2] += xv * wv.z; h[4*c+3] += xv * wv.w;
        }
    }
    #pragma unroll
    for (int g = 0; g < 16; g++) {
        float v = h[g];
        sw[KW_H + tok * 36 + gb + g] = (v > 0.f) ? v : (__expf(v) - 1.f);
    }
    __syncthreads();

    float h2[16];
    #pragma unroll
    for (int g = 0; g < 16; g++) h2[g] = sw[KW_VB + 32 + gb + g];
    for (int f = 0; f < 32; f++) {
        float hv = sw[KW_H + tok * 36 + f];
        const float4* wr = (const float4*)&sw[KW_S2 + f * 32 + gb];
        #pragma unroll
        for (int c = 0; c < 4; c++) {
            float4 wv = wr[c];
            h2[4*c+0] += hv * wv.x; h2[4*c+1] += hv * wv.y;
            h2[4*c+2] += hv * wv.z; h2[4*c+3] += hv * wv.w;
        }
    }
    #pragma unroll
    for (int g = 0; g < 16; g++) sw[KW_H2 + tok * 36 + gb + g] = h2[g];
    __syncthreads();

    float o1[16], o2[16];
    #pragma unroll
    for (int g = 0; g < 16; g++) { o1[g] = sw[KW_VB + 64 + gb + g]; o2[g] = sw[KW_VB + 96 + gb + g]; }
    for (int f = 0; f < 32; f++) {
        float hv = sw[KW_H2 + tok * 36 + f];
        const float4* w1r = (const float4*)&sw[KW_G1 + f * 32 + gb];
        const float4* w2r = (const float4*)&sw[KW_G2 + f * 32 + gb];
        #pragma unroll
        for (int c = 0; c < 4; c++) {
            float4 wa = w1r[c], wb = w2r[c];
            o1[4*c+0] += hv * wa.x; o1[4*c+1] += hv * wa.y;
            o1[4*c+2] += hv * wa.z; o1[4*c+3] += hv * wa.w;
            o2[4*c+0] += hv * wb.x; o2[4*c+1] += hv * wb.y;
            o2[4*c+2] += hv * wb.z; o2[4*c+3] += hv * wb.w;
        }
    }

    float s[16], ssum = 0.f, ssq = 0.f;
    #pragma unroll
    for (int g = 0; g < 16; g++) {
        float sg = 1.f / (1.f + __expf(-o2[g]));
        float v = o1[g] * sg + sw[KW_X + tok * 36 + gb + g];
        s[g] = v; ssum += v; ssq += v * v;
    }
    ssum += __shfl_xor_sync(0xffffffffu, ssum, 1);
    ssq  += __shfl_xor_sync(0xffffffffu, ssq, 1);
    float mean = ssum * (1.f / 32.f);
    float var  = ssq * (1.f / 32.f) - mean * mean;
    float inv  = rsqrtf(var + EPS);

    float y[16], mx = -1e30f;
    #pragma unroll
    for (int g = 0; g < 16; g++) {
        float v = (s[g] - mean) * inv * sw[KW_VB + 128 + gb + g] + sw[KW_VB + 160 + gb + g];
        y[g] = v; mx = fmaxf(mx, v);
    }
    mx = fmaxf(mx, __shfl_xor_sync(0xffffffffu, mx, 1));
    float se = 0.f;
    #pragma unroll
    for (int g = 0; g < 16; g++) { float e = __expf(y[g] - mx); y[g] = e; se += e; }
    se += __shfl_xor_sync(0xffffffffu, se, 1);
    float r = 1.f / se;
    {
        float4* op = (float4*)(wout + tokG * 32 + gb);
        #pragma unroll
        for (int c = 0; c < 4; c++)
            op[c] = make_float4(y[4*c] * r, y[4*c+1] * r, y[4*c+2] * r, y[4*c+3] * r);
    }
}

// ============================================================================
// Kernel 1: prep — per-feature fp16 images + folded gate biases.
// ============================================================================
__global__ __launch_bounds__(256) void k_prep(
    const float* __restrict__ W2, const float* __restrict__ Wg1, const float* __restrict__ Wg2,
    const float* __restrict__ b2, const float* __restrict__ bg1, const float* __restrict__ bg2,
    const float* __restrict__ W1, const float* __restrict__ b1,
    const float* __restrict__ Wp, const float* __restrict__ bp,
    const float* __restrict__ gamma, const float* __restrict__ beta)
{
    const int f = blockIdx.x;
    const int tid = threadIdx.x;
    const float* W2f  = W2  + (size_t)f * 4096;
    const float* Wg1f = Wg1 + (size_t)f * 4096;
    const float* Wg2f = Wg2 + (size_t)f * 4096;
    unsigned char* img = g_img[f];
    __half* W2h = (__half*)img;
    __half* Wgh = (__half*)(img + OFF_WG_B);
    float*  vec = (float*)(img + OFF_VEC_B);

    for (int i = tid; i < 4096; i += 256) {
        int n = i >> 6, k = i & 63;
        W2h[n * 72 + k] = __float2half_rn(W2f[k * 64 + n]);
    }
    for (int i = tid; i < 8192; i += 256) {
        int n = i >> 6, k = i & 63;
        float v = (n < 64) ? Wg1f[k * 64 + n] : Wg2f[k * 64 + (n - 64)];
        Wgh[n * 72 + k] = __float2half_rn(v);
    }
    if (tid < 64) {
        int o = f * 64 + tid;
        vec[0   + tid] = W1[o];
        vec[64  + tid] = b1[o];
        vec[128 + tid] = Wp[o];
        vec[192 + tid] = bp[o];
        vec[256 + tid] = gamma[o];
        vec[320 + tid] = beta[o];
        float s1 = bg1[o], s2 = bg2[o];
        for (int u = 0; u < 64; u++) {
            float bv = b2[f * 64 + u];
            s1 += bv * Wg1f[u * 64 + tid];
            s2 += bv * Wg2f[u * 64 + tid];
        }
        vec[384 + tid] = s1;
        vec[448 + tid] = s2;
    }
}

// ============================================================================
// Kernel 2: main — per-feature GRNs via mma.sync fp16 + ldmatrix B/A loads.
// CTA = 128 tokens, 256 threads, 8 warps x 16 tokens.
// ============================================================================
__global__ __launch_bounds__(256, 2) void k_vsn(
    const float* __restrict__ x,
    const float* __restrict__ w,
    float* __restrict__ out)
{
    extern __shared__ char smem[];
    const uint32_t sbase = smem_u32(smem);
    float* xs = (float*)(smem + XS_OFF);

    const int tid  = threadIdx.x;
    const int lane = tid & 31;
    const int warp = tid >> 5;
    const int q    = lane & 3;
    const int g    = lane >> 2;
    const int lrow = lane & 7;      // ldmatrix row within tile
    const int lmat = lane >> 3;     // ldmatrix tile index
    const int wtok = warp * 16;
    const size_t blk = (size_t)blockIdx.x * 128;

    uint32_t* h2u = (uint32_t*)(smem + H2SV_OFF) + warp * 1088;   // fp16 [16][72] as words
    float*    svw = (float*)(smem + H2SV_OFF) + warp * 1088;      // f32 [16][68] (same region)
    const uint32_t h2a = sbase + H2SV_OFF + warp * 4352;

    const uint32_t mbar0 = sbase + MBAR_OFF;
    const uint32_t mbar1 = sbase + MBAR_OFF + 8;
    if (tid == 0) { MBARRIER_INIT(mbar0, 1); MBARRIER_INIT(mbar1, 1); }

    {   // stage x tile [128][33]: 2 threads per row, scalar stores (odd stride)
        const int row  = tid >> 1;
        const int half = (tid & 1) * 16;
        const float4* xp = (const float4*)(x + (blk + row) * NF + half);
        #pragma unroll
        for (int i = 0; i < 4; i++) {
            float4 v = xp[i];
            xs[row * 33 + half + i * 4 + 0] = v.x;
            xs[row * 33 + half + i * 4 + 1] = v.y;
            xs[row * 33 + half + i * 4 + 2] = v.z;
            xs[row * 33 + half + i * 4 + 3] = v.w;
        }
    }
    __syncthreads();
    if (tid == 0) {
        MBARRIER_EXPECT_TX(mbar0, IMG_BYTES);
        bulk_g2s(sbase, &g_img[0][0], IMG_BYTES, mbar0);
        MBARRIER_EXPECT_TX(mbar1, IMG_BYTES);
        bulk_g2s(sbase + IMG_BYTES, &g_img[1][0], IMG_BYTES, mbar1);
    }

    float acc[2][16];
    #pragma unroll
    for (int t = 0; t < 2; t++)
        #pragma unroll
        for (int c = 0; c < 16; c++) acc[t][c] = 0.f;

    #pragma unroll 1
    for (int f = 0; f < NF; f++) {
        const int buf = f & 1;
        MBARRIER_WAIT_PARITY(buf ? mbar1 : mbar0, (f >> 1) & 1);

        const uint32_t bwa  = sbase + buf * IMG_BYTES;            // W2' base
        const uint32_t wgwa = bwa + OFF_WG_B;                     // Wg' base
        const float*   vecf = (const float*)(smem + buf * IMG_BYTES + OFF_VEC_B);

        float xf[2], wf[2];
        #pragma unroll
        for (int t = 0; t < 2; t++) {
            int row = g + 8 * t;
            xf[t] = xs[(wtok + row) * 33 + f];
            wf[t] = w[(blk + wtok + row) * NF + f];
        }

        // ---- A1 = fp16(elu(xf*W1+b1)) fragments ----
        uint32_t a1[4][4];
        #pragma unroll
        for (int s = 0; s < 4; s++) {
            #pragma unroll
            for (int p = 0; p < 2; p++) {
                int u0 = 16 * s + 2 * q + 8 * p;
                float2 wv  = *(const float2*)&vecf[u0];
                float2 bv2 = *(const float2*)&vecf[64 + u0];
                a1[s][2*p]   = packh2(eluf(fmaf(xf[0], wv.x, bv2.x)), eluf(fmaf(xf[0], wv.y, bv2.y)));
                a1[s][2*p+1] = packh2(eluf(fmaf(xf[1], wv.x, bv2.x)), eluf(fmaf(xf[1], wv.y, bv2.y)));
            }
        }

        // ---- GEMM1: h2' = h1 @ W2 -> fp16 per-warp tile [16][72] ----
        // ldmatrix tiles: m = lmat -> word offset 4*lmat (k = 8*lmat), rows 8j+lrow
        #pragma unroll
        for (int j = 0; j < 8; j++) {
            uint32_t ad = bwa + (uint32_t)(((8 * j + lrow) * 36 + 4 * lmat) * 4);
            uint32_t bb[8];
            ldsm4(bb, ad);            // s=0 (b0,b1), s=1 (b0,b1)
            ldsm4(bb + 4, ad + 64);   // s=2, s=3
            float c0[4] = {0.f,0.f,0.f,0.f};
            mma16(c0, a1[0], bb[0], bb[1]);
            mma16(c0, a1[1], bb[2], bb[3]);
            mma16(c0, a1[2], bb[4], bb[5]);
            mma16(c0, a1[3], bb[6], bb[7]);
            int cw = 4 * j + q;
            h2u[(g    ) * 36 + cw] = packh2(c0[0], c0[1]);
            h2u[(g + 8) * 36 + cw] = packh2(c0[2], c0[3]);
        }
        __syncwarp();

        // ---- A2 fragments from fp16 h2 tile via ldmatrix ----
        // tiles: m0 rows0-7 k-lo, m1 rows8-15 k-lo, m2 rows0-7 k-hi, m3 rows8-15 k-hi
        uint32_t a2[4][4];
        {
            uint32_t abase = h2a + (uint32_t)((((lmat & 1) * 8 + lrow) * 36 + (lmat >> 1) * 4) * 4);
            #pragma unroll
            for (int s = 0; s < 4; s++)
                ldsm4(a2[s], abase + (uint32_t)(32 * s));   // +8 words per s
        }
        __syncwarp();   // region now reused as f32 sv spill

        // ---- GEMM2 (o1 | o2) + gate + residual ----
        float ssum[2] = {0.f, 0.f};
        float ssq[2]  = {0.f, 0.f};
        #pragma unroll 2
        for (int j = 0; j < 8; j++) {
            uint32_t ad1 = wgwa + (uint32_t)(((8 * j + lrow) * 36 + 4 * lmat) * 4);
            uint32_t bb1[8], bb2[8];
            ldsm4(bb1, ad1);
            ldsm4(bb1 + 4, ad1 + 64);
            ldsm4(bb2, ad1 + 9216);         // +64 rows (B2)
            ldsm4(bb2 + 4, ad1 + 9216 + 64);
            float c1[4] = {0.f,0.f,0.f,0.f};
            float c2[4] = {0.f,0.f,0.f,0.f};
            #pragma unroll
            for (int s = 0; s < 4; s++) {
                mma16(c1, a2[s], bb1[2*s], bb1[2*s+1]);
                mma16(c2, a2[s], bb2[2*s], bb2[2*s+1]);
            }
            int col0 = 8 * j + 2 * q;
            float2 be1v = *(const float2*)&vecf[384 + col0];
            float2 be2v = *(const float2*)&vecf[448 + col0];
            float2 wpv  = *(const float2*)&vecf[128 + col0];
            float2 bpv  = *(const float2*)&vecf[192 + col0];
            #pragma unroll
            for (int t = 0; t < 2; t++) {
                float o1a = c1[2*t]     + be1v.x;
                float o1b = c1[2*t + 1] + be1v.y;
                float o2a = c2[2*t]     + be2v.x;
                float o2b = c2[2*t + 1] + be2v.y;
                float sv0 = fmaf(o1a, sigmf(o2a), fmaf(xf[t], wpv.x, bpv.x));
                float sv1 = fmaf(o1b, sigmf(o2b), fmaf(xf[t], wpv.y, bpv.y));
                *(float2*)&svw[(g + 8 * t) * 68 + col0] = make_float2(sv0, sv1);
                ssum[t] += sv0 + sv1;
                ssq[t]  = fmaf(sv0, sv0, fmaf(sv1, sv1, ssq[t]));
            }
        }

        // ---- per-row LN stats (quad reduce over q) ----
        #pragma unroll
        for (int off = 1; off < 4; off <<= 1) {
            #pragma unroll
            for (int t = 0; t < 2; t++) {
                ssum[t] += __shfl_xor_sync(0xffffffffu, ssum[t], off);
                ssq[t]  += __shfl_xor_sync(0xffffffffu, ssq[t],  off);
            }
        }

        // ---- pass 2: normalize + weighted accumulate ----
        #pragma unroll
        for (int t = 0; t < 2; t++) {
            float mean = ssum[t] * (1.f / 64.f);
            float var  = ssq[t] * (1.f / 64.f) - mean * mean;
            float inv  = rsqrtf(var + EPS);
            float wi   = wf[t] * inv;
            float wm   = wf[t];
            #pragma unroll
            for (int j = 0; j < 8; j++) {
                int col0 = 8 * j + 2 * q;
                float2 gv = *(const float2*)&vecf[256 + col0];
                float2 bv = *(const float2*)&vecf[320 + col0];
                float2 sv = *(const float2*)&svw[(g + 8 * t) * 68 + col0];
                acc[t][2*j]   = fmaf(wi * (sv.x - mean), gv.x, fmaf(wm, bv.x, acc[t][2*j]));
                acc[t][2*j+1] = fmaf(wi * (sv.y - mean), gv.y, fmaf(wm, bv.y, acc[t][2*j+1]));
            }
        }

        __syncthreads();   // all warps done with buf before refill
        if (tid == 0 && f + 2 < NF) {
            uint32_t mb = buf ? mbar1 : mbar0;
            MBARRIER_EXPECT_TX(mb, IMG_BYTES);
            bulk_g2s(sbase + buf * IMG_BYTES, &g_img[f + 2][0], IMG_BYTES, mb);
        }
    }

    // ---- store out [BT, 64] ----
    #pragma unroll
    for (int t = 0; t < 2; t++) {
        float* orow = out + (blk + wtok + g + 8 * t) * (size_t)NU;
        #pragma unroll
        for (int j = 0; j < 8; j++)
            *(float2*)&orow[8 * j + 2 * q] = make_float2(acc[t][2 * j], acc[t][2 * j + 1]);
    }
}

// ============================================================================
extern "C" void kernel_launch(void* const* d_in, const int* in_sizes, int n_in,
                              void* d_out, int out_size) {
    const float* x    = (const float*)d_in[0];
    const float* W1   = (const float*)d_in[1];
    const float* b1   = (const float*)d_in[2];
    const float* W2   = (const float*)d_in[3];
    const float* b2   = (const float*)d_in[4];
    const float* Wg1  = (const float*)d_in[5];
    const float* bg1  = (const float*)d_in[6];
    const float* Wg2  = (const float*)d_in[7];
    const float* bg2  = (const float*)d_in[8];
    const float* Wp   = (const float*)d_in[9];
    const float* bp   = (const float*)d_in[10];
    const float* gamma= (const float*)d_in[11];
    const float* beta = (const float*)d_in[12];
    const float* w1w  = (const float*)d_in[13];
    const float* b1w  = (const float*)d_in[14];
    const float* w2w  = (const float*)d_in[15];
    const float* b2w  = (const float*)d_in[16];
    const float* wg1w = (const float*)d_in[17];
    const float* bg1w = (const float*)d_in[18];
    const float* wg2w = (const float*)d_in[19];
    const float* bg2w = (const float*)d_in[20];
    const float* gammaw = (const float*)d_in[21];
    const float* betaw  = (const float*)d_in[22];

    float* outp = (float*)d_out;
    float* wp   = outp + W_OFF;

    cudaFuncSetAttribute(k_weights, cudaFuncAttributeMaxDynamicSharedMemorySize,
                         KW_FLOATS * sizeof(float));
    k_weights<<<BT / 128, 256, KW_FLOATS * sizeof(float)>>>(
        x, w1w, b1w, w2w, b2w, wg1w, bg1w, wg2w, bg2w, gammaw, betaw, wp);

    k_prep<<<NF, 256>>>(W2, Wg1, Wg2, b2, bg1, bg2, W1, b1, Wp, bp, gamma, beta);

    cudaFuncSetAttribute(k_vsn, cudaFuncAttributeMaxDynamicSharedMemorySize, SMEM_TOTAL);
    k_vsn<<<BT / 128, 256, SMEM_TOTAL>>>(x, wp, outp);
}

// round 10
// speedup vs baseline: 1.3394x; 1.2857x over previous
#include <cuda_runtime.h>
#include <cuda_fp16.h>
#include <cstdint>

#define BT 32768
#define NF 32
#define NU 64
#define EPS 1e-3f
#define W_OFF (BT * NU)

// ---- GRN-as-1D-function table ----
#define XMIN  (-6.0f)
#define NSEG  1536
#define DX    0.0078125f
#define INVDX 128.0f
#define NNODE 1537

// per-feature image (bytes): W2' fp16[64][72] | Wg' fp16[128][72] | vec f32[8][64]
#define IMG_BYTES  29696
#define OFF_WG_B   9216
#define OFF_VEC_B  27648

__device__ __align__(16) unsigned char g_img[NF][IMG_BYTES];
__device__ __align__(16) float g_tab[NF][NNODE][NU];   // ~12.6 MB, L2-resident

// ---------------- helpers ----------------
__device__ __forceinline__ uint32_t smem_u32(const void* p) {
    uint32_t a;
    asm("{ .reg .u64 t; cvta.to.shared.u64 t, %1; cvt.u32.u64 %0, t; }" : "=r"(a) : "l"(p));
    return a;
}
__device__ __forceinline__ float eluf(float z)  { return z > 0.f ? z : (__expf(z) - 1.f); }
__device__ __forceinline__ float sigmf(float z) {
    float t, h = 0.5f * z;
    asm("tanh.approx.f32 %0, %1;" : "=f"(t) : "f"(h));
    return fmaf(0.5f, t, 0.5f);
}
__device__ __forceinline__ uint32_t packh2(float lo, float hi) {
    __half2 h = __floats2half2_rn(lo, hi);
    return *reinterpret_cast<uint32_t*>(&h);
}
__device__ __forceinline__ void mma16(float* c, const uint32_t* a, uint32_t b0, uint32_t b1) {
    asm volatile(
        "mma.sync.aligned.m16n8k16.row.col.f32.f16.f16.f32 "
        "{%0,%1,%2,%3}, {%4,%5,%6,%7}, {%8,%9}, {%0,%1,%2,%3};"
        : "+f"(c[0]), "+f"(c[1]), "+f"(c[2]), "+f"(c[3])
        : "r"(a[0]), "r"(a[1]), "r"(a[2]), "r"(a[3]), "r"(b0), "r"(b1));
}
__device__ __forceinline__ void ldsm4(uint32_t* r, uint32_t addr) {
    asm volatile("ldmatrix.sync.aligned.m8n8.x4.shared.b16 {%0,%1,%2,%3}, [%4];"
        : "=r"(r[0]), "=r"(r[1]), "=r"(r[2]), "=r"(r[3]) : "r"(addr));
}

#define MBARRIER_INIT(addr, cnt) \
    asm volatile("mbarrier.init.shared.b64 [%0], %1;" :: "r"(addr), "r"(cnt) : "memory")
#define MBARRIER_EXPECT_TX(addr, tx) \
    asm volatile("mbarrier.arrive.expect_tx.shared.b64 _, [%0], %1;" :: "r"(addr), "r"(tx) : "memory")
#define MBARRIER_WAIT_PARITY(addr, par) do { \
    uint32_t _m = (addr); uint32_t _p = (par); uint32_t _d; \
    asm volatile("{ .reg .pred p; mbarrier.try_wait.parity.acquire.cta.shared::cta.b64 p, [%1], %2; selp.b32 %0, 1, 0, p; }" \
        : "=r"(_d) : "r"(_m), "r"(_p) : "memory"); \
    if (!_d) { \
        asm volatile("{ .reg .pred P1; WL_%=: mbarrier.try_wait.parity.acquire.cta.shared::cta.b64 P1, [%0], %1, 0x989680; @P1 bra.uni WD_%=; bra.uni WL_%=; WD_%=: }" \
            :: "r"(_m), "r"(_p) : "memory"); \
    } } while (0)

__device__ __forceinline__ void bulk_g2s(uint32_t dst, const void* src, uint32_t bytes, uint32_t mbar) {
    asm volatile("cp.async.bulk.shared::cluster.global.mbarrier::complete_tx::bytes [%0], [%1], %2, [%3];"
                 :: "r"(dst), "l"(src), "r"(bytes), "r"(mbar) : "memory");
}

// ============================================================================
// Kernel 0: weights GRN + LN + softmax -> w [BT,32]  (unchanged, best measured)
// ============================================================================
#define KW_S1 0
#define KW_S2 1024
#define KW_G1 2048
#define KW_G2 3072
#define KW_VB 4096
#define KW_X  4288
#define KW_H  8896
#define KW_H2 13504
#define KW_FLOATS 18112

__global__ __launch_bounds__(256) void k_weights(
    const float* __restrict__ x,
    const float* __restrict__ w1w, const float* __restrict__ b1w,
    const float* __restrict__ w2w, const float* __restrict__ b2w,
    const float* __restrict__ wg1w, const float* __restrict__ bg1w,
    const float* __restrict__ wg2w, const float* __restrict__ bg2w,
    const float* __restrict__ gammaw, const float* __restrict__ betaw,
    float* __restrict__ wout)
{
    extern __shared__ float sw[];
    const int tid = threadIdx.x;
    for (int i = tid; i < 1024; i += 256) {
        sw[KW_S1 + i] = w1w[i]; sw[KW_S2 + i] = w2w[i];
        sw[KW_G1 + i] = wg1w[i]; sw[KW_G2 + i] = wg2w[i];
    }
    if (tid < 32) {
        sw[KW_VB + tid]       = b1w[tid];
        sw[KW_VB + 32 + tid]  = b2w[tid];
        sw[KW_VB + 64 + tid]  = bg1w[tid];
        sw[KW_VB + 96 + tid]  = bg2w[tid];
        sw[KW_VB + 128 + tid] = gammaw[tid];
        sw[KW_VB + 160 + tid] = betaw[tid];
    }
    const int tok  = tid >> 1;
    const int gb   = (tid & 1) * 16;
    const size_t tokG = (size_t)blockIdx.x * 128 + tok;
    {
        const float4* xp = (const float4*)(x + tokG * 32 + gb);
        float4* xr = (float4*)&sw[KW_X + tok * 36 + gb];
        #pragma unroll
        for (int c = 0; c < 4; c++) xr[c] = xp[c];
    }
    __syncthreads();

    float h[16];
    #pragma unroll
    for (int g = 0; g < 16; g++) h[g] = sw[KW_VB + gb + g];
    for (int f = 0; f < 32; f++) {
        float xv = sw[KW_X + tok * 36 + f];
        const float4* wr = (const float4*)&sw[KW_S1 + f * 32 + gb];
        #pragma unroll
        for (int c = 0; c < 4; c++) {
            float4 wv = wr[c];
            h[4*c+0] += xv * wv.x; h[4*c+1] += xv * wv.y;
            h[4*c+2] += xv * wv.z; h[4*c+3] += xv * wv.w;
        }
    }
    #pragma unroll
    for (int g = 0; g < 16; g++) {
        float v = h[g];
        sw[KW_H + tok * 36 + gb + g] = (v > 0.f) ? v : (__expf(v) - 1.f);
    }
    __syncthreads();

    float h2[16];
    #pragma unroll
    for (int g = 0; g < 16; g++) h2[g] = sw[KW_VB + 32 + gb + g];
    for (int f = 0; f < 32; f++) {
        float hv = sw[KW_H + tok * 36 + f];
        const float4* wr = (const float4*)&sw[KW_S2 + f * 32 + gb];
        #pragma unroll
        for (int c = 0; c < 4; c++) {
            float4 wv = wr[c];
            h2[4*c+0] += hv * wv.x; h2[4*c+1] += hv * wv.y;
            h2[4*c+2] += hv * wv.z; h2[4*c+3] += hv * wv.w;
        }
    }
    #pragma unroll
    for (int g = 0; g < 16; g++) sw[KW_H2 + tok * 36 + gb + g] = h2[g];
    __syncthreads();

    float o1[16], o2[16];
    #pragma unroll
    for (int g = 0; g < 16; g++) { o1[g] = sw[KW_VB + 64 + gb + g]; o2[g] = sw[KW_VB + 96 + gb + g]; }
    for (int f = 0; f < 32; f++) {
        float hv = sw[KW_H2 + tok * 36 + f];
        const float4* w1r = (const float4*)&sw[KW_G1 + f * 32 + gb];
        const float4* w2r = (const float4*)&sw[KW_G2 + f * 32 + gb];
        #pragma unroll
        for (int c = 0; c < 4; c++) {
            float4 wa = w1r[c], wb = w2r[c];
            o1[4*c+0] += hv * wa.x; o1[4*c+1] += hv * wa.y;
            o1[4*c+2] += hv * wa.z; o1[4*c+3] += hv * wa.w;
            o2[4*c+0] += hv * wb.x; o2[4*c+1] += hv * wb.y;
            o2[4*c+2] += hv * wb.z; o2[4*c+3] += hv * wb.w;
        }
    }

    float s[16], ssum = 0.f, ssq = 0.f;
    #pragma unroll
    for (int g = 0; g < 16; g++) {
        float sg = 1.f / (1.f + __expf(-o2[g]));
        float v = o1[g] * sg + sw[KW_X + tok * 36 + gb + g];
        s[g] = v; ssum += v; ssq += v * v;
    }
    ssum += __shfl_xor_sync(0xffffffffu, ssum, 1);
    ssq  += __shfl_xor_sync(0xffffffffu, ssq, 1);
    float mean = ssum * (1.f / 32.f);
    float var  = ssq * (1.f / 32.f) - mean * mean;
    float inv  = rsqrtf(var + EPS);

    float y[16], mx = -1e30f;
    #pragma unroll
    for (int g = 0; g < 16; g++) {
        float v = (s[g] - mean) * inv * sw[KW_VB + 128 + gb + g] + sw[KW_VB + 160 + gb + g];
        y[g] = v; mx = fmaxf(mx, v);
    }
    mx = fmaxf(mx, __shfl_xor_sync(0xffffffffu, mx, 1));
    float se = 0.f;
    #pragma unroll
    for (int g = 0; g < 16; g++) { float e = __expf(y[g] - mx); y[g] = e; se += e; }
    se += __shfl_xor_sync(0xffffffffu, se, 1);
    float r = 1.f / se;
    {
        float4* op = (float4*)(wout + tokG * 32 + gb);
        #pragma unroll
        for (int c = 0; c < 4; c++)
            op[c] = make_float4(y[4*c] * r, y[4*c+1] * r, y[4*c+2] * r, y[4*c+3] * r);
    }
}

// ============================================================================
// Kernel 1: prep — per-feature fp16 images + folded gate biases (unchanged).
// ============================================================================
__global__ __launch_bounds__(256) void k_prep(
    const float* __restrict__ W2, const float* __restrict__ Wg1, const float* __restrict__ Wg2,
    const float* __restrict__ b2, const float* __restrict__ bg1, const float* __restrict__ bg2,
    const float* __restrict__ W1, const float* __restrict__ b1,
    const float* __restrict__ Wp, const float* __restrict__ bp,
    const float* __restrict__ gamma, const float* __restrict__ beta)
{
    const int f = blockIdx.x;
    const int tid = threadIdx.x;
    const float* W2f  = W2  + (size_t)f * 4096;
    const float* Wg1f = Wg1 + (size_t)f * 4096;
    const float* Wg2f = Wg2 + (size_t)f * 4096;
    unsigned char* img = g_img[f];
    __half* W2h = (__half*)img;
    __half* Wgh = (__half*)(img + OFF_WG_B);
    float*  vec = (float*)(img + OFF_VEC_B);

    for (int i = tid; i < 4096; i += 256) {
        int n = i >> 6, k = i & 63;
        W2h[n * 72 + k] = __float2half_rn(W2f[k * 64 + n]);
    }
    for (int i = tid; i < 8192; i += 256) {
        int n = i >> 6, k = i & 63;
        float v = (n < 64) ? Wg1f[k * 64 + n] : Wg2f[k * 64 + (n - 64)];
        Wgh[n * 72 + k] = __float2half_rn(v);
    }
    if (tid < 64) {
        int o = f * 64 + tid;
        vec[0   + tid] = W1[o];
        vec[64  + tid] = b1[o];
        vec[128 + tid] = Wp[o];
        vec[192 + tid] = bp[o];
        vec[256 + tid] = gamma[o];
        vec[320 + tid] = beta[o];
        float s1 = bg1[o], s2 = bg2[o];
        for (int u = 0; u < 64; u++) {
            float bv = b2[f * 64 + u];
            s1 += bv * Wg1f[u * 64 + tid];
            s2 += bv * Wg2f[u * 64 + tid];
        }
        vec[384 + tid] = s1;
        vec[448 + tid] = s2;
    }
}

// ============================================================================
// Kernel 2: k_tab — evaluate the per-feature GRN (pre-LN) at table nodes via
// the verified fp16 HMMA pipeline. One feature per CTA (grid 13 x 32),
// 256 threads = 8 warps x 16 nodes.
// ============================================================================
#define KT_H2_OFF   29696u
#define KT_MBAR_OFF 48128u
#define KT_SMEM     48144u

__global__ __launch_bounds__(256) void k_tab()
{
    extern __shared__ char smem[];
    const uint32_t sbase = smem_u32(smem);

    const int f    = blockIdx.y;
    const int part = blockIdx.x;
    const int tid  = threadIdx.x;
    const int lane = tid & 31;
    const int warp = tid >> 5;
    const int q    = lane & 3;
    const int g    = lane >> 2;
    const int lrow = lane & 7;
    const int lmat = lane >> 3;
    const int nodeb = part * 128 + warp * 16;

    uint32_t* h2u = (uint32_t*)(smem + KT_H2_OFF) + warp * 576;   // fp16 [16][72] words
    const uint32_t h2a = sbase + KT_H2_OFF + warp * 2304;
    const uint32_t mbar = sbase + KT_MBAR_OFF;

    if (tid == 0) MBARRIER_INIT(mbar, 1);
    __syncthreads();
    if (tid == 0) {
        MBARRIER_EXPECT_TX(mbar, IMG_BYTES);
        bulk_g2s(sbase, &g_img[f][0], IMG_BYTES, mbar);
    }
    MBARRIER_WAIT_PARITY(mbar, 0);

    const uint32_t bwa  = sbase;
    const uint32_t wgwa = sbase + OFF_WG_B;
    const float*   vecf = (const float*)(smem + OFF_VEC_B);

    float xf[2];
    int   node[2];
    #pragma unroll
    for (int t = 0; t < 2; t++) {
        node[t] = nodeb + g + 8 * t;
        xf[t] = XMIN + (float)node[t] * DX;
    }

    // A1 = fp16(elu(xf*W1+b1))
    uint32_t a1[4][4];
    #pragma unroll
    for (int s = 0; s < 4; s++) {
        #pragma unroll
        for (int p = 0; p < 2; p++) {
            int u0 = 16 * s + 2 * q + 8 * p;
            float2 wv  = *(const float2*)&vecf[u0];
            float2 bv2 = *(const float2*)&vecf[64 + u0];
            a1[s][2*p]   = packh2(eluf(fmaf(xf[0], wv.x, bv2.x)), eluf(fmaf(xf[0], wv.y, bv2.y)));
            a1[s][2*p+1] = packh2(eluf(fmaf(xf[1], wv.x, bv2.x)), eluf(fmaf(xf[1], wv.y, bv2.y)));
        }
    }

    // GEMM1 -> h2 fp16 tile
    #pragma unroll
    for (int j = 0; j < 8; j++) {
        uint32_t ad = bwa + (uint32_t)(((8 * j + lrow) * 36 + 4 * lmat) * 4);
        uint32_t bb[8];
        ldsm4(bb, ad);
        ldsm4(bb + 4, ad + 64);
        float c0[4] = {0.f,0.f,0.f,0.f};
        mma16(c0, a1[0], bb[0], bb[1]);
        mma16(c0, a1[1], bb[2], bb[3]);
        mma16(c0, a1[2], bb[4], bb[5]);
        mma16(c0, a1[3], bb[6], bb[7]);
        int cw = 4 * j + q;
        h2u[(g    ) * 36 + cw] = packh2(c0[0], c0[1]);
        h2u[(g + 8) * 36 + cw] = packh2(c0[2], c0[3]);
    }
    __syncwarp();

    // A2 fragments
    uint32_t a2[4][4];
    {
        uint32_t abase = h2a + (uint32_t)((((lmat & 1) * 8 + lrow) * 36 + (lmat >> 1) * 4) * 4);
        #pragma unroll
        for (int s = 0; s < 4; s++)
            ldsm4(a2[s], abase + (uint32_t)(32 * s));
    }

    // GEMM2 (o1|o2) + gate + residual -> table rows
    #pragma unroll 2
    for (int j = 0; j < 8; j++) {
        uint32_t ad1 = wgwa + (uint32_t)(((8 * j + lrow) * 36 + 4 * lmat) * 4);
        uint32_t bb1[8], bb2[8];
        ldsm4(bb1, ad1);
        ldsm4(bb1 + 4, ad1 + 64);
        ldsm4(bb2, ad1 + 9216);
        ldsm4(bb2 + 4, ad1 + 9216 + 64);
        float c1[4] = {0.f,0.f,0.f,0.f};
        float c2[4] = {0.f,0.f,0.f,0.f};
        #pragma unroll
        for (int s = 0; s < 4; s++) {
            mma16(c1, a2[s], bb1[2*s], bb1[2*s+1]);
            mma16(c2, a2[s], bb2[2*s], bb2[2*s+1]);
        }
        int col0 = 8 * j + 2 * q;
        float2 be1v = *(const float2*)&vecf[384 + col0];
        float2 be2v = *(const float2*)&vecf[448 + col0];
        float2 wpv  = *(const float2*)&vecf[128 + col0];
        float2 bpv  = *(const float2*)&vecf[192 + col0];
        #pragma unroll
        for (int t = 0; t < 2; t++) {
            float o1a = c1[2*t]     + be1v.x;
            float o1b = c1[2*t + 1] + be1v.y;
            float o2a = c2[2*t]     + be2v.x;
            float o2b = c2[2*t + 1] + be2v.y;
            float sv0 = fmaf(o1a, sigmf(o2a), fmaf(xf[t], wpv.x, bpv.x));
            float sv1 = fmaf(o1b, sigmf(o2b), fmaf(xf[t], wpv.y, bpv.y));
            if (node[t] < NNODE)
                *(float2*)&g_tab[f][node[t]][col0] = make_float2(sv0, sv1);
        }
    }
}

// ============================================================================
// Kernel 3: k_main — per (token,f): table lerp -> s[64]; LN; acc += w_f * y.
// CTA = 64 tokens, 256 threads (4 threads/token x 16 u each). Grid 512.
// ============================================================================
#define KM_XS  0                 // 64*33 floats
#define KM_WS  2112
#define KM_GAM 4224              // 32*64
#define KM_BET 6272
#define KM_FLOATS 8320           // 33280 B

__global__ __launch_bounds__(256, 2) void k_main(
    const float* __restrict__ x,
    const float* __restrict__ w,
    const float* __restrict__ gamma, const float* __restrict__ beta,
    float* __restrict__ out)
{
    extern __shared__ float sm[];
    const int tid = threadIdx.x;
    const int tok = tid >> 2;
    const int ql  = tid & 3;
    const int gb  = ql * 16;
    const size_t blk = (size_t)blockIdx.x * 64;

    {   // stage x/w rows (scalar stores: odd stride 33)
        const int off = ql * 8;
        const float2* xp = (const float2*)(x + (blk + tok) * NF + off);
        const float2* wp = (const float2*)(w + (blk + tok) * NF + off);
        #pragma unroll
        for (int i = 0; i < 4; i++) {
            float2 xv = xp[i], wv = wp[i];
            sm[KM_XS + tok * 33 + off + 2*i]     = xv.x;
            sm[KM_XS + tok * 33 + off + 2*i + 1] = xv.y;
            sm[KM_WS + tok * 33 + off + 2*i]     = wv.x;
            sm[KM_WS + tok * 33 + off + 2*i + 1] = wv.y;
        }
        for (int i = tid; i < 2048; i += 256) {
            sm[KM_GAM + i] = gamma[i];
            sm[KM_BET + i] = beta[i];
        }
    }
    __syncthreads();

    float acc[16];
    #pragma unroll
    for (int c = 0; c < 16; c++) acc[c] = 0.f;

    #pragma unroll 1
    for (int f = 0; f < NF; f++) {
        float xf = sm[KM_XS + tok * 33 + f];
        float wf = sm[KM_WS + tok * 33 + f];

        float tpos = (xf - XMIN) * INVDX;
        int   i    = (int)tpos;
        i = (i < 0) ? 0 : ((i > NSEG - 1) ? NSEG - 1 : i);
        float fr = tpos - (float)i;

        const float4* r0 = (const float4*)&g_tab[f][i][gb];
        const float4* r1 = (const float4*)&g_tab[f][i + 1][gb];

        float sv[16];
        float ssum = 0.f, ssq = 0.f;
        #pragma unroll
        for (int c = 0; c < 4; c++) {
            float4 a = r0[c], b = r1[c];
            float v0 = fmaf(fr, b.x - a.x, a.x);
            float v1 = fmaf(fr, b.y - a.y, a.y);
            float v2 = fmaf(fr, b.z - a.z, a.z);
            float v3 = fmaf(fr, b.w - a.w, a.w);
            sv[4*c] = v0; sv[4*c+1] = v1; sv[4*c+2] = v2; sv[4*c+3] = v3;
            ssum += (v0 + v1) + (v2 + v3);
            ssq = fmaf(v0, v0, fmaf(v1, v1, fmaf(v2, v2, fmaf(v3, v3, ssq))));
        }
        ssum += __shfl_xor_sync(0xffffffffu, ssum, 1);
        ssq  += __shfl_xor_sync(0xffffffffu, ssq,  1);
        ssum += __shfl_xor_sync(0xffffffffu, ssum, 2);
        ssq  += __shfl_xor_sync(0xffffffffu, ssq,  2);

        float mean = ssum * (1.f / 64.f);
        float var  = ssq * (1.f / 64.f) - mean * mean;
        float inv  = rsqrtf(var + EPS);
        float wi   = wf * inv;

        const float4* gp = (const float4*)&sm[KM_GAM + f * 64 + gb];
        const float4* bp = (const float4*)&sm[KM_BET + f * 64 + gb];
        #pragma unroll
        for (int c = 0; c < 4; c++) {
            float4 gv = gp[c], bv = bp[c];
            acc[4*c]   = fmaf(wi * (sv[4*c]   - mean), gv.x, fmaf(wf, bv.x, acc[4*c]));
            acc[4*c+1] = fmaf(wi * (sv[4*c+1] - mean), gv.y, fmaf(wf, bv.y, acc[4*c+1]));
            acc[4*c+2] = fmaf(wi * (sv[4*c+2] - mean), gv.z, fmaf(wf, bv.z, acc[4*c+2]));
            acc[4*c+3] = fmaf(wi * (sv[4*c+3] - mean), gv.w, fmaf(wf, bv.w, acc[4*c+3]));
        }
    }

    {
        float4* op = (float4*)(out + (blk + tok) * NU + gb);
        #pragma unroll
        for (int c = 0; c < 4; c++)
            op[c] = make_float4(acc[4*c], acc[4*c+1], acc[4*c+2], acc[4*c+3]);
    }
}

// ============================================================================
extern "C" void kernel_launch(void* const* d_in, const int* in_sizes, int n_in,
                              void* d_out, int out_size) {
    const float* x    = (const float*)d_in[0];
    const float* W1   = (const float*)d_in[1];
    const float* b1   = (const float*)d_in[2];
    const float* W2   = (const float*)d_in[3];
    const float* b2   = (const float*)d_in[4];
    const float* Wg1  = (const float*)d_in[5];
    const float* bg1  = (const float*)d_in[6];
    const float* Wg2  = (const float*)d_in[7];
    const float* bg2  = (const float*)d_in[8];
    const float* Wp   = (const float*)d_in[9];
    const float* bp   = (const float*)d_in[10];
    const float* gamma= (const float*)d_in[11];
    const float* beta = (const float*)d_in[12];
    const float* w1w  = (const float*)d_in[13];
    const float* b1w  = (const float*)d_in[14];
    const float* w2w  = (const float*)d_in[15];
    const float* b2w  = (const float*)d_in[16];
    const float* wg1w = (const float*)d_in[17];
    const float* bg1w = (const float*)d_in[18];
    const float* wg2w = (const float*)d_in[19];
    const float* bg2w = (const float*)d_in[20];
    const float* gammaw = (const float*)d_in[21];
    const float* betaw  = (const float*)d_in[22];

    float* outp = (float*)d_out;
    float* wp   = outp + W_OFF;

    cudaFuncSetAttribute(k_weights, cudaFuncAttributeMaxDynamicSharedMemorySize,
                         KW_FLOATS * sizeof(float));
    k_weights<<<BT / 128, 256, KW_FLOATS * sizeof(float)>>>(
        x, w1w, b1w, w2w, b2w, wg1w, bg1w, wg2w, bg2w, gammaw, betaw, wp);

    k_prep<<<NF, 256>>>(W2, Wg1, Wg2, b2, bg1, bg2, W1, b1, Wp, bp, gamma, beta);

    cudaFuncSetAttribute(k_tab, cudaFuncAttributeMaxDynamicSharedMemorySize, KT_SMEM);
    k_tab<<<dim3(13, 32), 256, KT_SMEM>>>();

    cudaFuncSetAttribute(k_main, cudaFuncAttributeMaxDynamicSharedMemorySize,
                         KM_FLOATS * sizeof(float));
    k_main<<<BT / 64, 256, KM_FLOATS * sizeof(float)>>>(x, wp, gamma, beta, outp);
}

// round 11
// speedup vs baseline: 1.9431x; 1.4507x over previous
#include <cuda_runtime.h>
#include <cuda_fp16.h>
#include <cstdint>

#define BT 32768
#define NF 32
#define NU 64
#define EPS 1e-3f
#define W_OFF (BT * NU)

// ---- GRN-as-1D-function table ----
#define XMIN  (-6.0f)
#define NSEG  1536
#define DX    0.0078125f
#define INVDX 128.0f
#define NNODE 1537

// per-feature image (bytes): W2' fp16[64][72] | Wg' fp16[128][72] | vec f32[8][64]
#define IMG_BYTES  29696
#define OFF_WG_B   9216
#define OFF_VEC_B  27648

__device__ __align__(16) unsigned char g_img[NF][IMG_BYTES];
__device__ __align__(16) uint32_t g_tab[NF][NNODE][NU / 2];   // half2-packed, ~6.3 MB

// ---------------- helpers ----------------
__device__ __forceinline__ uint32_t smem_u32(const void* p) {
    uint32_t a;
    asm("{ .reg .u64 t; cvta.to.shared.u64 t, %1; cvt.u32.u64 %0, t; }" : "=r"(a) : "l"(p));
    return a;
}
__device__ __forceinline__ float eluf(float z)  { return z > 0.f ? z : (__expf(z) - 1.f); }
__device__ __forceinline__ float sigmf(float z) {
    float t, h = 0.5f * z;
    asm("tanh.approx.f32 %0, %1;" : "=f"(t) : "f"(h));
    return fmaf(0.5f, t, 0.5f);
}
__device__ __forceinline__ uint32_t packh2(float lo, float hi) {
    __half2 h = __floats2half2_rn(lo, hi);
    return *reinterpret_cast<uint32_t*>(&h);
}
__device__ __forceinline__ float2 unpackh2(uint32_t u) {
    __half2 h = *reinterpret_cast<__half2*>(&u);
    return __half22float2(h);
}
__device__ __forceinline__ void mma16(float* c, const uint32_t* a, uint32_t b0, uint32_t b1) {
    asm volatile(
        "mma.sync.aligned.m16n8k16.row.col.f32.f16.f16.f32 "
        "{%0,%1,%2,%3}, {%4,%5,%6,%7}, {%8,%9}, {%0,%1,%2,%3};"
        : "+f"(c[0]), "+f"(c[1]), "+f"(c[2]), "+f"(c[3])
        : "r"(a[0]), "r"(a[1]), "r"(a[2]), "r"(a[3]), "r"(b0), "r"(b1));
}
__device__ __forceinline__ void ldsm4(uint32_t* r, uint32_t addr) {
    asm volatile("ldmatrix.sync.aligned.m8n8.x4.shared.b16 {%0,%1,%2,%3}, [%4];"
        : "=r"(r[0]), "=r"(r[1]), "=r"(r[2]), "=r"(r[3]) : "r"(addr));
}

#define MBARRIER_INIT(addr, cnt) \
    asm volatile("mbarrier.init.shared.b64 [%0], %1;" :: "r"(addr), "r"(cnt) : "memory")
#define MBARRIER_EXPECT_TX(addr, tx) \
    asm volatile("mbarrier.arrive.expect_tx.shared.b64 _, [%0], %1;" :: "r"(addr), "r"(tx) : "memory")
#define MBARRIER_WAIT_PARITY(addr, par) do { \
    uint32_t _m = (addr); uint32_t _p = (par); uint32_t _d; \
    asm volatile("{ .reg .pred p; mbarrier.try_wait.parity.acquire.cta.shared::cta.b64 p, [%1], %2; selp.b32 %0, 1, 0, p; }" \
        : "=r"(_d) : "r"(_m), "r"(_p) : "memory"); \
    if (!_d) { \
        asm volatile("{ .reg .pred P1; WL_%=: mbarrier.try_wait.parity.acquire.cta.shared::cta.b64 P1, [%0], %1, 0x989680; @P1 bra.uni WD_%=; bra.uni WL_%=; WD_%=: }" \
            :: "r"(_m), "r"(_p) : "memory"); \
    } } while (0)

__device__ __forceinline__ void bulk_g2s(uint32_t dst, const void* src, uint32_t bytes, uint32_t mbar) {
    asm volatile("cp.async.bulk.shared::cluster.global.mbarrier::complete_tx::bytes [%0], [%1], %2, [%3];"
                 :: "r"(dst), "l"(src), "r"(bytes), "r"(mbar) : "memory");
}

// ============================================================================
// Kernel 0: weights GRN + LN + softmax -> w [BT,32]  (unchanged, best measured)
// ============================================================================
#define KW_S1 0
#define KW_S2 1024
#define KW_G1 2048
#define KW_G2 3072
#define KW_VB 4096
#define KW_X  4288
#define KW_H  8896
#define KW_H2 13504
#define KW_FLOATS 18112

__global__ __launch_bounds__(256) void k_weights(
    const float* __restrict__ x,
    const float* __restrict__ w1w, const float* __restrict__ b1w,
    const float* __restrict__ w2w, const float* __restrict__ b2w,
    const float* __restrict__ wg1w, const float* __restrict__ bg1w,
    const float* __restrict__ wg2w, const float* __restrict__ bg2w,
    const float* __restrict__ gammaw, const float* __restrict__ betaw,
    float* __restrict__ wout)
{
    extern __shared__ float sw[];
    const int tid = threadIdx.x;
    for (int i = tid; i < 1024; i += 256) {
        sw[KW_S1 + i] = w1w[i]; sw[KW_S2 + i] = w2w[i];
        sw[KW_G1 + i] = wg1w[i]; sw[KW_G2 + i] = wg2w[i];
    }
    if (tid < 32) {
        sw[KW_VB + tid]       = b1w[tid];
        sw[KW_VB + 32 + tid]  = b2w[tid];
        sw[KW_VB + 64 + tid]  = bg1w[tid];
        sw[KW_VB + 96 + tid]  = bg2w[tid];
        sw[KW_VB + 128 + tid] = gammaw[tid];
        sw[KW_VB + 160 + tid] = betaw[tid];
    }
    const int tok  = tid >> 1;
    const int gb   = (tid & 1) * 16;
    const size_t tokG = (size_t)blockIdx.x * 128 + tok;
    {
        const float4* xp = (const float4*)(x + tokG * 32 + gb);
        float4* xr = (float4*)&sw[KW_X + tok * 36 + gb];
        #pragma unroll
        for (int c = 0; c < 4; c++) xr[c] = xp[c];
    }
    __syncthreads();

    float h[16];
    #pragma unroll
    for (int g = 0; g < 16; g++) h[g] = sw[KW_VB + gb + g];
    for (int f = 0; f < 32; f++) {
        float xv = sw[KW_X + tok * 36 + f];
        const float4* wr = (const float4*)&sw[KW_S1 + f * 32 + gb];
        #pragma unroll
        for (int c = 0; c < 4; c++) {
            float4 wv = wr[c];
            h[4*c+0] += xv * wv.x; h[4*c+1] += xv * wv.y;
            h[4*c+2] += xv * wv.z; h[4*c+3] += xv * wv.w;
        }
    }
    #pragma unroll
    for (int g = 0; g < 16; g++) {
        float v = h[g];
        sw[KW_H + tok * 36 + gb + g] = (v > 0.f) ? v : (__expf(v) - 1.f);
    }
    __syncthreads();

    float h2[16];
    #pragma unroll
    for (int g = 0; g < 16; g++) h2[g] = sw[KW_VB + 32 + gb + g];
    for (int f = 0; f < 32; f++) {
        float hv = sw[KW_H + tok * 36 + f];
        const float4* wr = (const float4*)&sw[KW_S2 + f * 32 + gb];
        #pragma unroll
        for (int c = 0; c < 4; c++) {
            float4 wv = wr[c];
            h2[4*c+0] += hv * wv.x; h2[4*c+1] += hv * wv.y;
            h2[4*c+2] += hv * wv.z; h2[4*c+3] += hv * wv.w;
        }
    }
    #pragma unroll
    for (int g = 0; g < 16; g++) sw[KW_H2 + tok * 36 + gb + g] = h2[g];
    __syncthreads();

    float o1[16], o2[16];
    #pragma unroll
    for (int g = 0; g < 16; g++) { o1[g] = sw[KW_VB + 64 + gb + g]; o2[g] = sw[KW_VB + 96 + gb + g]; }
    for (int f = 0; f < 32; f++) {
        float hv = sw[KW_H2 + tok * 36 + f];
        const float4* w1r = (const float4*)&sw[KW_G1 + f * 32 + gb];
        const float4* w2r = (const float4*)&sw[KW_G2 + f * 32 + gb];
        #pragma unroll
        for (int c = 0; c < 4; c++) {
            float4 wa = w1r[c], wb = w2r[c];
            o1[4*c+0] += hv * wa.x; o1[4*c+1] += hv * wa.y;
            o1[4*c+2] += hv * wa.z; o1[4*c+3] += hv * wa.w;
            o2[4*c+0] += hv * wb.x; o2[4*c+1] += hv * wb.y;
            o2[4*c+2] += hv * wb.z; o2[4*c+3] += hv * wb.w;
        }
    }

    float s[16], ssum = 0.f, ssq = 0.f;
    #pragma unroll
    for (int g = 0; g < 16; g++) {
        float sg = 1.f / (1.f + __expf(-o2[g]));
        float v = o1[g] * sg + sw[KW_X + tok * 36 + gb + g];
        s[g] = v; ssum += v; ssq += v * v;
    }
    ssum += __shfl_xor_sync(0xffffffffu, ssum, 1);
    ssq  += __shfl_xor_sync(0xffffffffu, ssq, 1);
    float mean = ssum * (1.f / 32.f);
    float var  = ssq * (1.f / 32.f) - mean * mean;
    float inv  = rsqrtf(var + EPS);

    float y[16], mx = -1e30f;
    #pragma unroll
    for (int g = 0; g < 16; g++) {
        float v = (s[g] - mean) * inv * sw[KW_VB + 128 + gb + g] + sw[KW_VB + 160 + gb + g];
        y[g] = v; mx = fmaxf(mx, v);
    }
    mx = fmaxf(mx, __shfl_xor_sync(0xffffffffu, mx, 1));
    float se = 0.f;
    #pragma unroll
    for (int g = 0; g < 16; g++) { float e = __expf(y[g] - mx); y[g] = e; se += e; }
    se += __shfl_xor_sync(0xffffffffu, se, 1);
    float r = 1.f / se;
    {
        float4* op = (float4*)(wout + tokG * 32 + gb);
        #pragma unroll
        for (int c = 0; c < 4; c++)
            op[c] = make_float4(y[4*c] * r, y[4*c+1] * r, y[4*c+2] * r, y[4*c+3] * r);
    }
}

// ============================================================================
// Kernel 1: prep — per-feature fp16 images + folded gate biases (unchanged).
// ============================================================================
__global__ __launch_bounds__(256) void k_prep(
    const float* __restrict__ W2, const float* __restrict__ Wg1, const float* __restrict__ Wg2,
    const float* __restrict__ b2, const float* __restrict__ bg1, const float* __restrict__ bg2,
    const float* __restrict__ W1, const float* __restrict__ b1,
    const float* __restrict__ Wp, const float* __restrict__ bp,
    const float* __restrict__ gamma, const float* __restrict__ beta)
{
    const int f = blockIdx.x;
    const int tid = threadIdx.x;
    const float* W2f  = W2  + (size_t)f * 4096;
    const float* Wg1f = Wg1 + (size_t)f * 4096;
    const float* Wg2f = Wg2 + (size_t)f * 4096;
    unsigned char* img = g_img[f];
    __half* W2h = (__half*)img;
    __half* Wgh = (__half*)(img + OFF_WG_B);
    float*  vec = (float*)(img + OFF_VEC_B);

    for (int i = tid; i < 4096; i += 256) {
        int n = i >> 6, k = i & 63;
        W2h[n * 72 + k] = __float2half_rn(W2f[k * 64 + n]);
    }
    for (int i = tid; i < 8192; i += 256) {
        int n = i >> 6, k = i & 63;
        float v = (n < 64) ? Wg1f[k * 64 + n] : Wg2f[k * 64 + (n - 64)];
        Wgh[n * 72 + k] = __float2half_rn(v);
    }
    if (tid < 64) {
        int o = f * 64 + tid;
        vec[0   + tid] = W1[o];
        vec[64  + tid] = b1[o];
        vec[128 + tid] = Wp[o];
        vec[192 + tid] = bp[o];
        vec[256 + tid] = gamma[o];
        vec[320 + tid] = beta[o];
        float s1 = bg1[o], s2 = bg2[o];
        for (int u = 0; u < 64; u++) {
            float bv = b2[f * 64 + u];
            s1 += bv * Wg1f[u * 64 + tid];
            s2 += bv * Wg2f[u * 64 + tid];
        }
        vec[384 + tid] = s1;
        vec[448 + tid] = s2;
    }
}

// ============================================================================
// Kernel 2: k_tab — evaluate per-feature GRN (pre-LN) at table nodes via HMMA.
// One feature per CTA-row (grid 13 x 32), 256 threads = 8 warps x 16 nodes.
// Writes half2-packed table rows.
// ============================================================================
#define KT_H2_OFF   29696u
#define KT_MBAR_OFF 48128u
#define KT_SMEM     48144u

__global__ __launch_bounds__(256) void k_tab()
{
    extern __shared__ char smem[];
    const uint32_t sbase = smem_u32(smem);

    const int f    = blockIdx.y;
    const int part = blockIdx.x;
    const int tid  = threadIdx.x;
    const int lane = tid & 31;
    const int warp = tid >> 5;
    const int q    = lane & 3;
    const int g    = lane >> 2;
    const int lrow = lane & 7;
    const int lmat = lane >> 3;
    const int nodeb = part * 128 + warp * 16;

    uint32_t* h2u = (uint32_t*)(smem + KT_H2_OFF) + warp * 576;
    const uint32_t h2a = sbase + KT_H2_OFF + warp * 2304;
    const uint32_t mbar = sbase + KT_MBAR_OFF;

    if (tid == 0) MBARRIER_INIT(mbar, 1);
    __syncthreads();
    if (tid == 0) {
        MBARRIER_EXPECT_TX(mbar, IMG_BYTES);
        bulk_g2s(sbase, &g_img[f][0], IMG_BYTES, mbar);
    }
    MBARRIER_WAIT_PARITY(mbar, 0);

    const uint32_t bwa  = sbase;
    const uint32_t wgwa = sbase + OFF_WG_B;
    const float*   vecf = (const float*)(smem + OFF_VEC_B);

    float xf[2];
    int   node[2];
    #pragma unroll
    for (int t = 0; t < 2; t++) {
        node[t] = nodeb + g + 8 * t;
        xf[t] = XMIN + (float)node[t] * DX;
    }

    // A1 = fp16(elu(xf*W1+b1))
    uint32_t a1[4][4];
    #pragma unroll
    for (int s = 0; s < 4; s++) {
        #pragma unroll
        for (int p = 0; p < 2; p++) {
            int u0 = 16 * s + 2 * q + 8 * p;
            float2 wv  = *(const float2*)&vecf[u0];
            float2 bv2 = *(const float2*)&vecf[64 + u0];
            a1[s][2*p]   = packh2(eluf(fmaf(xf[0], wv.x, bv2.x)), eluf(fmaf(xf[0], wv.y, bv2.y)));
            a1[s][2*p+1] = packh2(eluf(fmaf(xf[1], wv.x, bv2.x)), eluf(fmaf(xf[1], wv.y, bv2.y)));
        }
    }

    // GEMM1 -> h2 fp16 tile
    #pragma unroll
    for (int j = 0; j < 8; j++) {
        uint32_t ad = bwa + (uint32_t)(((8 * j + lrow) * 36 + 4 * lmat) * 4);
        uint32_t bb[8];
        ldsm4(bb, ad);
        ldsm4(bb + 4, ad + 64);
        float c0[4] = {0.f,0.f,0.f,0.f};
        mma16(c0, a1[0], bb[0], bb[1]);
        mma16(c0, a1[1], bb[2], bb[3]);
        mma16(c0, a1[2], bb[4], bb[5]);
        mma16(c0, a1[3], bb[6], bb[7]);
        int cw = 4 * j + q;
        h2u[(g    ) * 36 + cw] = packh2(c0[0], c0[1]);
        h2u[(g + 8) * 36 + cw] = packh2(c0[2], c0[3]);
    }
    __syncwarp();

    // A2 fragments
    uint32_t a2[4][4];
    {
        uint32_t abase = h2a + (uint32_t)((((lmat & 1) * 8 + lrow) * 36 + (lmat >> 1) * 4) * 4);
        #pragma unroll
        for (int s = 0; s < 4; s++)
            ldsm4(a2[s], abase + (uint32_t)(32 * s));
    }

    // GEMM2 (o1|o2) + gate + residual -> half2-packed table rows
    #pragma unroll 2
    for (int j = 0; j < 8; j++) {
        uint32_t ad1 = wgwa + (uint32_t)(((8 * j + lrow) * 36 + 4 * lmat) * 4);
        uint32_t bb1[8], bb2[8];
        ldsm4(bb1, ad1);
        ldsm4(bb1 + 4, ad1 + 64);
        ldsm4(bb2, ad1 + 9216);
        ldsm4(bb2 + 4, ad1 + 9216 + 64);
        float c1[4] = {0.f,0.f,0.f,0.f};
        float c2[4] = {0.f,0.f,0.f,0.f};
        #pragma unroll
        for (int s = 0; s < 4; s++) {
            mma16(c1, a2[s], bb1[2*s], bb1[2*s+1]);
            mma16(c2, a2[s], bb2[2*s], bb2[2*s+1]);
        }
        int col0 = 8 * j + 2 * q;
        float2 be1v = *(const float2*)&vecf[384 + col0];
        float2 be2v = *(const float2*)&vecf[448 + col0];
        float2 wpv  = *(const float2*)&vecf[128 + col0];
        float2 bpv  = *(const float2*)&vecf[192 + col0];
        #pragma unroll
        for (int t = 0; t < 2; t++) {
            float o1a = c1[2*t]     + be1v.x;
            float o1b = c1[2*t + 1] + be1v.y;
            float o2a = c2[2*t]     + be2v.x;
            float o2b = c2[2*t + 1] + be2v.y;
            float sv0 = fmaf(o1a, sigmf(o2a), fmaf(xf[t], wpv.x, bpv.x));
            float sv1 = fmaf(o1b, sigmf(o2b), fmaf(xf[t], wpv.y, bpv.y));
            if (node[t] < NNODE)
                g_tab[f][node[t]][4 * j + q] = packh2(sv0, sv1);
        }
    }
}

// ============================================================================
// Kernel 3: k_main — per (token,f): fp16 table lerp -> s[64]; LN; acc += w_f*y.
// CTA = 64 tokens, 256 threads (4 threads/token x 16 u each). Grid 512.
// ============================================================================
#define KM_XS  0                 // 64*33 floats
#define KM_WS  2112
#define KM_GAM 4224              // 32*64
#define KM_BET 6272
#define KM_FLOATS 8320           // 33280 B

__global__ __launch_bounds__(256, 2) void k_main(
    const float* __restrict__ x,
    const float* __restrict__ w,
    const float* __restrict__ gamma, const float* __restrict__ beta,
    float* __restrict__ out)
{
    extern __shared__ float sm[];
    const int tid = threadIdx.x;
    const int tok = tid >> 2;
    const int ql  = tid & 3;
    const int gb  = ql * 16;
    const size_t blk = (size_t)blockIdx.x * 64;

    {   // stage x/w rows (scalar stores: odd stride 33)
        const int off = ql * 8;
        const float2* xp = (const float2*)(x + (blk + tok) * NF + off);
        const float2* wp = (const float2*)(w + (blk + tok) * NF + off);
        #pragma unroll
        for (int i = 0; i < 4; i++) {
            float2 xv = xp[i], wv = wp[i];
            sm[KM_XS + tok * 33 + off + 2*i]     = xv.x;
            sm[KM_XS + tok * 33 + off + 2*i + 1] = xv.y;
            sm[KM_WS + tok * 33 + off + 2*i]     = wv.x;
            sm[KM_WS + tok * 33 + off + 2*i + 1] = wv.y;
        }
        for (int i = tid; i < 2048; i += 256) {
            sm[KM_GAM + i] = gamma[i];
            sm[KM_BET + i] = beta[i];
        }
    }
    __syncthreads();

    float acc[16];
    #pragma unroll
    for (int c = 0; c < 16; c++) acc[c] = 0.f;

    #pragma unroll 1
    for (int f = 0; f < NF; f++) {
        float xf = sm[KM_XS + tok * 33 + f];
        float wf = sm[KM_WS + tok * 33 + f];

        float tpos = (xf - XMIN) * INVDX;
        int   i    = (int)tpos;
        i = (i < 0) ? 0 : ((i > NSEG - 1) ? NSEG - 1 : i);
        float fr = tpos - (float)i;

        // fp16 table: thread covers 8 half2 words per row = 2 uint4 loads/row
        const uint4* r0 = (const uint4*)&g_tab[f][i][ql * 8];
        const uint4* r1 = (const uint4*)&g_tab[f][i + 1][ql * 8];
        uint4 a0 = r0[0], a1v = r0[1];
        uint4 b0 = r1[0], b1v = r1[1];

        float sv[16];
        float ssum = 0.f, ssq = 0.f;
        {
            const uint32_t aw[8] = { a0.x, a0.y, a0.z, a0.w, a1v.x, a1v.y, a1v.z, a1v.w };
            const uint32_t bw[8] = { b0.x, b0.y, b0.z, b0.w, b1v.x, b1v.y, b1v.z, b1v.w };
            #pragma unroll
            for (int c = 0; c < 8; c++) {
                float2 av = unpackh2(aw[c]);
                float2 bv = unpackh2(bw[c]);
                float v0 = fmaf(fr, bv.x - av.x, av.x);
                float v1 = fmaf(fr, bv.y - av.y, av.y);
                sv[2*c] = v0; sv[2*c+1] = v1;
                ssum += v0 + v1;
                ssq = fmaf(v0, v0, fmaf(v1, v1, ssq));
            }
        }
        ssum += __shfl_xor_sync(0xffffffffu, ssum, 1);
        ssq  += __shfl_xor_sync(0xffffffffu, ssq,  1);
        ssum += __shfl_xor_sync(0xffffffffu, ssum, 2);
        ssq  += __shfl_xor_sync(0xffffffffu, ssq,  2);

        float mean = ssum * (1.f / 64.f);
        float var  = ssq * (1.f / 64.f) - mean * mean;
        float inv  = rsqrtf(var + EPS);
        float wi   = wf * inv;

        const float4* gp = (const float4*)&sm[KM_GAM + f * 64 + gb];
        const float4* bp = (const float4*)&sm[KM_BET + f * 64 + gb];
        #pragma unroll
        for (int c = 0; c < 4; c++) {
            float4 gv = gp[c], bv = bp[c];
            acc[4*c]   = fmaf(wi * (sv[4*c]   - mean), gv.x, fmaf(wf, bv.x, acc[4*c]));
            acc[4*c+1] = fmaf(wi * (sv[4*c+1] - mean), gv.y, fmaf(wf, bv.y, acc[4*c+1]));
            acc[4*c+2] = fmaf(wi * (sv[4*c+2] - mean), gv.z, fmaf(wf, bv.z, acc[4*c+2]));
            acc[4*c+3] = fmaf(wi * (sv[4*c+3] - mean), gv.w, fmaf(wf, bv.w, acc[4*c+3]));
        }
    }

    {
        float4* op = (float4*)(out + (blk + tok) * NU + gb);
        #pragma unroll
        for (int c = 0; c < 4; c++)
            op[c] = make_float4(acc[4*c], acc[4*c+1], acc[4*c+2], acc[4*c+3]);
    }
}

// ============================================================================
extern "C" void kernel_launch(void* const* d_in, const int* in_sizes, int n_in,
                              void* d_out, int out_size) {
    const float* x    = (const float*)d_in[0];
    const float* W1   = (const float*)d_in[1];
    const float* b1   = (const float*)d_in[2];
    const float* W2   = (const float*)d_in[3];
    const float* b2   = (const float*)d_in[4];
    const float* Wg1  = (const float*)d_in[5];
    const float* bg1  = (const float*)d_in[6];
    const float* Wg2  = (const float*)d_in[7];
    const float* bg2  = (const float*)d_in[8];
    const float* Wp   = (const float*)d_in[9];
    const float* bp   = (const float*)d_in[10];
    const float* gamma= (const float*)d_in[11];
    const float* beta = (const float*)d_in[12];
    const float* w1w  = (const float*)d_in[13];
    const float* b1w  = (const float*)d_in[14];
    const float* w2w  = (const float*)d_in[15];
    const float* b2w  = (const float*)d_in[16];
    const float* wg1w = (const float*)d_in[17];
    const float* bg1w = (const float*)d_in[18];
    const float* wg2w = (const float*)d_in[19];
    const float* bg2w = (const float*)d_in[20];
    const float* gammaw = (const float*)d_in[21];
    const float* betaw  = (const float*)d_in[22];

    float* outp = (float*)d_out;
    float* wp   = outp + W_OFF;

    cudaFuncSetAttribute(k_weights, cudaFuncAttributeMaxDynamicSharedMemorySize,
                         KW_FLOATS * sizeof(float));
    k_weights<<<BT / 128, 256, KW_FLOATS * sizeof(float)>>>(
        x, w1w, b1w, w2w, b2w, wg1w, bg1w, wg2w, bg2w, gammaw, betaw, wp);

    k_prep<<<NF, 256>>>(W2, Wg1, Wg2, b2, bg1, bg2, W1, b1, Wp, bp, gamma, beta);

    cudaFuncSetAttribute(k_tab, cudaFuncAttributeMaxDynamicSharedMemorySize, KT_SMEM);
    k_tab<<<dim3(13, 32), 256, KT_SMEM>>>();

    cudaFuncSetAttribute(k_main, cudaFuncAttributeMaxDynamicSharedMemorySize,
                         KM_FLOATS * sizeof(float));
    k_main<<<BT / 64, 256, KM_FLOATS * sizeof(float)>>>(x, wp, gamma, beta, outp);
}

// round 12
// speedup vs baseline: 2.9626x; 1.5246x over previous
#include <cuda_runtime.h>
#include <cuda_fp16.h>
#include <cstdint>

#define BT 32768
#define NF 32
#define NU 64
#define EPS 1e-3f
#define W_OFF (BT * NU)

// ---- GRN-as-1D-function table (post-LN y values) ----
#define XMIN  (-6.0f)
#define NSEG  1536
#define DX    0.0078125f
#define INVDX 128.0f
#define NNODE 1537

// per-feature image (bytes): W2' fp16[64][72] | Wg' fp16[128][72] | vec f32[8][64]
#define IMG_BYTES  29696
#define OFF_WG_B   9216
#define OFF_VEC_B  27648

__device__ __align__(16) unsigned char g_img[NF][IMG_BYTES];
__device__ __align__(16) uint32_t g_tab[NF][NNODE][NU / 2];   // half2-packed y, ~6.3 MB

// ---------------- helpers ----------------
__device__ __forceinline__ uint32_t smem_u32(const void* p) {
    uint32_t a;
    asm("{ .reg .u64 t; cvta.to.shared.u64 t, %1; cvt.u32.u64 %0, t; }" : "=r"(a) : "l"(p));
    return a;
}
__device__ __forceinline__ float eluf(float z)  { return z > 0.f ? z : (__expf(z) - 1.f); }
__device__ __forceinline__ float sigmf(float z) {
    float t, h = 0.5f * z;
    asm("tanh.approx.f32 %0, %1;" : "=f"(t) : "f"(h));
    return fmaf(0.5f, t, 0.5f);
}
__device__ __forceinline__ uint32_t packh2(float lo, float hi) {
    __half2 h = __floats2half2_rn(lo, hi);
    return *reinterpret_cast<uint32_t*>(&h);
}
__device__ __forceinline__ float2 unpackh2(uint32_t u) {
    __half2 h = *reinterpret_cast<__half2*>(&u);
    return __half22float2(h);
}
__device__ __forceinline__ void mma16(float* c, const uint32_t* a, uint32_t b0, uint32_t b1) {
    asm volatile(
        "mma.sync.aligned.m16n8k16.row.col.f32.f16.f16.f32 "
        "{%0,%1,%2,%3}, {%4,%5,%6,%7}, {%8,%9}, {%0,%1,%2,%3};"
        : "+f"(c[0]), "+f"(c[1]), "+f"(c[2]), "+f"(c[3])
        : "r"(a[0]), "r"(a[1]), "r"(a[2]), "r"(a[3]), "r"(b0), "r"(b1));
}
__device__ __forceinline__ void ldsm4(uint32_t* r, uint32_t addr) {
    asm volatile("ldmatrix.sync.aligned.m8n8.x4.shared.b16 {%0,%1,%2,%3}, [%4];"
        : "=r"(r[0]), "=r"(r[1]), "=r"(r[2]), "=r"(r[3]) : "r"(addr));
}

#define MBARRIER_INIT(addr, cnt) \
    asm volatile("mbarrier.init.shared.b64 [%0], %1;" :: "r"(addr), "r"(cnt) : "memory")
#define MBARRIER_EXPECT_TX(addr, tx) \
    asm volatile("mbarrier.arrive.expect_tx.shared.b64 _, [%0], %1;" :: "r"(addr), "r"(tx) : "memory")
#define MBARRIER_WAIT_PARITY(addr, par) do { \
    uint32_t _m = (addr); uint32_t _p = (par); uint32_t _d; \
    asm volatile("{ .reg .pred p; mbarrier.try_wait.parity.acquire.cta.shared::cta.b64 p, [%1], %2; selp.b32 %0, 1, 0, p; }" \
        : "=r"(_d) : "r"(_m), "r"(_p) : "memory"); \
    if (!_d) { \
        asm volatile("{ .reg .pred P1; WL_%=: mbarrier.try_wait.parity.acquire.cta.shared::cta.b64 P1, [%0], %1, 0x989680; @P1 bra.uni WD_%=; bra.uni WL_%=; WD_%=: }" \
            :: "r"(_m), "r"(_p) : "memory"); \
    } } while (0)

__device__ __forceinline__ void bulk_g2s(uint32_t dst, const void* src, uint32_t bytes, uint32_t mbar) {
    asm volatile("cp.async.bulk.shared::cluster.global.mbarrier::complete_tx::bytes [%0], [%1], %2, [%3];"
                 :: "r"(dst), "l"(src), "r"(bytes), "r"(mbar) : "memory");
}

// ============================================================================
// Kernel 0: weights GRN + LN + softmax -> w [BT,32]  (unchanged, best measured)
// ============================================================================
#define KW_S1 0
#define KW_S2 1024
#define KW_G1 2048
#define KW_G2 3072
#define KW_VB 4096
#define KW_X  4288
#define KW_H  8896
#define KW_H2 13504
#define KW_FLOATS 18112

__global__ __launch_bounds__(256) void k_weights(
    const float* __restrict__ x,
    const float* __restrict__ w1w, const float* __restrict__ b1w,
    const float* __restrict__ w2w, const float* __restrict__ b2w,
    const float* __restrict__ wg1w, const float* __restrict__ bg1w,
    const float* __restrict__ wg2w, const float* __restrict__ bg2w,
    const float* __restrict__ gammaw, const float* __restrict__ betaw,
    float* __restrict__ wout)
{
    extern __shared__ float sw[];
    const int tid = threadIdx.x;
    for (int i = tid; i < 1024; i += 256) {
        sw[KW_S1 + i] = w1w[i]; sw[KW_S2 + i] = w2w[i];
        sw[KW_G1 + i] = wg1w[i]; sw[KW_G2 + i] = wg2w[i];
    }
    if (tid < 32) {
        sw[KW_VB + tid]       = b1w[tid];
        sw[KW_VB + 32 + tid]  = b2w[tid];
        sw[KW_VB + 64 + tid]  = bg1w[tid];
        sw[KW_VB + 96 + tid]  = bg2w[tid];
        sw[KW_VB + 128 + tid] = gammaw[tid];
        sw[KW_VB + 160 + tid] = betaw[tid];
    }
    const int tok  = tid >> 1;
    const int gb   = (tid & 1) * 16;
    const size_t tokG = (size_t)blockIdx.x * 128 + tok;
    {
        const float4* xp = (const float4*)(x + tokG * 32 + gb);
        float4* xr = (float4*)&sw[KW_X + tok * 36 + gb];
        #pragma unroll
        for (int c = 0; c < 4; c++) xr[c] = xp[c];
    }
    __syncthreads();

    float h[16];
    #pragma unroll
    for (int g = 0; g < 16; g++) h[g] = sw[KW_VB + gb + g];
    for (int f = 0; f < 32; f++) {
        float xv = sw[KW_X + tok * 36 + f];
        const float4* wr = (const float4*)&sw[KW_S1 + f * 32 + gb];
        #pragma unroll
        for (int c = 0; c < 4; c++) {
            float4 wv = wr[c];
            h[4*c+0] += xv * wv.x; h[4*c+1] += xv * wv.y;
            h[4*c+2] += xv * wv.z; h[4*c+3] += xv * wv.w;
        }
    }
    #pragma unroll
    for (int g = 0; g < 16; g++) {
        float v = h[g];
        sw[KW_H + tok * 36 + gb + g] = (v > 0.f) ? v : (__expf(v) - 1.f);
    }
    __syncthreads();

    float h2[16];
    #pragma unroll
    for (int g = 0; g < 16; g++) h2[g] = sw[KW_VB + 32 + gb + g];
    for (int f = 0; f < 32; f++) {
        float hv = sw[KW_H + tok * 36 + f];
        const float4* wr = (const float4*)&sw[KW_S2 + f * 32 + gb];
        #pragma unroll
        for (int c = 0; c < 4; c++) {
            float4 wv = wr[c];
            h2[4*c+0] += hv * wv.x; h2[4*c+1] += hv * wv.y;
            h2[4*c+2] += hv * wv.z; h2[4*c+3] += hv * wv.w;
        }
    }
    #pragma unroll
    for (int g = 0; g < 16; g++) sw[KW_H2 + tok * 36 + gb + g] = h2[g];
    __syncthreads();

    float o1[16], o2[16];
    #pragma unroll
    for (int g = 0; g < 16; g++) { o1[g] = sw[KW_VB + 64 + gb + g]; o2[g] = sw[KW_VB + 96 + gb + g]; }
    for (int f = 0; f < 32; f++) {
        float hv = sw[KW_H2 + tok * 36 + f];
        const float4* w1r = (const float4*)&sw[KW_G1 + f * 32 + gb];
        const float4* w2r = (const float4*)&sw[KW_G2 + f * 32 + gb];
        #pragma unroll
        for (int c = 0; c < 4; c++) {
            float4 wa = w1r[c], wb = w2r[c];
            o1[4*c+0] += hv * wa.x; o1[4*c+1] += hv * wa.y;
            o1[4*c+2] += hv * wa.z; o1[4*c+3] += hv * wa.w;
            o2[4*c+0] += hv * wb.x; o2[4*c+1] += hv * wb.y;
            o2[4*c+2] += hv * wb.z; o2[4*c+3] += hv * wb.w;
        }
    }

    float s[16], ssum = 0.f, ssq = 0.f;
    #pragma unroll
    for (int g = 0; g < 16; g++) {
        float sg = 1.f / (1.f + __expf(-o2[g]));
        float v = o1[g] * sg + sw[KW_X + tok * 36 + gb + g];
        s[g] = v; ssum += v; ssq += v * v;
    }
    ssum += __shfl_xor_sync(0xffffffffu, ssum, 1);
    ssq  += __shfl_xor_sync(0xffffffffu, ssq, 1);
    float mean = ssum * (1.f / 32.f);
    float var  = ssq * (1.f / 32.f) - mean * mean;
    float inv  = rsqrtf(var + EPS);

    float y[16], mx = -1e30f;
    #pragma unroll
    for (int g = 0; g < 16; g++) {
        float v = (s[g] - mean) * inv * sw[KW_VB + 128 + gb + g] + sw[KW_VB + 160 + gb + g];
        y[g] = v; mx = fmaxf(mx, v);
    }
    mx = fmaxf(mx, __shfl_xor_sync(0xffffffffu, mx, 1));
    float se = 0.f;
    #pragma unroll
    for (int g = 0; g < 16; g++) { float e = __expf(y[g] - mx); y[g] = e; se += e; }
    se += __shfl_xor_sync(0xffffffffu, se, 1);
    float r = 1.f / se;
    {
        float4* op = (float4*)(wout + tokG * 32 + gb);
        #pragma unroll
        for (int c = 0; c < 4; c++)
            op[c] = make_float4(y[4*c] * r, y[4*c+1] * r, y[4*c+2] * r, y[4*c+3] * r);
    }
}

// ============================================================================
// Kernel 1: prep — per-feature fp16 images + folded gate biases (unchanged).
// ============================================================================
__global__ __launch_bounds__(256) void k_prep(
    const float* __restrict__ W2, const float* __restrict__ Wg1, const float* __restrict__ Wg2,
    const float* __restrict__ b2, const float* __restrict__ bg1, const float* __restrict__ bg2,
    const float* __restrict__ W1, const float* __restrict__ b1,
    const float* __restrict__ Wp, const float* __restrict__ bp,
    const float* __restrict__ gamma, const float* __restrict__ beta)
{
    const int f = blockIdx.x;
    const int tid = threadIdx.x;
    const float* W2f  = W2  + (size_t)f * 4096;
    const float* Wg1f = Wg1 + (size_t)f * 4096;
    const float* Wg2f = Wg2 + (size_t)f * 4096;
    unsigned char* img = g_img[f];
    __half* W2h = (__half*)img;
    __half* Wgh = (__half*)(img + OFF_WG_B);
    float*  vec = (float*)(img + OFF_VEC_B);

    for (int i = tid; i < 4096; i += 256) {
        int n = i >> 6, k = i & 63;
        W2h[n * 72 + k] = __float2half_rn(W2f[k * 64 + n]);
    }
    for (int i = tid; i < 8192; i += 256) {
        int n = i >> 6, k = i & 63;
        float v = (n < 64) ? Wg1f[k * 64 + n] : Wg2f[k * 64 + (n - 64)];
        Wgh[n * 72 + k] = __float2half_rn(v);
    }
    if (tid < 64) {
        int o = f * 64 + tid;
        vec[0   + tid] = W1[o];
        vec[64  + tid] = b1[o];
        vec[128 + tid] = Wp[o];
        vec[192 + tid] = bp[o];
        vec[256 + tid] = gamma[o];
        vec[320 + tid] = beta[o];
        float s1 = bg1[o], s2 = bg2[o];
        for (int u = 0; u < 64; u++) {
            float bv = b2[f * 64 + u];
            s1 += bv * Wg1f[u * 64 + tid];
            s2 += bv * Wg2f[u * 64 + tid];
        }
        vec[384 + tid] = s1;
        vec[448 + tid] = s2;
    }
}

// ============================================================================
// Kernel 2: k_tab — per-feature GRN at table nodes via HMMA, then LN per node
// row, storing POST-LN y = (s-mean)*inv*gamma+beta as half2-packed rows.
// Grid 13 x 32, 256 threads = 8 warps x 16 nodes.
// ============================================================================
#define KT_H2_OFF   29696u
#define KT_MBAR_OFF 48128u
#define KT_SMEM     48144u

__global__ __launch_bounds__(256) void k_tab()
{
    extern __shared__ char smem[];
    const uint32_t sbase = smem_u32(smem);

    const int f    = blockIdx.y;
    const int part = blockIdx.x;
    const int tid  = threadIdx.x;
    const int lane = tid & 31;
    const int warp = tid >> 5;
    const int q    = lane & 3;
    const int g    = lane >> 2;
    const int lrow = lane & 7;
    const int lmat = lane >> 3;
    const int nodeb = part * 128 + warp * 16;

    uint32_t* h2u = (uint32_t*)(smem + KT_H2_OFF) + warp * 576;
    const uint32_t h2a = sbase + KT_H2_OFF + warp * 2304;
    const uint32_t mbar = sbase + KT_MBAR_OFF;

    if (tid == 0) MBARRIER_INIT(mbar, 1);
    __syncthreads();
    if (tid == 0) {
        MBARRIER_EXPECT_TX(mbar, IMG_BYTES);
        bulk_g2s(sbase, &g_img[f][0], IMG_BYTES, mbar);
    }
    MBARRIER_WAIT_PARITY(mbar, 0);

    const uint32_t bwa  = sbase;
    const uint32_t wgwa = sbase + OFF_WG_B;
    const float*   vecf = (const float*)(smem + OFF_VEC_B);

    float xf[2];
    int   node[2];
    #pragma unroll
    for (int t = 0; t < 2; t++) {
        node[t] = nodeb + g + 8 * t;
        xf[t] = XMIN + (float)node[t] * DX;
    }

    // A1 = fp16(elu(xf*W1+b1))
    uint32_t a1[4][4];
    #pragma unroll
    for (int s = 0; s < 4; s++) {
        #pragma unroll
        for (int p = 0; p < 2; p++) {
            int u0 = 16 * s + 2 * q + 8 * p;
            float2 wv  = *(const float2*)&vecf[u0];
            float2 bv2 = *(const float2*)&vecf[64 + u0];
            a1[s][2*p]   = packh2(eluf(fmaf(xf[0], wv.x, bv2.x)), eluf(fmaf(xf[0], wv.y, bv2.y)));
            a1[s][2*p+1] = packh2(eluf(fmaf(xf[1], wv.x, bv2.x)), eluf(fmaf(xf[1], wv.y, bv2.y)));
        }
    }

    // GEMM1 -> h2 fp16 tile
    #pragma unroll
    for (int j = 0; j < 8; j++) {
        uint32_t ad = bwa + (uint32_t)(((8 * j + lrow) * 36 + 4 * lmat) * 4);
        uint32_t bb[8];
        ldsm4(bb, ad);
        ldsm4(bb + 4, ad + 64);
        float c0[4] = {0.f,0.f,0.f,0.f};
        mma16(c0, a1[0], bb[0], bb[1]);
        mma16(c0, a1[1], bb[2], bb[3]);
        mma16(c0, a1[2], bb[4], bb[5]);
        mma16(c0, a1[3], bb[6], bb[7]);
        int cw = 4 * j + q;
        h2u[(g    ) * 36 + cw] = packh2(c0[0], c0[1]);
        h2u[(g + 8) * 36 + cw] = packh2(c0[2], c0[3]);
    }
    __syncwarp();

    // A2 fragments
    uint32_t a2[4][4];
    {
        uint32_t abase = h2a + (uint32_t)((((lmat & 1) * 8 + lrow) * 36 + (lmat >> 1) * 4) * 4);
        #pragma unroll
        for (int s = 0; s < 4; s++)
            ldsm4(a2[s], abase + (uint32_t)(32 * s));
    }

    // GEMM2 (o1|o2) + gate + residual -> sv registers
    float sv[2][16];
    float ssum[2] = {0.f, 0.f};
    float ssq[2]  = {0.f, 0.f};
    #pragma unroll 2
    for (int j = 0; j < 8; j++) {
        uint32_t ad1 = wgwa + (uint32_t)(((8 * j + lrow) * 36 + 4 * lmat) * 4);
        uint32_t bb1[8], bb2[8];
        ldsm4(bb1, ad1);
        ldsm4(bb1 + 4, ad1 + 64);
        ldsm4(bb2, ad1 + 9216);
        ldsm4(bb2 + 4, ad1 + 9216 + 64);
        float c1[4] = {0.f,0.f,0.f,0.f};
        float c2[4] = {0.f,0.f,0.f,0.f};
        #pragma unroll
        for (int s = 0; s < 4; s++) {
            mma16(c1, a2[s], bb1[2*s], bb1[2*s+1]);
            mma16(c2, a2[s], bb2[2*s], bb2[2*s+1]);
        }
        int col0 = 8 * j + 2 * q;
        float2 be1v = *(const float2*)&vecf[384 + col0];
        float2 be2v = *(const float2*)&vecf[448 + col0];
        float2 wpv  = *(const float2*)&vecf[128 + col0];
        float2 bpv  = *(const float2*)&vecf[192 + col0];
        #pragma unroll
        for (int t = 0; t < 2; t++) {
            float o1a = c1[2*t]     + be1v.x;
            float o1b = c1[2*t + 1] + be1v.y;
            float o2a = c2[2*t]     + be2v.x;
            float o2b = c2[2*t + 1] + be2v.y;
            float sv0 = fmaf(o1a, sigmf(o2a), fmaf(xf[t], wpv.x, bpv.x));
            float sv1 = fmaf(o1b, sigmf(o2b), fmaf(xf[t], wpv.y, bpv.y));
            sv[t][2*j]     = sv0;
            sv[t][2*j + 1] = sv1;
            ssum[t] += sv0 + sv1;
            ssq[t]  = fmaf(sv0, sv0, fmaf(sv1, sv1, ssq[t]));
        }
    }

    // LN stats per node row (quad reduce over q lanes)
    #pragma unroll
    for (int off = 1; off < 4; off <<= 1) {
        #pragma unroll
        for (int t = 0; t < 2; t++) {
            ssum[t] += __shfl_xor_sync(0xffffffffu, ssum[t], off);
            ssq[t]  += __shfl_xor_sync(0xffffffffu, ssq[t],  off);
        }
    }

    // normalize + gamma/beta -> fp16 table rows
    #pragma unroll
    for (int t = 0; t < 2; t++) {
        float mean = ssum[t] * (1.f / 64.f);
        float var  = ssq[t] * (1.f / 64.f) - mean * mean;
        float inv  = rsqrtf(var + EPS);
        if (node[t] < NNODE) {
            #pragma unroll
            for (int j = 0; j < 8; j++) {
                int col0 = 8 * j + 2 * q;
                float2 gv = *(const float2*)&vecf[256 + col0];
                float2 bv = *(const float2*)&vecf[320 + col0];
                float y0 = fmaf((sv[t][2*j]     - mean) * inv, gv.x, bv.x);
                float y1 = fmaf((sv[t][2*j + 1] - mean) * inv, gv.y, bv.y);
                g_tab[f][node[t]][4 * j + q] = packh2(y0, y1);
            }
        }
    }
}

// ============================================================================
// Kernel 3: k_main — per (token,f): acc += w_f * lerp(y-table). No LN here.
// CTA = 64 tokens, 256 threads (4 threads/token x 16 u each). Grid 512.
// ============================================================================
#define KM_XS  0                 // 64*33 floats
#define KM_WS  2112
#define KM_FLOATS 4224           // 16896 B

__global__ __launch_bounds__(256) void k_main(
    const float* __restrict__ x,
    const float* __restrict__ w,
    float* __restrict__ out)
{
    extern __shared__ float sm[];
    const int tid = threadIdx.x;
    const int tok = tid >> 2;
    const int ql  = tid & 3;
    const int gb  = ql * 16;
    const size_t blk = (size_t)blockIdx.x * 64;

    {   // stage x/w rows (scalar stores: odd stride 33)
        const int off = ql * 8;
        const float2* xp = (const float2*)(x + (blk + tok) * NF + off);
        const float2* wp = (const float2*)(w + (blk + tok) * NF + off);
        #pragma unroll
        for (int i = 0; i < 4; i++) {
            float2 xv = xp[i], wv = wp[i];
            sm[KM_XS + tok * 33 + off + 2*i]     = xv.x;
            sm[KM_XS + tok * 33 + off + 2*i + 1] = xv.y;
            sm[KM_WS + tok * 33 + off + 2*i]     = wv.x;
            sm[KM_WS + tok * 33 + off + 2*i + 1] = wv.y;
        }
    }
    __syncthreads();

    float acc[16];
    #pragma unroll
    for (int c = 0; c < 16; c++) acc[c] = 0.f;

    #pragma unroll 1
    for (int f = 0; f < NF; f++) {
        float xf = sm[KM_XS + tok * 33 + f];
        float wf = sm[KM_WS + tok * 33 + f];

        float tpos = (xf - XMIN) * INVDX;
        int   i    = (int)tpos;
        i = (i < 0) ? 0 : ((i > NSEG - 1) ? NSEG - 1 : i);
        float fr  = tpos - (float)i;
        float wfr = wf * fr;          // weight on node i+1
        float wfa = wf - wfr;         // weight on node i

        const uint4* r0 = (const uint4*)&g_tab[f][i][ql * 8];
        const uint4* r1 = (const uint4*)&g_tab[f][i + 1][ql * 8];
        uint4 a0 = r0[0], a1v = r0[1];
        uint4 b0 = r1[0], b1v = r1[1];

        const uint32_t aw[8] = { a0.x, a0.y, a0.z, a0.w, a1v.x, a1v.y, a1v.z, a1v.w };
        const uint32_t bw[8] = { b0.x, b0.y, b0.z, b0.w, b1v.x, b1v.y, b1v.z, b1v.w };
        #pragma unroll
        for (int c = 0; c < 8; c++) {
            float2 av = unpackh2(aw[c]);
            float2 bv = unpackh2(bw[c]);
            acc[2*c]   = fmaf(av.x, wfa, fmaf(bv.x, wfr, acc[2*c]));
            acc[2*c+1] = fmaf(av.y, wfa, fmaf(bv.y, wfr, acc[2*c+1]));
        }
    }

    {
        float4* op = (float4*)(out + (blk + tok) * NU + gb);
        #pragma unroll
        for (int c = 0; c < 4; c++)
            op[c] = make_float4(acc[4*c], acc[4*c+1], acc[4*c+2], acc[4*c+3]);
    }
}

// ============================================================================
extern "C" void kernel_launch(void* const* d_in, const int* in_sizes, int n_in,
                              void* d_out, int out_size) {
    const float* x    = (const float*)d_in[0];
    const float* W1   = (const float*)d_in[1];
    const float* b1   = (const float*)d_in[2];
    const float* W2   = (const float*)d_in[3];
    const float* b2   = (const float*)d_in[4];
    const float* Wg1  = (const float*)d_in[5];
    const float* bg1  = (const float*)d_in[6];
    const float* Wg2  = (const float*)d_in[7];
    const float* bg2  = (const float*)d_in[8];
    const float* Wp   = (const float*)d_in[9];
    const float* bp   = (const float*)d_in[10];
    const float* gamma= (const float*)d_in[11];
    const float* beta = (const float*)d_in[12];
    const float* w1w  = (const float*)d_in[13];
    const float* b1w  = (const float*)d_in[14];
    const float* w2w  = (const float*)d_in[15];
    const float* b2w  = (const float*)d_in[16];
    const float* wg1w = (const float*)d_in[17];
    const float* bg1w = (const float*)d_in[18];
    const float* wg2w = (const float*)d_in[19];
    const float* bg2w = (const float*)d_in[20];
    const float* gammaw = (const float*)d_in[21];
    const float* betaw  = (const float*)d_in[22];

    float* outp = (float*)d_out;
    float* wp   = outp + W_OFF;

    cudaFuncSetAttribute(k_weights, cudaFuncAttributeMaxDynamicSharedMemorySize,
                         KW_FLOATS * sizeof(float));
    k_weights<<<BT / 128, 256, KW_FLOATS * sizeof(float)>>>(
        x, w1w, b1w, w2w, b2w, wg1w, bg1w, wg2w, bg2w, gammaw, betaw, wp);

    k_prep<<<NF, 256>>>(W2, Wg1, Wg2, b2, bg1, bg2, W1, b1, Wp, bp, gamma, beta);

    cudaFuncSetAttribute(k_tab, cudaFuncAttributeMaxDynamicSharedMemorySize, KT_SMEM);
    k_tab<<<dim3(13, 32), 256, KT_SMEM>>>();

    cudaFuncSetAttribute(k_main, cudaFuncAttributeMaxDynamicSharedMemorySize,
                         KM_FLOATS * sizeof(float));
    k_main<<<BT / 64, 256, KM_FLOATS * sizeof(float)>>>(x, wp, outp);
}

// round 13
// speedup vs baseline: 3.3080x; 1.1166x over previous
#include <cuda_runtime.h>
#include <cuda_fp16.h>
#include <cstdint>

#define BT 32768
#define NF 32
#define NU 64
#define EPS 1e-3f
#define W_OFF (BT * NU)

// ---- GRN-as-1D-function table (post-LN y values) ----
#define XMIN  (-6.0f)
#define NSEG  1536
#define DX    0.0078125f
#define INVDX 128.0f
#define NNODE 1537

// per-feature image (bytes): W2' fp16[64][72] | Wg' fp16[128][72] | vec f32[8][64]
#define IMG_BYTES  29696
#define OFF_WG_B   9216
#define OFF_VEC_B  27648

__device__ __align__(16) unsigned char g_img[NF][IMG_BYTES];
__device__ __align__(16) uint32_t g_tab[NF][NNODE][NU / 2];   // half2-packed y, ~6.3 MB

// ---------------- helpers ----------------
__device__ __forceinline__ uint32_t smem_u32(const void* p) {
    uint32_t a;
    asm("{ .reg .u64 t; cvta.to.shared.u64 t, %1; cvt.u32.u64 %0, t; }" : "=r"(a) : "l"(p));
    return a;
}
__device__ __forceinline__ float eluf(float z)  { return z > 0.f ? z : (__expf(z) - 1.f); }
__device__ __forceinline__ float sigmf(float z) {
    float t, h = 0.5f * z;
    asm("tanh.approx.f32 %0, %1;" : "=f"(t) : "f"(h));
    return fmaf(0.5f, t, 0.5f);
}
__device__ __forceinline__ uint32_t packh2(float lo, float hi) {
    __half2 h = __floats2half2_rn(lo, hi);
    return *reinterpret_cast<uint32_t*>(&h);
}
__device__ __forceinline__ float2 unpackh2(uint32_t u) {
    __half2 h = *reinterpret_cast<__half2*>(&u);
    return __half22float2(h);
}
__device__ __forceinline__ void mma16(float* c, const uint32_t* a, uint32_t b0, uint32_t b1) {
    asm volatile(
        "mma.sync.aligned.m16n8k16.row.col.f32.f16.f16.f32 "
        "{%0,%1,%2,%3}, {%4,%5,%6,%7}, {%8,%9}, {%0,%1,%2,%3};"
        : "+f"(c[0]), "+f"(c[1]), "+f"(c[2]), "+f"(c[3])
        : "r"(a[0]), "r"(a[1]), "r"(a[2]), "r"(a[3]), "r"(b0), "r"(b1));
}
__device__ __forceinline__ void ldsm4(uint32_t* r, uint32_t addr) {
    asm volatile("ldmatrix.sync.aligned.m8n8.x4.shared.b16 {%0,%1,%2,%3}, [%4];"
        : "=r"(r[0]), "=r"(r[1]), "=r"(r[2]), "=r"(r[3]) : "r"(addr));
}

#define MBARRIER_INIT(addr, cnt) \
    asm volatile("mbarrier.init.shared.b64 [%0], %1;" :: "r"(addr), "r"(cnt) : "memory")
#define MBARRIER_EXPECT_TX(addr, tx) \
    asm volatile("mbarrier.arrive.expect_tx.shared.b64 _, [%0], %1;" :: "r"(addr), "r"(tx) : "memory")
#define MBARRIER_WAIT_PARITY(addr, par) do { \
    uint32_t _m = (addr); uint32_t _p = (par); uint32_t _d; \
    asm volatile("{ .reg .pred p; mbarrier.try_wait.parity.acquire.cta.shared::cta.b64 p, [%1], %2; selp.b32 %0, 1, 0, p; }" \
        : "=r"(_d) : "r"(_m), "r"(_p) : "memory"); \
    if (!_d) { \
        asm volatile("{ .reg .pred P1; WL_%=: mbarrier.try_wait.parity.acquire.cta.shared::cta.b64 P1, [%0], %1, 0x989680; @P1 bra.uni WD_%=; bra.uni WL_%=; WD_%=: }" \
            :: "r"(_m), "r"(_p) : "memory"); \
    } } while (0)

__device__ __forceinline__ void bulk_g2s(uint32_t dst, const void* src, uint32_t bytes, uint32_t mbar) {
    asm volatile("cp.async.bulk.shared::cluster.global.mbarrier::complete_tx::bytes [%0], [%1], %2, [%3];"
                 :: "r"(dst), "l"(src), "r"(bytes), "r"(mbar) : "memory");
}

// ============================================================================
// Kernel 0: weights GRN + LN + softmax -> w [BT,32] via fp16 HMMA.
// CTA = 128 tokens, 256 threads, 8 warps x 16 tokens.
// Weight images [n][k] fp16, ld = 20 words (conflict-free, 16B-aligned rows).
// ============================================================================
#define KWB_W1  0u
#define KWB_W2  2560u
#define KWB_WG  5120u        // [64][40] halves: wg1 rows 0-31, wg2 rows 32-63
#define KWB_HT  10240u       // 8 warps x [16][40] halves (1280 B each)
#define KWB_XT  20480u       // x fp32 [128][36]
#define KWB_PRM 38912u       // 6 x 32 f32: b1,b2,bg1,bg2,gamma,beta
#define KWB_SMEM 39680u

__global__ __launch_bounds__(256) void k_weights(
    const float* __restrict__ x,
    const float* __restrict__ w1w, const float* __restrict__ b1w,
    const float* __restrict__ w2w, const float* __restrict__ b2w,
    const float* __restrict__ wg1w, const float* __restrict__ bg1w,
    const float* __restrict__ wg2w, const float* __restrict__ bg2w,
    const float* __restrict__ gammaw, const float* __restrict__ betaw,
    float* __restrict__ wout)
{
    extern __shared__ char smw[];
    __half* w1h = (__half*)(smw + KWB_W1);
    __half* w2h = (__half*)(smw + KWB_W2);
    __half* wgh = (__half*)(smw + KWB_WG);
    float*  xt  = (float*)(smw + KWB_XT);
    float*  prm = (float*)(smw + KWB_PRM);
    const uint32_t sb = smem_u32(smw);

    const int tid  = threadIdx.x;
    const int lane = tid & 31;
    const int warp = tid >> 5;
    const int q    = lane & 3;
    const int g    = lane >> 2;
    const int lrow = lane & 7;
    const int lmat = lane >> 3;
    const int wtok = warp * 16;
    const size_t blk = (size_t)blockIdx.x * 128;

    // build fp16 weight images (B'[n][k] = W[k][n])
    for (int i = tid; i < 1024; i += 256) {
        int n = i >> 5, k = i & 31;
        w1h[n * 40 + k] = __float2half_rn(w1w[k * 32 + n]);
        w2h[n * 40 + k] = __float2half_rn(w2w[k * 32 + n]);
    }
    for (int i = tid; i < 2048; i += 256) {
        int n = i >> 5, k = i & 31;
        float v = (n < 32) ? wg1w[k * 32 + n] : wg2w[k * 32 + (n - 32)];
        wgh[n * 40 + k] = __float2half_rn(v);
    }
    if (tid < 32) {
        prm[tid]       = b1w[tid];
        prm[32 + tid]  = b2w[tid];
        prm[64 + tid]  = bg1w[tid];
        prm[96 + tid]  = bg2w[tid];
        prm[128 + tid] = gammaw[tid];
        prm[160 + tid] = betaw[tid];
    }
    {   // stage x [128][36] fp32
        const int row = tid >> 1, half = (tid & 1) * 16;
        const float4* xp = (const float4*)(x + (blk + row) * 32 + half);
        float4* xr = (float4*)&xt[row * 36 + half];
        xr[0] = xp[0]; xr[1] = xp[1]; xr[2] = xp[2]; xr[3] = xp[3];
    }
    __syncthreads();

    uint32_t* h2u = (uint32_t*)(smw + KWB_HT) + warp * 320;   // [16][40] halves
    const uint32_t htb = sb + KWB_HT + (uint32_t)warp * 1280u;
    const uint32_t abw = htb + (uint32_t)((((lmat & 1) * 8 + lrow) * 20 + (lmat >> 1) * 4) * 4);

    const float* xr0 = &xt[(wtok + g) * 36];
    const float* xr1 = &xt[(wtok + g + 8) * 36];

    // A1 = fp16(x) fragments
    uint32_t a1[2][4];
    #pragma unroll
    for (int s = 0; s < 2; s++) {
        int k0 = 16 * s + 2 * q;
        a1[s][0] = packh2(xr0[k0],     xr0[k0 + 1]);
        a1[s][1] = packh2(xr1[k0],     xr1[k0 + 1]);
        a1[s][2] = packh2(xr0[k0 + 8], xr0[k0 + 9]);
        a1[s][3] = packh2(xr1[k0 + 8], xr1[k0 + 9]);
    }

    // GEMM1: h = elu(x @ w1 + b1) -> fp16 tile
    #pragma unroll
    for (int j = 0; j < 4; j++) {
        uint32_t ad = sb + KWB_W1 + (uint32_t)(((8 * j + lrow) * 20 + 4 * lmat) * 4);
        uint32_t bb[4];
        ldsm4(bb, ad);
        float c[4] = {0.f, 0.f, 0.f, 0.f};
        mma16(c, a1[0], bb[0], bb[1]);
        mma16(c, a1[1], bb[2], bb[3]);
        int col0 = 8 * j + 2 * q;
        float b0 = prm[col0], b1v = prm[col0 + 1];
        h2u[g * 20 + 4 * j + q]       = packh2(eluf(c[0] + b0), eluf(c[1] + b1v));
        h2u[(g + 8) * 20 + 4 * j + q] = packh2(eluf(c[2] + b0), eluf(c[3] + b1v));
    }
    __syncwarp();
    uint32_t a2[2][4];
    ldsm4(a2[0], abw);
    ldsm4(a2[1], abw + 32);
    __syncwarp();

    // GEMM2: h2 = h @ w2 + b2 -> fp16 tile
    #pragma unroll
    for (int j = 0; j < 4; j++) {
        uint32_t ad = sb + KWB_W2 + (uint32_t)(((8 * j + lrow) * 20 + 4 * lmat) * 4);
        uint32_t bb[4];
        ldsm4(bb, ad);
        float c[4] = {0.f, 0.f, 0.f, 0.f};
        mma16(c, a2[0], bb[0], bb[1]);
        mma16(c, a2[1], bb[2], bb[3]);
        int col0 = 8 * j + 2 * q;
        float b0 = prm[32 + col0], b1v = prm[32 + col0 + 1];
        h2u[g * 20 + 4 * j + q]       = packh2(c[0] + b0, c[1] + b1v);
        h2u[(g + 8) * 20 + 4 * j + q] = packh2(c[2] + b0, c[3] + b1v);
    }
    __syncwarp();
    uint32_t a3[2][4];
    ldsm4(a3[0], abw);
    ldsm4(a3[1], abw + 32);

    // Gates: [o1|o2] = h2 @ [wg1|wg2]   (8 n-tiles over the combined image)
    float o1v[2][8], o2v[2][8];
    #pragma unroll
    for (int j = 0; j < 8; j++) {
        uint32_t ad = sb + KWB_WG + (uint32_t)(((8 * j + lrow) * 20 + 4 * lmat) * 4);
        uint32_t bb[4];
        ldsm4(bb, ad);
        float c[4] = {0.f, 0.f, 0.f, 0.f};
        mma16(c, a3[0], bb[0], bb[1]);
        mma16(c, a3[1], bb[2], bb[3]);
        if (j < 4) {
            o1v[0][2*j] = c[0]; o1v[0][2*j+1] = c[1];
            o1v[1][2*j] = c[2]; o1v[1][2*j+1] = c[3];
        } else {
            int jj = j - 4;
            o2v[0][2*jj] = c[0]; o2v[0][2*jj+1] = c[1];
            o2v[1][2*jj] = c[2]; o2v[1][2*jj+1] = c[3];
        }
    }

    // gate + residual; LN over 32 (quad reduce); softmax; store w
    float s[2][8];
    float ssum[2] = {0.f, 0.f}, ssq[2] = {0.f, 0.f};
    #pragma unroll
    for (int t = 0; t < 2; t++) {
        const float* xr = (t == 0) ? xr0 : xr1;
        #pragma unroll
        for (int j = 0; j < 4; j++) {
            #pragma unroll
            for (int i2 = 0; i2 < 2; i2++) {
                int col = 8 * j + 2 * q + i2;
                float o1 = o1v[t][2*j + i2] + prm[64 + col];
                float o2 = o2v[t][2*j + i2] + prm[96 + col];
                float sv = fmaf(o1, sigmf(o2), xr[col]);
                s[t][2*j + i2] = sv;
                ssum[t] += sv;
                ssq[t] = fmaf(sv, sv, ssq[t]);
            }
        }
    }
    #pragma unroll
    for (int off = 1; off < 4; off <<= 1) {
        #pragma unroll
        for (int t = 0; t < 2; t++) {
            ssum[t] += __shfl_xor_sync(0xffffffffu, ssum[t], off);
            ssq[t]  += __shfl_xor_sync(0xffffffffu, ssq[t],  off);
        }
    }
    #pragma unroll
    for (int t = 0; t < 2; t++) {
        float mean = ssum[t] * (1.f / 32.f);
        float var  = ssq[t] * (1.f / 32.f) - mean * mean;
        float inv  = rsqrtf(var + EPS);
        float y[8], mx = -1e30f;
        #pragma unroll
        for (int j = 0; j < 4; j++) {
            #pragma unroll
            for (int i2 = 0; i2 < 2; i2++) {
                int col = 8 * j + 2 * q + i2;
                float v = fmaf((s[t][2*j + i2] - mean) * inv, prm[128 + col], prm[160 + col]);
                y[2*j + i2] = v;
                mx = fmaxf(mx, v);
            }
        }
        #pragma unroll
        for (int off = 1; off < 4; off <<= 1)
            mx = fmaxf(mx, __shfl_xor_sync(0xffffffffu, mx, off));
        float se = 0.f;
        #pragma unroll
        for (int e = 0; e < 8; e++) { float ev = __expf(y[e] - mx); y[e] = ev; se += ev; }
        #pragma unroll
        for (int off = 1; off < 4; off <<= 1)
            se += __shfl_xor_sync(0xffffffffu, se, off);
        float r = 1.f / se;
        float* orow = wout + (blk + wtok + g + 8 * t) * (size_t)NF;
        #pragma unroll
        for (int j = 0; j < 4; j++)
            *(float2*)&orow[8 * j + 2 * q] = make_float2(y[2*j] * r, y[2*j + 1] * r);
    }
}

// ============================================================================
// Kernel 1: prep — per-feature fp16 images + folded gate biases (unchanged).
// ============================================================================
__global__ __launch_bounds__(256) void k_prep(
    const float* __restrict__ W2, const float* __restrict__ Wg1, const float* __restrict__ Wg2,
    const float* __restrict__ b2, const float* __restrict__ bg1, const float* __restrict__ bg2,
    const float* __restrict__ W1, const float* __restrict__ b1,
    const float* __restrict__ Wp, const float* __restrict__ bp,
    const float* __restrict__ gamma, const float* __restrict__ beta)
{
    const int f = blockIdx.x;
    const int tid = threadIdx.x;
    const float* W2f  = W2  + (size_t)f * 4096;
    const float* Wg1f = Wg1 + (size_t)f * 4096;
    const float* Wg2f = Wg2 + (size_t)f * 4096;
    unsigned char* img = g_img[f];
    __half* W2h = (__half*)img;
    __half* Wgh = (__half*)(img + OFF_WG_B);
    float*  vec = (float*)(img + OFF_VEC_B);

    for (int i = tid; i < 4096; i += 256) {
        int n = i >> 6, k = i & 63;
        W2h[n * 72 + k] = __float2half_rn(W2f[k * 64 + n]);
    }
    for (int i = tid; i < 8192; i += 256) {
        int n = i >> 6, k = i & 63;
        float v = (n < 64) ? Wg1f[k * 64 + n] : Wg2f[k * 64 + (n - 64)];
        Wgh[n * 72 + k] = __float2half_rn(v);
    }
    if (tid < 64) {
        int o = f * 64 + tid;
        vec[0   + tid] = W1[o];
        vec[64  + tid] = b1[o];
        vec[128 + tid] = Wp[o];
        vec[192 + tid] = bp[o];
        vec[256 + tid] = gamma[o];
        vec[320 + tid] = beta[o];
        float s1 = bg1[o], s2 = bg2[o];
        for (int u = 0; u < 64; u++) {
            float bv = b2[f * 64 + u];
            s1 += bv * Wg1f[u * 64 + tid];
            s2 += bv * Wg2f[u * 64 + tid];
        }
        vec[384 + tid] = s1;
        vec[448 + tid] = s2;
    }
}

// ============================================================================
// Kernel 2: k_tab — per-feature GRN at table nodes via HMMA + LN -> fp16 y rows.
// Grid 13 x 32, 256 threads = 8 warps x 16 nodes.  (unchanged)
// ============================================================================
#define KT_H2_OFF   29696u
#define KT_MBAR_OFF 48128u
#define KT_SMEM     48144u

__global__ __launch_bounds__(256) void k_tab()
{
    extern __shared__ char smem[];
    const uint32_t sbase = smem_u32(smem);

    const int f    = blockIdx.y;
    const int part = blockIdx.x;
    const int tid  = threadIdx.x;
    const int lane = tid & 31;
    const int warp = tid >> 5;
    const int q    = lane & 3;
    const int g    = lane >> 2;
    const int lrow = lane & 7;
    const int lmat = lane >> 3;
    const int nodeb = part * 128 + warp * 16;

    uint32_t* h2u = (uint32_t*)(smem + KT_H2_OFF) + warp * 576;
    const uint32_t h2a = sbase + KT_H2_OFF + warp * 2304;
    const uint32_t mbar = sbase + KT_MBAR_OFF;

    if (tid == 0) MBARRIER_INIT(mbar, 1);
    __syncthreads();
    if (tid == 0) {
        MBARRIER_EXPECT_TX(mbar, IMG_BYTES);
        bulk_g2s(sbase, &g_img[f][0], IMG_BYTES, mbar);
    }
    MBARRIER_WAIT_PARITY(mbar, 0);

    const uint32_t bwa  = sbase;
    const uint32_t wgwa = sbase + OFF_WG_B;
    const float*   vecf = (const float*)(smem + OFF_VEC_B);

    float xf[2];
    int   node[2];
    #pragma unroll
    for (int t = 0; t < 2; t++) {
        node[t] = nodeb + g + 8 * t;
        xf[t] = XMIN + (float)node[t] * DX;
    }

    uint32_t a1[4][4];
    #pragma unroll
    for (int s = 0; s < 4; s++) {
        #pragma unroll
        for (int p = 0; p < 2; p++) {
            int u0 = 16 * s + 2 * q + 8 * p;
            float2 wv  = *(const float2*)&vecf[u0];
            float2 bv2 = *(const float2*)&vecf[64 + u0];
            a1[s][2*p]   = packh2(eluf(fmaf(xf[0], wv.x, bv2.x)), eluf(fmaf(xf[0], wv.y, bv2.y)));
            a1[s][2*p+1] = packh2(eluf(fmaf(xf[1], wv.x, bv2.x)), eluf(fmaf(xf[1], wv.y, bv2.y)));
        }
    }

    #pragma unroll
    for (int j = 0; j < 8; j++) {
        uint32_t ad = bwa + (uint32_t)(((8 * j + lrow) * 36 + 4 * lmat) * 4);
        uint32_t bb[8];
        ldsm4(bb, ad);
        ldsm4(bb + 4, ad + 64);
        float c0[4] = {0.f,0.f,0.f,0.f};
        mma16(c0, a1[0], bb[0], bb[1]);
        mma16(c0, a1[1], bb[2], bb[3]);
        mma16(c0, a1[2], bb[4], bb[5]);
        mma16(c0, a1[3], bb[6], bb[7]);
        int cw = 4 * j + q;
        h2u[(g    ) * 36 + cw] = packh2(c0[0], c0[1]);
        h2u[(g + 8) * 36 + cw] = packh2(c0[2], c0[3]);
    }
    __syncwarp();

    uint32_t a2[4][4];
    {
        uint32_t abase = h2a + (uint32_t)((((lmat & 1) * 8 + lrow) * 36 + (lmat >> 1) * 4) * 4);
        #pragma unroll
        for (int s = 0; s < 4; s++)
            ldsm4(a2[s], abase + (uint32_t)(32 * s));
    }

    float sv[2][16];
    float ssum[2] = {0.f, 0.f};
    float ssq[2]  = {0.f, 0.f};
    #pragma unroll 2
    for (int j = 0; j < 8; j++) {
        uint32_t ad1 = wgwa + (uint32_t)(((8 * j + lrow) * 36 + 4 * lmat) * 4);
        uint32_t bb1[8], bb2[8];
        ldsm4(bb1, ad1);
        ldsm4(bb1 + 4, ad1 + 64);
        ldsm4(bb2, ad1 + 9216);
        ldsm4(bb2 + 4, ad1 + 9216 + 64);
        float c1[4] = {0.f,0.f,0.f,0.f};
        float c2[4] = {0.f,0.f,0.f,0.f};
        #pragma unroll
        for (int s = 0; s < 4; s++) {
            mma16(c1, a2[s], bb1[2*s], bb1[2*s+1]);
            mma16(c2, a2[s], bb2[2*s], bb2[2*s+1]);
        }
        int col0 = 8 * j + 2 * q;
        float2 be1v = *(const float2*)&vecf[384 + col0];
        float2 be2v = *(const float2*)&vecf[448 + col0];
        float2 wpv  = *(const float2*)&vecf[128 + col0];
        float2 bpv  = *(const float2*)&vecf[192 + col0];
        #pragma unroll
        for (int t = 0; t < 2; t++) {
            float o1a = c1[2*t]     + be1v.x;
            float o1b = c1[2*t + 1] + be1v.y;
            float o2a = c2[2*t]     + be2v.x;
            float o2b = c2[2*t + 1] + be2v.y;
            float sv0 = fmaf(o1a, sigmf(o2a), fmaf(xf[t], wpv.x, bpv.x));
            float sv1 = fmaf(o1b, sigmf(o2b), fmaf(xf[t], wpv.y, bpv.y));
            sv[t][2*j]     = sv0;
            sv[t][2*j + 1] = sv1;
            ssum[t] += sv0 + sv1;
            ssq[t]  = fmaf(sv0, sv0, fmaf(sv1, sv1, ssq[t]));
        }
    }

    #pragma unroll
    for (int off = 1; off < 4; off <<= 1) {
        #pragma unroll
        for (int t = 0; t < 2; t++) {
            ssum[t] += __shfl_xor_sync(0xffffffffu, ssum[t], off);
            ssq[t]  += __shfl_xor_sync(0xffffffffu, ssq[t],  off);
        }
    }

    #pragma unroll
    for (int t = 0; t < 2; t++) {
        float mean = ssum[t] * (1.f / 64.f);
        float var  = ssq[t] * (1.f / 64.f) - mean * mean;
        float inv  = rsqrtf(var + EPS);
        if (node[t] < NNODE) {
            #pragma unroll
            for (int j = 0; j < 8; j++) {
                int col0 = 8 * j + 2 * q;
                float2 gv = *(const float2*)&vecf[256 + col0];
                float2 bv = *(const float2*)&vecf[320 + col0];
                float y0 = fmaf((sv[t][2*j]     - mean) * inv, gv.x, bv.x);
                float y1 = fmaf((sv[t][2*j + 1] - mean) * inv, gv.y, bv.y);
                g_tab[f][node[t]][4 * j + q] = packh2(y0, y1);
            }
        }
    }
}

// ============================================================================
// Kernel 3: k_main — per (token,f): acc += w_f * lerp(y-table). (unchanged)
// ============================================================================
#define KM_XS  0
#define KM_WS  2112
#define KM_FLOATS 4224

__global__ __launch_bounds__(256) void k_main(
    const float* __restrict__ x,
    const float* __restrict__ w,
    float* __restrict__ out)
{
    extern __shared__ float sm[];
    const int tid = threadIdx.x;
    const int tok = tid >> 2;
    const int ql  = tid & 3;
    const int gb  = ql * 16;
    const size_t blk = (size_t)blockIdx.x * 64;

    {
        const int off = ql * 8;
        const float2* xp = (const float2*)(x + (blk + tok) * NF + off);
        const float2* wp = (const float2*)(w + (blk + tok) * NF + off);
        #pragma unroll
        for (int i = 0; i < 4; i++) {
            float2 xv = xp[i], wv = wp[i];
            sm[KM_XS + tok * 33 + off + 2*i]     = xv.x;
            sm[KM_XS + tok * 33 + off + 2*i + 1] = xv.y;
            sm[KM_WS + tok * 33 + off + 2*i]     = wv.x;
            sm[KM_WS + tok * 33 + off + 2*i + 1] = wv.y;
        }
    }
    __syncthreads();

    float acc[16];
    #pragma unroll
    for (int c = 0; c < 16; c++) acc[c] = 0.f;

    #pragma unroll 1
    for (int f = 0; f < NF; f++) {
        float xf = sm[KM_XS + tok * 33 + f];
        float wf = sm[KM_WS + tok * 33 + f];

        float tpos = (xf - XMIN) * INVDX;
        int   i    = (int)tpos;
        i = (i < 0) ? 0 : ((i > NSEG - 1) ? NSEG - 1 : i);
        float fr  = tpos - (float)i;
        float wfr = wf * fr;
        float wfa = wf - wfr;

        const uint4* r0 = (const uint4*)&g_tab[f][i][ql * 8];
        const uint4* r1 = (const uint4*)&g_tab[f][i + 1][ql * 8];
        uint4 a0 = r0[0], a1v = r0[1];
        uint4 b0 = r1[0], b1v = r1[1];

        const uint32_t aw[8] = { a0.x, a0.y, a0.z, a0.w, a1v.x, a1v.y, a1v.z, a1v.w };
        const uint32_t bw[8] = { b0.x, b0.y, b0.z, b0.w, b1v.x, b1v.y, b1v.z, b1v.w };
        #pragma unroll
        for (int c = 0; c < 8; c++) {
            float2 av = unpackh2(aw[c]);
            float2 bv = unpackh2(bw[c]);
            acc[2*c]   = fmaf(av.x, wfa, fmaf(bv.x, wfr, acc[2*c]));
            acc[2*c+1] = fmaf(av.y, wfa, fmaf(bv.y, wfr, acc[2*c+1]));
        }
    }

    {
        float4* op = (float4*)(out + (blk + tok) * NU + gb);
        #pragma unroll
        for (int c = 0; c < 4; c++)
            op[c] = make_float4(acc[4*c], acc[4*c+1], acc[4*c+2], acc[4*c+3]);
    }
}

// ============================================================================
extern "C" void kernel_launch(void* const* d_in, const int* in_sizes, int n_in,
                              void* d_out, int out_size) {
    const float* x    = (const float*)d_in[0];
    const float* W1   = (const float*)d_in[1];
    const float* b1   = (const float*)d_in[2];
    const float* W2   = (const float*)d_in[3];
    const float* b2   = (const float*)d_in[4];
    const float* Wg1  = (const float*)d_in[5];
    const float* bg1  = (const float*)d_in[6];
    const float* Wg2  = (const float*)d_in[7];
    const float* bg2  = (const float*)d_in[8];
    const float* Wp   = (const float*)d_in[9];
    const float* bp   = (const float*)d_in[10];
    const float* gamma= (const float*)d_in[11];
    const float* beta = (const float*)d_in[12];
    const float* w1w  = (const float*)d_in[13];
    const float* b1w  = (const float*)d_in[14];
    const float* w2w  = (const float*)d_in[15];
    const float* b2w  = (const float*)d_in[16];
    const float* wg1w = (const float*)d_in[17];
    const float* bg1w = (const float*)d_in[18];
    const float* wg2w = (const float*)d_in[19];
    const float* bg2w = (const float*)d_in[20];
    const float* gammaw = (const float*)d_in[21];
    const float* betaw  = (const float*)d_in[22];

    float* outp = (float*)d_out;
    float* wp   = outp + W_OFF;

    cudaFuncSetAttribute(k_weights, cudaFuncAttributeMaxDynamicSharedMemorySize, KWB_SMEM);
    k_weights<<<BT / 128, 256, KWB_SMEM>>>(
        x, w1w, b1w, w2w, b2w, wg1w, bg1w, wg2w, bg2w, gammaw, betaw, wp);

    k_prep<<<NF, 256>>>(W2, Wg1, Wg2, b2, bg1, bg2, W1, b1, Wp, bp, gamma, beta);

    cudaFuncSetAttribute(k_tab, cudaFuncAttributeMaxDynamicSharedMemorySize, KT_SMEM);
    k_tab<<<dim3(13, 32), 256, KT_SMEM>>>();

    cudaFuncSetAttribute(k_main, cudaFuncAttributeMaxDynamicSharedMemorySize,
                         KM_FLOATS * sizeof(float));
    k_main<<<BT / 64, 256, KM_FLOATS * sizeof(float)>>>(x, wp, outp);
}

// round 14
// speedup vs baseline: 3.4504x; 1.0430x over previous
#include <cuda_runtime.h>
#include <cuda_fp16.h>
#include <cstdint>

#define BT 32768
#define NF 32
#define NU 64
#define EPS 1e-3f
#define W_OFF (BT * NU)

// ---- GRN-as-1D-function table (post-LN y values) ----
#define XMIN  (-6.0f)
#define NSEG  768
#define DX    0.015625f
#define INVDX 64.0f
#define NNODE 769

// per-feature image (bytes): W2' fp16[64][72] | Wg' fp16[128][72] | vec f32[8][64]
#define IMG_BYTES  29696
#define OFF_WG_B   9216
#define OFF_VEC_B  27648

__device__ __align__(16) unsigned char g_img[NF][IMG_BYTES];
__device__ __align__(16) uint32_t g_tab[NF][NNODE][NU / 2];   // half2-packed y, ~3.15 MB

// ---------------- helpers ----------------
__device__ __forceinline__ uint32_t smem_u32(const void* p) {
    uint32_t a;
    asm("{ .reg .u64 t; cvta.to.shared.u64 t, %1; cvt.u32.u64 %0, t; }" : "=r"(a) : "l"(p));
    return a;
}
__device__ __forceinline__ float eluf(float z)  { return z > 0.f ? z : (__expf(z) - 1.f); }
__device__ __forceinline__ float sigmf(float z) {
    float t, h = 0.5f * z;
    asm("tanh.approx.f32 %0, %1;" : "=f"(t) : "f"(h));
    return fmaf(0.5f, t, 0.5f);
}
__device__ __forceinline__ uint32_t packh2(float lo, float hi) {
    __half2 h = __floats2half2_rn(lo, hi);
    return *reinterpret_cast<uint32_t*>(&h);
}
__device__ __forceinline__ float2 unpackh2(uint32_t u) {
    __half2 h = *reinterpret_cast<__half2*>(&u);
    return __half22float2(h);
}
__device__ __forceinline__ void mma16(float* c, const uint32_t* a, uint32_t b0, uint32_t b1) {
    asm volatile(
        "mma.sync.aligned.m16n8k16.row.col.f32.f16.f16.f32 "
        "{%0,%1,%2,%3}, {%4,%5,%6,%7}, {%8,%9}, {%0,%1,%2,%3};"
        : "+f"(c[0]), "+f"(c[1]), "+f"(c[2]), "+f"(c[3])
        : "r"(a[0]), "r"(a[1]), "r"(a[2]), "r"(a[3]), "r"(b0), "r"(b1));
}
__device__ __forceinline__ void ldsm4(uint32_t* r, uint32_t addr) {
    asm volatile("ldmatrix.sync.aligned.m8n8.x4.shared.b16 {%0,%1,%2,%3}, [%4];"
        : "=r"(r[0]), "=r"(r[1]), "=r"(r[2]), "=r"(r[3]) : "r"(addr));
}

#define MBARRIER_INIT(addr, cnt) \
    asm volatile("mbarrier.init.shared.b64 [%0], %1;" :: "r"(addr), "r"(cnt) : "memory")
#define MBARRIER_EXPECT_TX(addr, tx) \
    asm volatile("mbarrier.arrive.expect_tx.shared.b64 _, [%0], %1;" :: "r"(addr), "r"(tx) : "memory")
#define MBARRIER_WAIT_PARITY(addr, par) do { \
    uint32_t _m = (addr); uint32_t _p = (par); uint32_t _d; \
    asm volatile("{ .reg .pred p; mbarrier.try_wait.parity.acquire.cta.shared::cta.b64 p, [%1], %2; selp.b32 %0, 1, 0, p; }" \
        : "=r"(_d) : "r"(_m), "r"(_p) : "memory"); \
    if (!_d) { \
        asm volatile("{ .reg .pred P1; WL_%=: mbarrier.try_wait.parity.acquire.cta.shared::cta.b64 P1, [%0], %1, 0x989680; @P1 bra.uni WD_%=; bra.uni WL_%=; WD_%=: }" \
            :: "r"(_m), "r"(_p) : "memory"); \
    } } while (0)

__device__ __forceinline__ void bulk_g2s(uint32_t dst, const void* src, uint32_t bytes, uint32_t mbar) {
    asm volatile("cp.async.bulk.shared::cluster.global.mbarrier::complete_tx::bytes [%0], [%1], %2, [%3];"
                 :: "r"(dst), "l"(src), "r"(bytes), "r"(mbar) : "memory");
}

// ============================================================================
// Kernel 1: prep — per-feature fp16 images + folded gate biases (unchanged).
// ============================================================================
__global__ __launch_bounds__(256) void k_prep(
    const float* __restrict__ W2, const float* __restrict__ Wg1, const float* __restrict__ Wg2,
    const float* __restrict__ b2, const float* __restrict__ bg1, const float* __restrict__ bg2,
    const float* __restrict__ W1, const float* __restrict__ b1,
    const float* __restrict__ Wp, const float* __restrict__ bp,
    const float* __restrict__ gamma, const float* __restrict__ beta)
{
    const int f = blockIdx.x;
    const int tid = threadIdx.x;
    const float* W2f  = W2  + (size_t)f * 4096;
    const float* Wg1f = Wg1 + (size_t)f * 4096;
    const float* Wg2f = Wg2 + (size_t)f * 4096;
    unsigned char* img = g_img[f];
    __half* W2h = (__half*)img;
    __half* Wgh = (__half*)(img + OFF_WG_B);
    float*  vec = (float*)(img + OFF_VEC_B);

    for (int i = tid; i < 4096; i += 256) {
        int n = i >> 6, k = i & 63;
        W2h[n * 72 + k] = __float2half_rn(W2f[k * 64 + n]);
    }
    for (int i = tid; i < 8192; i += 256) {
        int n = i >> 6, k = i & 63;
        float v = (n < 64) ? Wg1f[k * 64 + n] : Wg2f[k * 64 + (n - 64)];
        Wgh[n * 72 + k] = __float2half_rn(v);
    }
    if (tid < 64) {
        int o = f * 64 + tid;
        vec[0   + tid] = W1[o];
        vec[64  + tid] = b1[o];
        vec[128 + tid] = Wp[o];
        vec[192 + tid] = bp[o];
        vec[256 + tid] = gamma[o];
        vec[320 + tid] = beta[o];
        float s1 = bg1[o], s2 = bg2[o];
        for (int u = 0; u < 64; u++) {
            float bv = b2[f * 64 + u];
            s1 += bv * Wg1f[u * 64 + tid];
            s2 += bv * Wg2f[u * 64 + tid];
        }
        vec[384 + tid] = s1;
        vec[448 + tid] = s2;
    }
}

// ============================================================================
// Kernel 2: k_tab — per-feature GRN at table nodes via HMMA + LN -> fp16 y rows.
// Grid 7 x 32, 256 threads = 8 warps x 16 nodes.
// ============================================================================
#define KT_H2_OFF   29696u
#define KT_MBAR_OFF 48128u
#define KT_SMEM     48144u

__global__ __launch_bounds__(256) void k_tab()
{
    extern __shared__ char smem[];
    const uint32_t sbase = smem_u32(smem);

    const int f    = blockIdx.y;
    const int part = blockIdx.x;
    const int tid  = threadIdx.x;
    const int lane = tid & 31;
    const int warp = tid >> 5;
    const int q    = lane & 3;
    const int g    = lane >> 2;
    const int lrow = lane & 7;
    const int lmat = lane >> 3;
    const int nodeb = part * 128 + warp * 16;

    uint32_t* h2u = (uint32_t*)(smem + KT_H2_OFF) + warp * 576;
    const uint32_t h2a = sbase + KT_H2_OFF + warp * 2304;
    const uint32_t mbar = sbase + KT_MBAR_OFF;

    if (tid == 0) MBARRIER_INIT(mbar, 1);
    __syncthreads();
    if (tid == 0) {
        MBARRIER_EXPECT_TX(mbar, IMG_BYTES);
        bulk_g2s(sbase, &g_img[f][0], IMG_BYTES, mbar);
    }
    MBARRIER_WAIT_PARITY(mbar, 0);

    const uint32_t bwa  = sbase;
    const uint32_t wgwa = sbase + OFF_WG_B;
    const float*   vecf = (const float*)(smem + OFF_VEC_B);

    float xf[2];
    int   node[2];
    #pragma unroll
    for (int t = 0; t < 2; t++) {
        node[t] = nodeb + g + 8 * t;
        xf[t] = XMIN + (float)node[t] * DX;
    }

    uint32_t a1[4][4];
    #pragma unroll
    for (int s = 0; s < 4; s++) {
        #pragma unroll
        for (int p = 0; p < 2; p++) {
            int u0 = 16 * s + 2 * q + 8 * p;
            float2 wv  = *(const float2*)&vecf[u0];
            float2 bv2 = *(const float2*)&vecf[64 + u0];
            a1[s][2*p]   = packh2(eluf(fmaf(xf[0], wv.x, bv2.x)), eluf(fmaf(xf[0], wv.y, bv2.y)));
            a1[s][2*p+1] = packh2(eluf(fmaf(xf[1], wv.x, bv2.x)), eluf(fmaf(xf[1], wv.y, bv2.y)));
        }
    }

    #pragma unroll
    for (int j = 0; j < 8; j++) {
        uint32_t ad = bwa + (uint32_t)(((8 * j + lrow) * 36 + 4 * lmat) * 4);
        uint32_t bb[8];
        ldsm4(bb, ad);
        ldsm4(bb + 4, ad + 64);
        float c0[4] = {0.f,0.f,0.f,0.f};
        mma16(c0, a1[0], bb[0], bb[1]);
        mma16(c0, a1[1], bb[2], bb[3]);
        mma16(c0, a1[2], bb[4], bb[5]);
        mma16(c0, a1[3], bb[6], bb[7]);
        int cw = 4 * j + q;
        h2u[(g    ) * 36 + cw] = packh2(c0[0], c0[1]);
        h2u[(g + 8) * 36 + cw] = packh2(c0[2], c0[3]);
    }
    __syncwarp();

    uint32_t a2[4][4];
    {
        uint32_t abase = h2a + (uint32_t)((((lmat & 1) * 8 + lrow) * 36 + (lmat >> 1) * 4) * 4);
        #pragma unroll
        for (int s = 0; s < 4; s++)
            ldsm4(a2[s], abase + (uint32_t)(32 * s));
    }

    float sv[2][16];
    float ssum[2] = {0.f, 0.f};
    float ssq[2]  = {0.f, 0.f};
    #pragma unroll 2
    for (int j = 0; j < 8; j++) {
        uint32_t ad1 = wgwa + (uint32_t)(((8 * j + lrow) * 36 + 4 * lmat) * 4);
        uint32_t bb1[8], bb2[8];
        ldsm4(bb1, ad1);
        ldsm4(bb1 + 4, ad1 + 64);
        ldsm4(bb2, ad1 + 9216);
        ldsm4(bb2 + 4, ad1 + 9216 + 64);
        float c1[4] = {0.f,0.f,0.f,0.f};
        float c2[4] = {0.f,0.f,0.f,0.f};
        #pragma unroll
        for (int s = 0; s < 4; s++) {
            mma16(c1, a2[s], bb1[2*s], bb1[2*s+1]);
            mma16(c2, a2[s], bb2[2*s], bb2[2*s+1]);
        }
        int col0 = 8 * j + 2 * q;
        float2 be1v = *(const float2*)&vecf[384 + col0];
        float2 be2v = *(const float2*)&vecf[448 + col0];
        float2 wpv  = *(const float2*)&vecf[128 + col0];
        float2 bpv  = *(const float2*)&vecf[192 + col0];
        #pragma unroll
        for (int t = 0; t < 2; t++) {
            float o1a = c1[2*t]     + be1v.x;
            float o1b = c1[2*t + 1] + be1v.y;
            float o2a = c2[2*t]     + be2v.x;
            float o2b = c2[2*t + 1] + be2v.y;
            float sv0 = fmaf(o1a, sigmf(o2a), fmaf(xf[t], wpv.x, bpv.x));
            float sv1 = fmaf(o1b, sigmf(o2b), fmaf(xf[t], wpv.y, bpv.y));
            sv[t][2*j]     = sv0;
            sv[t][2*j + 1] = sv1;
            ssum[t] += sv0 + sv1;
            ssq[t]  = fmaf(sv0, sv0, fmaf(sv1, sv1, ssq[t]));
        }
    }

    #pragma unroll
    for (int off = 1; off < 4; off <<= 1) {
        #pragma unroll
        for (int t = 0; t < 2; t++) {
            ssum[t] += __shfl_xor_sync(0xffffffffu, ssum[t], off);
            ssq[t]  += __shfl_xor_sync(0xffffffffu, ssq[t],  off);
        }
    }

    #pragma unroll
    for (int t = 0; t < 2; t++) {
        float mean = ssum[t] * (1.f / 64.f);
        float var  = ssq[t] * (1.f / 64.f) - mean * mean;
        float inv  = rsqrtf(var + EPS);
        if (node[t] < NNODE) {
            #pragma unroll
            for (int j = 0; j < 8; j++) {
                int col0 = 8 * j + 2 * q;
                float2 gv = *(const float2*)&vecf[256 + col0];
                float2 bv = *(const float2*)&vecf[320 + col0];
                float y0 = fmaf((sv[t][2*j]     - mean) * inv, gv.x, bv.x);
                float y1 = fmaf((sv[t][2*j + 1] - mean) * inv, gv.y, bv.y);
                g_tab[f][node[t]][4 * j + q] = packh2(y0, y1);
            }
        }
    }
}

// ============================================================================
// Kernel 3: k_fused — phase 1: warps 0-3 compute w (HMMA GRN over F) for the
// CTA's 64 tokens -> smem + global; phase 2: all 256 threads (4/token) do the
// table lerp-accumulate.  Grid 512 x 256 threads.
// ============================================================================
#define KF_W1   0u
#define KF_W2   2560u
#define KF_WG   5120u        // [64][40] halves
#define KF_HT   10240u       // 4 warps x [16][40] halves (1280 B each)
#define KF_XT   15360u       // x f32 [64][36]
#define KF_PRM  24576u       // 6 x 32 f32
#define KF_WS   25344u       // w f32 [64][36]
#define KF_SMEM 34560u

__global__ __launch_bounds__(256) void k_fused(
    const float* __restrict__ x,
    const float* __restrict__ w1w, const float* __restrict__ b1w,
    const float* __restrict__ w2w, const float* __restrict__ b2w,
    const float* __restrict__ wg1w, const float* __restrict__ bg1w,
    const float* __restrict__ wg2w, const float* __restrict__ bg2w,
    const float* __restrict__ gammaw, const float* __restrict__ betaw,
    float* __restrict__ wout,
    float* __restrict__ out)
{
    extern __shared__ char smw[];
    __half* w1h = (__half*)(smw + KF_W1);
    __half* w2h = (__half*)(smw + KF_W2);
    __half* wgh = (__half*)(smw + KF_WG);
    float*  xt  = (float*)(smw + KF_XT);
    float*  prm = (float*)(smw + KF_PRM);
    float*  ws  = (float*)(smw + KF_WS);
    const uint32_t sb = smem_u32(smw);

    const int tid  = threadIdx.x;
    const int lane = tid & 31;
    const int warp = tid >> 5;
    const int q    = lane & 3;
    const int g    = lane >> 2;
    const int lrow = lane & 7;
    const int lmat = lane >> 3;
    const size_t blk = (size_t)blockIdx.x * 64;

    // ---- stage weight images + x (all 256 threads) ----
    for (int i = tid; i < 1024; i += 256) {
        int n = i >> 5, k = i & 31;
        w1h[n * 40 + k] = __float2half_rn(w1w[k * 32 + n]);
        w2h[n * 40 + k] = __float2half_rn(w2w[k * 32 + n]);
    }
    for (int i = tid; i < 2048; i += 256) {
        int n = i >> 5, k = i & 31;
        float v = (n < 32) ? wg1w[k * 32 + n] : wg2w[k * 32 + (n - 32)];
        wgh[n * 40 + k] = __float2half_rn(v);
    }
    if (tid < 32) {
        prm[tid]       = b1w[tid];
        prm[32 + tid]  = b2w[tid];
        prm[64 + tid]  = bg1w[tid];
        prm[96 + tid]  = bg2w[tid];
        prm[128 + tid] = gammaw[tid];
        prm[160 + tid] = betaw[tid];
    }
    {   // x [64][36] f32
        const int row = tid >> 2, off = (tid & 3) * 8;
        const float4* xp = (const float4*)(x + (blk + row) * 32 + off);
        float4* xr = (float4*)&xt[row * 36 + off];
        xr[0] = xp[0]; xr[1] = xp[1];
    }
    __syncthreads();

    // ---- phase 1: warps 0-3 compute w for 64 tokens ----
    if (warp < 4) {
        const int wtok = warp * 16;
        uint32_t* h2u = (uint32_t*)(smw + KF_HT) + warp * 320;
        const uint32_t htb = sb + KF_HT + (uint32_t)warp * 1280u;
        const uint32_t abw = htb + (uint32_t)((((lmat & 1) * 8 + lrow) * 20 + (lmat >> 1) * 4) * 4);

        const float* xr0 = &xt[(wtok + g) * 36];
        const float* xr1 = &xt[(wtok + g + 8) * 36];

        uint32_t a1[2][4];
        #pragma unroll
        for (int s = 0; s < 2; s++) {
            int k0 = 16 * s + 2 * q;
            a1[s][0] = packh2(xr0[k0],     xr0[k0 + 1]);
            a1[s][1] = packh2(xr1[k0],     xr1[k0 + 1]);
            a1[s][2] = packh2(xr0[k0 + 8], xr0[k0 + 9]);
            a1[s][3] = packh2(xr1[k0 + 8], xr1[k0 + 9]);
        }

        #pragma unroll
        for (int j = 0; j < 4; j++) {
            uint32_t ad = sb + KF_W1 + (uint32_t)(((8 * j + lrow) * 20 + 4 * lmat) * 4);
            uint32_t bb[4];
            ldsm4(bb, ad);
            float c[4] = {0.f, 0.f, 0.f, 0.f};
            mma16(c, a1[0], bb[0], bb[1]);
            mma16(c, a1[1], bb[2], bb[3]);
            int col0 = 8 * j + 2 * q;
            float b0 = prm[col0], b1v = prm[col0 + 1];
            h2u[g * 20 + 4 * j + q]       = packh2(eluf(c[0] + b0), eluf(c[1] + b1v));
            h2u[(g + 8) * 20 + 4 * j + q] = packh2(eluf(c[2] + b0), eluf(c[3] + b1v));
        }
        __syncwarp();
        uint32_t a2[2][4];
        ldsm4(a2[0], abw);
        ldsm4(a2[1], abw + 32);
        __syncwarp();

        #pragma unroll
        for (int j = 0; j < 4; j++) {
            uint32_t ad = sb + KF_W2 + (uint32_t)(((8 * j + lrow) * 20 + 4 * lmat) * 4);
            uint32_t bb[4];
            ldsm4(bb, ad);
            float c[4] = {0.f, 0.f, 0.f, 0.f};
            mma16(c, a2[0], bb[0], bb[1]);
            mma16(c, a2[1], bb[2], bb[3]);
            int col0 = 8 * j + 2 * q;
            float b0 = prm[32 + col0], b1v = prm[32 + col0 + 1];
            h2u[g * 20 + 4 * j + q]       = packh2(c[0] + b0, c[1] + b1v);
            h2u[(g + 8) * 20 + 4 * j + q] = packh2(c[2] + b0, c[3] + b1v);
        }
        __syncwarp();
        uint32_t a3[2][4];
        ldsm4(a3[0], abw);
        ldsm4(a3[1], abw + 32);

        float o1v[2][8], o2v[2][8];
        #pragma unroll
        for (int j = 0; j < 8; j++) {
            uint32_t ad = sb + KF_WG + (uint32_t)(((8 * j + lrow) * 20 + 4 * lmat) * 4);
            uint32_t bb[4];
            ldsm4(bb, ad);
            float c[4] = {0.f, 0.f, 0.f, 0.f};
            mma16(c, a3[0], bb[0], bb[1]);
            mma16(c, a3[1], bb[2], bb[3]);
            if (j < 4) {
                o1v[0][2*j] = c[0]; o1v[0][2*j+1] = c[1];
                o1v[1][2*j] = c[2]; o1v[1][2*j+1] = c[3];
            } else {
                int jj = j - 4;
                o2v[0][2*jj] = c[0]; o2v[0][2*jj+1] = c[1];
                o2v[1][2*jj] = c[2]; o2v[1][2*jj+1] = c[3];
            }
        }

        float s[2][8];
        float ssum[2] = {0.f, 0.f}, ssq[2] = {0.f, 0.f};
        #pragma unroll
        for (int t = 0; t < 2; t++) {
            const float* xr = (t == 0) ? xr0 : xr1;
            #pragma unroll
            for (int j = 0; j < 4; j++) {
                #pragma unroll
                for (int i2 = 0; i2 < 2; i2++) {
                    int col = 8 * j + 2 * q + i2;
                    float o1 = o1v[t][2*j + i2] + prm[64 + col];
                    float o2 = o2v[t][2*j + i2] + prm[96 + col];
                    float sv = fmaf(o1, sigmf(o2), xr[col]);
                    s[t][2*j + i2] = sv;
                    ssum[t] += sv;
                    ssq[t] = fmaf(sv, sv, ssq[t]);
                }
            }
        }
        #pragma unroll
        for (int off = 1; off < 4; off <<= 1) {
            #pragma unroll
            for (int t = 0; t < 2; t++) {
                ssum[t] += __shfl_xor_sync(0xffffffffu, ssum[t], off);
                ssq[t]  += __shfl_xor_sync(0xffffffffu, ssq[t],  off);
            }
        }
        #pragma unroll
        for (int t = 0; t < 2; t++) {
            float mean = ssum[t] * (1.f / 32.f);
            float var  = ssq[t] * (1.f / 32.f) - mean * mean;
            float inv  = rsqrtf(var + EPS);
            float y[8], mx = -1e30f;
            #pragma unroll
            for (int j = 0; j < 4; j++) {
                #pragma unroll
                for (int i2 = 0; i2 < 2; i2++) {
                    int col = 8 * j + 2 * q + i2;
                    float v = fmaf((s[t][2*j + i2] - mean) * inv, prm[128 + col], prm[160 + col]);
                    y[2*j + i2] = v;
                    mx = fmaxf(mx, v);
                }
            }
            #pragma unroll
            for (int off = 1; off < 4; off <<= 1)
                mx = fmaxf(mx, __shfl_xor_sync(0xffffffffu, mx, off));
            float se = 0.f;
            #pragma unroll
            for (int e = 0; e < 8; e++) { float ev = __expf(y[e] - mx); y[e] = ev; se += ev; }
            #pragma unroll
            for (int off = 1; off < 4; off <<= 1)
                se += __shfl_xor_sync(0xffffffffu, se, off);
            float r = 1.f / se;
            int row = wtok + g + 8 * t;
            float* orow = wout + (blk + row) * (size_t)NF;
            #pragma unroll
            for (int j = 0; j < 4; j++) {
                float2 v2 = make_float2(y[2*j] * r, y[2*j + 1] * r);
                *(float2*)&orow[8 * j + 2 * q] = v2;
                *(float2*)&ws[row * 36 + 8 * j + 2 * q] = v2;
            }
        }
    }
    __syncthreads();

    // ---- phase 2: table lerp-accumulate (4 threads/token) ----
    const int tok = tid >> 2;
    const int ql  = tid & 3;
    const int gb  = ql * 16;

    float acc[16];
    #pragma unroll
    for (int c = 0; c < 16; c++) acc[c] = 0.f;

    #pragma unroll 2
    for (int f = 0; f < NF; f++) {
        float xf = xt[tok * 36 + f];
        float wf = ws[tok * 36 + f];

        float tpos = (xf - XMIN) * INVDX;
        int   i    = (int)tpos;
        i = (i < 0) ? 0 : ((i > NSEG - 1) ? NSEG - 1 : i);
        float fr  = tpos - (float)i;
        float wfr = wf * fr;
        float wfa = wf - wfr;

        const uint4* r0 = (const uint4*)&g_tab[f][i][ql * 8];
        const uint4* r1 = (const uint4*)&g_tab[f][i + 1][ql * 8];
        uint4 a0 = r0[0], a1v = r0[1];
        uint4 b0 = r1[0], b1v = r1[1];

        const uint32_t aw[8] = { a0.x, a0.y, a0.z, a0.w, a1v.x, a1v.y, a1v.z, a1v.w };
        const uint32_t bw[8] = { b0.x, b0.y, b0.z, b0.w, b1v.x, b1v.y, b1v.z, b1v.w };
        #pragma unroll
        for (int c = 0; c < 8; c++) {
            float2 av = unpackh2(aw[c]);
            float2 bv = unpackh2(bw[c]);
            acc[2*c]   = fmaf(av.x, wfa, fmaf(bv.x, wfr, acc[2*c]));
            acc[2*c+1] = fmaf(av.y, wfa, fmaf(bv.y, wfr, acc[2*c+1]));
        }
    }

    {
        float4* op = (float4*)(out + (blk + tok) * NU + gb);
        #pragma unroll
        for (int c = 0; c < 4; c++)
            op[c] = make_float4(acc[4*c], acc[4*c+1], acc[4*c+2], acc[4*c+3]);
    }
}

// ============================================================================
extern "C" void kernel_launch(void* const* d_in, const int* in_sizes, int n_in,
                              void* d_out, int out_size) {
    const float* x    = (const float*)d_in[0];
    const float* W1   = (const float*)d_in[1];
    const float* b1   = (const float*)d_in[2];
    const float* W2   = (const float*)d_in[3];
    const float* b2   = (const float*)d_in[4];
    const float* Wg1  = (const float*)d_in[5];
    const float* bg1  = (const float*)d_in[6];
    const float* Wg2  = (const float*)d_in[7];
    const float* bg2  = (const float*)d_in[8];
    const float* Wp   = (const float*)d_in[9];
    const float* bp   = (const float*)d_in[10];
    const float* gamma= (const float*)d_in[11];
    const float* beta = (const float*)d_in[12];
    const float* w1w  = (const float*)d_in[13];
    const float* b1w  = (const float*)d_in[14];
    const float* w2w  = (const float*)d_in[15];
    const float* b2w  = (const float*)d_in[16];
    const float* wg1w = (const float*)d_in[17];
    const float* bg1w = (const float*)d_in[18];
    const float* wg2w = (const float*)d_in[19];
    const float* bg2w = (const float*)d_in[20];
    const float* gammaw = (const float*)d_in[21];
    const float* betaw  = (const float*)d_in[22];

    float* outp = (float*)d_out;
    float* wp   = outp + W_OFF;

    k_prep<<<NF, 256>>>(W2, Wg1, Wg2, b2, bg1, bg2, W1, b1, Wp, bp, gamma, beta);

    cudaFuncSetAttribute(k_tab, cudaFuncAttributeMaxDynamicSharedMemorySize, KT_SMEM);
    k_tab<<<dim3(7, 32), 256, KT_SMEM>>>();

    cudaFuncSetAttribute(k_fused, cudaFuncAttributeMaxDynamicSharedMemorySize, KF_SMEM);
    k_fused<<<BT / 64, 256, KF_SMEM>>>(
        x, w1w, b1w, w2w, b2w, wg1w, bg1w, wg2w, bg2w, gammaw, betaw, wp, outp);
}